// round 4
// baseline (speedup 1.0000x reference)
#include <cuda_runtime.h>
#include <cuda_bf16.h>
#include <math.h>
#include <stdint.h>

// ---------------- problem constants ----------------
#define S     4096
#define DM    768
#define FF    3072
#define HNUM  12
#define HD    64
#define WIN   256
#define CCH   16          // chunks
#define NW    8           // global tokens
#define LNUM  12
#define OUTD  128
#define SCALE 0.125f      // 1/sqrt(64)

// ---------------- scratch ----------------
__device__ float g_h   [S*DM];
__device__ float g_q   [S*DM];
__device__ float g_k   [S*DM];
__device__ float g_v   [S*DM];
__device__ float g_kg  [S*DM];
__device__ float g_vg  [S*DM];
__device__ float g_attn[S*DM];
__device__ float g_y   [S*DM];
__device__ float g_ffn [S*FF];
__device__ float g_qg  [NW*DM];

// ---------------- helpers ----------------
__device__ __forceinline__ float gelu_f(float x) {
    float x3 = x * x * x;
    return 0.5f * x * (1.0f + tanhf(0.7978845608028654f * (x + 0.044715f * x3)));
}

__device__ __forceinline__ uint32_t f2tf32(float f) {
    uint32_t r;
    asm("cvt.rna.tf32.f32 %0, %1;" : "=r"(r) : "f"(f));
    return r;
}

// ---------------- embedding + LN ----------------
__global__ void embed_kernel(const int* __restrict__ x, const float* __restrict__ we,
                             const float* __restrict__ pe, const float* __restrict__ ls,
                             const float* __restrict__ lb, float* __restrict__ h)
{
    int s = blockIdx.x;
    int tid = threadIdx.x;
    int r = s & 511, w = s >> 9;
    int id = (r == 0) ? 0 : x[w * 511 + r - 1];
    __shared__ float red[256];
    float vals[3];
    float sum = 0.f;
#pragma unroll
    for (int i = 0; i < 3; i++) {
        int d = tid + i * 256;
        vals[i] = we[(size_t)id * DM + d] + pe[s * DM + d];
        sum += vals[i];
    }
    red[tid] = sum; __syncthreads();
    for (int o = 128; o > 0; o >>= 1) { if (tid < o) red[tid] += red[tid + o]; __syncthreads(); }
    float mean = red[0] / (float)DM;
    __syncthreads();
    float vsum = 0.f;
#pragma unroll
    for (int i = 0; i < 3; i++) { float t = vals[i] - mean; vsum += t * t; }
    red[tid] = vsum; __syncthreads();
    for (int o = 128; o > 0; o >>= 1) { if (tid < o) red[tid] += red[tid + o]; __syncthreads(); }
    float rstd = rsqrtf(red[0] / (float)DM + 1e-5f);
#pragma unroll
    for (int i = 0; i < 3; i++) {
        int d = tid + i * 256;
        h[s * DM + d] = (vals[i] - mean) * rstd * ls[d] + lb[d];
    }
}

// ---------------- residual add + LN ----------------
__global__ void add_ln_kernel(const float* __restrict__ x, const float* __restrict__ y,
                              const float* __restrict__ ls, const float* __restrict__ lb,
                              float* __restrict__ o)
{
    int s = blockIdx.x;
    int tid = threadIdx.x;
    __shared__ float red[256];
    float vals[3];
    float sum = 0.f;
#pragma unroll
    for (int i = 0; i < 3; i++) {
        int d = tid + i * 256;
        vals[i] = x[(size_t)s * DM + d] + y[(size_t)s * DM + d];
        sum += vals[i];
    }
    red[tid] = sum; __syncthreads();
    for (int off = 128; off > 0; off >>= 1) { if (tid < off) red[tid] += red[tid + off]; __syncthreads(); }
    float mean = red[0] / (float)DM;
    __syncthreads();
    float vsum = 0.f;
#pragma unroll
    for (int i = 0; i < 3; i++) { float t = vals[i] - mean; vsum += t * t; }
    red[tid] = vsum; __syncthreads();
    for (int off = 128; off > 0; off >>= 1) { if (tid < off) red[tid] += red[tid + off]; __syncthreads(); }
    float rstd = rsqrtf(red[0] / (float)DM + 1e-5f);
#pragma unroll
    for (int i = 0; i < 3; i++) {
        int d = tid + i * 256;
        o[(size_t)s * DM + d] = (vals[i] - mean) * rstd * ls[d] + lb[d];
    }
}

// ---------------- tf32 tensor-core GEMM, 2-stage double buffered ----------------
// C[M,N] = act((A[M,K] @ B[K,N] + bias) * alpha)
// BM=128 BN=128 BK=32, 256 threads = 8 warps, warp tile 64x32.
// Dynamic smem: 2 stages x (As[128][36] + Bs[32][136]) u32 = 71680 bytes.
#define STG_U32 8960          // u32 per stage
#define BS_OFF  4608          // As size in u32 (128*36)

__global__ __launch_bounds__(256)
void tgemm_kernel(const float* __restrict__ A, const float* __restrict__ B,
                  const float* __restrict__ bias, float* __restrict__ C,
                  int M, int N, int K, float alpha, int act)
{
    extern __shared__ uint32_t sm[];

    const int tid  = threadIdx.x;
    const int lane = tid & 31;
    const int warp = tid >> 5;
    const int wm = warp >> 2;     // 0..1
    const int wn = warp & 3;      // 0..3
    const int g  = lane >> 2;     // 0..7
    const int t  = lane & 3;      // 0..3

    const int bRow = blockIdx.y * 128;
    const int bCol = blockIdx.x * 128;

    float acc[4][4][4];
#pragma unroll
    for (int i = 0; i < 4; i++)
#pragma unroll
        for (int j = 0; j < 4; j++)
#pragma unroll
            for (int r = 0; r < 4; r++) acc[i][j][r] = 0.f;

    const int a_row = tid >> 1;
    const int a_col = (tid & 1) * 16;

    // ---- prologue: stage 0 ----
    {
        const float* Ag = A + (size_t)(bRow + a_row) * K + a_col;
        uint32_t* as0 = sm + a_row * 36;
#pragma unroll
        for (int c = 0; c < 16; c += 4) {
            float4 v = *(const float4*)(Ag + c);
            uint4 pk;
            pk.x = f2tf32(v.x); pk.y = f2tf32(v.y);
            pk.z = f2tf32(v.z); pk.w = f2tf32(v.w);
            *(uint4*)(as0 + a_col + c) = pk;
        }
#pragma unroll
        for (int p = 0; p < 4; p++) {
            int f4 = p * 256 + tid;
            int r = f4 >> 5;
            int c = (f4 & 31) * 4;
            float4 v = *(const float4*)(B + (size_t)r * N + bCol + c);
            uint4 pk;
            pk.x = f2tf32(v.x); pk.y = f2tf32(v.y);
            pk.z = f2tf32(v.z); pk.w = f2tf32(v.w);
            *(uint4*)(sm + BS_OFF + r * 136 + c) = pk;
        }
    }
    __syncthreads();

    const int nk = K >> 5;
    for (int kt = 0; kt < nk; kt++) {
        const int cur = kt & 1;
        const int nxt = cur ^ 1;
        const bool pref = (kt + 1 < nk);

        // issue prefetch loads (in flight during MMA)
        float4 pa[4], pb[4];
        if (pref) {
            int k0 = (kt + 1) << 5;
            const float* Ag = A + (size_t)(bRow + a_row) * K + k0 + a_col;
#pragma unroll
            for (int i = 0; i < 4; i++) pa[i] = *(const float4*)(Ag + i * 4);
#pragma unroll
            for (int p = 0; p < 4; p++) {
                int f4 = p * 256 + tid;
                int r = f4 >> 5;
                int c = (f4 & 31) * 4;
                pb[p] = *(const float4*)(B + (size_t)(k0 + r) * N + bCol + c);
            }
        }

        // MMAs on current stage
        const uint32_t* asc = sm + cur * STG_U32;
        const uint32_t* bsc = sm + cur * STG_U32 + BS_OFF;
#pragma unroll
        for (int kk = 0; kk < 32; kk += 8) {
            uint32_t af[4][4];
#pragma unroll
            for (int mi = 0; mi < 4; mi++) {
                int r0 = wm * 64 + mi * 16 + g;
                af[mi][0] = asc[r0 * 36 + kk + t];
                af[mi][1] = asc[(r0 + 8) * 36 + kk + t];
                af[mi][2] = asc[r0 * 36 + kk + t + 4];
                af[mi][3] = asc[(r0 + 8) * 36 + kk + t + 4];
            }
            uint32_t bf[4][2];
#pragma unroll
            for (int ni = 0; ni < 4; ni++) {
                int cn = wn * 32 + ni * 8 + g;
                bf[ni][0] = bsc[(kk + t) * 136 + cn];
                bf[ni][1] = bsc[(kk + t + 4) * 136 + cn];
            }
#pragma unroll
            for (int mi = 0; mi < 4; mi++)
#pragma unroll
                for (int ni = 0; ni < 4; ni++) {
                    asm volatile(
                        "mma.sync.aligned.m16n8k8.row.col.f32.tf32.tf32.f32 "
                        "{%0,%1,%2,%3}, {%4,%5,%6,%7}, {%8,%9}, {%0,%1,%2,%3};"
                        : "+f"(acc[mi][ni][0]), "+f"(acc[mi][ni][1]),
                          "+f"(acc[mi][ni][2]), "+f"(acc[mi][ni][3])
                        : "r"(af[mi][0]), "r"(af[mi][1]), "r"(af[mi][2]), "r"(af[mi][3]),
                          "r"(bf[ni][0]), "r"(bf[ni][1]));
                }
        }

        // store prefetch into next stage
        if (pref) {
            uint32_t* asn = sm + nxt * STG_U32 + a_row * 36;
#pragma unroll
            for (int i = 0; i < 4; i++) {
                uint4 pk;
                pk.x = f2tf32(pa[i].x); pk.y = f2tf32(pa[i].y);
                pk.z = f2tf32(pa[i].z); pk.w = f2tf32(pa[i].w);
                *(uint4*)(asn + a_col + i * 4) = pk;
            }
            uint32_t* bsn = sm + nxt * STG_U32 + BS_OFF;
#pragma unroll
            for (int p = 0; p < 4; p++) {
                int f4 = p * 256 + tid;
                int r = f4 >> 5;
                int c = (f4 & 31) * 4;
                uint4 pk;
                pk.x = f2tf32(pb[p].x); pk.y = f2tf32(pb[p].y);
                pk.z = f2tf32(pb[p].z); pk.w = f2tf32(pb[p].w);
                *(uint4*)(bsn + r * 136 + c) = pk;
            }
        }
        __syncthreads();
    }

    // epilogue
#pragma unroll
    for (int mi = 0; mi < 4; mi++) {
        int row0 = bRow + wm * 64 + mi * 16 + g;
#pragma unroll
        for (int ni = 0; ni < 4; ni++) {
            int col = bCol + wn * 32 + ni * 8 + t * 2;
            float b0 = bias[col], b1 = bias[col + 1];
            float v0 = (acc[mi][ni][0] + b0) * alpha;
            float v1 = (acc[mi][ni][1] + b1) * alpha;
            float v2 = (acc[mi][ni][2] + b0) * alpha;
            float v3 = (acc[mi][ni][3] + b1) * alpha;
            if (act == 1) { v0 = gelu_f(v0); v1 = gelu_f(v1); v2 = gelu_f(v2); v3 = gelu_f(v3); }
            *(float2*)&C[(size_t)row0 * N + col]       = make_float2(v0, v1);
            *(float2*)&C[(size_t)(row0 + 8) * N + col] = make_float2(v2, v3);
        }
    }
}

// ---------------- local (sliding-window + global-key) attention ----------------
// double-buffered 16-key tiles; one sync per tile; prefetch overlaps compute
__global__ __launch_bounds__(256, 1)
void local_attn_kernel(const float* __restrict__ q, const float* __restrict__ k,
                       const float* __restrict__ v, float* __restrict__ out)
{
    int c = blockIdx.x, hh = blockIdx.y;
    int qi = threadIdx.x;
    int qpos = c * WIN + qi;
    int hoff = hh * HD;

    float qreg[HD];
#pragma unroll
    for (int d = 0; d < HD; d++) qreg[d] = q[(size_t)qpos * DM + hoff + d];

    __shared__ float ks[2][16][HD];
    __shared__ float vs[2][16][HD];

    float m = -1e30f, l = 0.f;
    float acc[HD];
#pragma unroll
    for (int d = 0; d < HD; d++) acc[d] = 0.f;

    const int ld_j  = threadIdx.x >> 4;        // 0..15
    const int ld_d4 = (threadIdx.x & 15) * 4;  // 0..60

    // ---- global keys (8) in buffer 0 ----
    {
        int tt = threadIdx.x;
        if (tt < 128) {
            int gg = tt / 16;
            int d4 = (tt % 16) * 4;
            int gpos = gg * 512;
            *(float4*)&ks[0][gg][d4] = *(const float4*)&k[(size_t)gpos * DM + hoff + d4];
            *(float4*)&vs[0][gg][d4] = *(const float4*)&v[(size_t)gpos * DM + hoff + d4];
        }
        __syncthreads();
        float s[8];
        float tmax = m;
#pragma unroll
        for (int j = 0; j < 8; j++) {
            float a = 0.f;
#pragma unroll
            for (int d = 0; d < HD; d++) a += qreg[d] * ks[0][j][d];
            s[j] = a;
            tmax = fmaxf(tmax, a);
        }
        float sc = __expf(m - tmax);
        l *= sc;
#pragma unroll
        for (int d = 0; d < HD; d++) acc[d] *= sc;
#pragma unroll
        for (int j = 0; j < 8; j++) {
            float p = __expf(s[j] - tmax);
            l += p;
#pragma unroll
            for (int d = 0; d < HD; d++) acc[d] += p * vs[0][j][d];
        }
        m = tmax;
        __syncthreads();   // done reading buffer 0 before overwrite
    }

    // ---- prologue: tile 0 into buffer 0 ----
    {
        int kpos = c * WIN + ld_j - WIN;
        float4 kv4 = make_float4(0.f, 0.f, 0.f, 0.f);
        float4 vv4 = make_float4(0.f, 0.f, 0.f, 0.f);
        if (kpos >= 0 && kpos < S) {
            kv4 = *(const float4*)&k[(size_t)kpos * DM + hoff + ld_d4];
            vv4 = *(const float4*)&v[(size_t)kpos * DM + hoff + ld_d4];
        }
        *(float4*)&ks[0][ld_j][ld_d4] = kv4;
        *(float4*)&vs[0][ld_j][ld_d4] = vv4;
    }
    __syncthreads();

    // ---- 48 tiles of 16 keys, double buffered ----
    for (int t0 = 0; t0 < 48; t0++) {
        int cur = t0 & 1, nxt = cur ^ 1;

        // prefetch tile t0+1
        float4 kv4 = make_float4(0.f, 0.f, 0.f, 0.f);
        float4 vv4 = make_float4(0.f, 0.f, 0.f, 0.f);
        bool pref = (t0 + 1 < 48);
        if (pref) {
            int kpos = c * WIN + (t0 + 1) * 16 + ld_j - WIN;
            if (kpos >= 0 && kpos < S) {
                kv4 = *(const float4*)&k[(size_t)kpos * DM + hoff + ld_d4];
                vv4 = *(const float4*)&v[(size_t)kpos * DM + hoff + ld_d4];
            }
        }

        // compute tile t0 from buf[cur]
        float s[16];
        float tmax = m;
#pragma unroll
        for (int jj = 0; jj < 16; jj++) {
            int jg = t0 * 16 + jj;
            int kp = c * WIN + jg - WIN;
            bool valid = (jg >= qi) && (jg <= qi + 2 * WIN) && (kp >= 0) && (kp < S);
            float a = 0.f;
#pragma unroll
            for (int d = 0; d < HD; d++) a += qreg[d] * ks[cur][jj][d];
            s[jj] = valid ? a : -1e30f;
            tmax = fmaxf(tmax, s[jj]);
        }
        float sc = __expf(m - tmax);
        l *= sc;
#pragma unroll
        for (int d = 0; d < HD; d++) acc[d] *= sc;
#pragma unroll
        for (int jj = 0; jj < 16; jj++) {
            float p = __expf(s[jj] - tmax);
            l += p;
#pragma unroll
            for (int d = 0; d < HD; d++) acc[d] += p * vs[cur][jj][d];
        }
        m = tmax;

        // store prefetch into buf[nxt]
        if (pref) {
            *(float4*)&ks[nxt][ld_j][ld_d4] = kv4;
            *(float4*)&vs[nxt][ld_j][ld_d4] = vv4;
        }
        __syncthreads();
    }

    float inv = 1.f / l;
#pragma unroll
    for (int d = 0; d < HD; d++)
        out[(size_t)qpos * DM + hoff + d] = acc[d] * inv;
}

// ---------------- qg projection ----------------
__global__ void qg_kernel(const float* __restrict__ h, const float* __restrict__ Wqg,
                          const float* __restrict__ bqg, float* __restrict__ qg)
{
    int g = blockIdx.x;
    int o = blockIdx.y * 128 + threadIdx.x;
    const float* hr = h + (size_t)(g * 512) * DM;
    float a = bqg[o];
    for (int d = 0; d < DM; d++) a += hr[d] * Wqg[(size_t)d * DM + o];
    qg[g * DM + o] = a * SCALE;
}

// ---------------- global-token full attention ----------------
__global__ void global_attn_kernel(const float* __restrict__ qg, const float* __restrict__ kg,
                                   const float* __restrict__ vg, float* __restrict__ out)
{
    int g = blockIdx.x, hh = blockIdx.y;
    int hoff = hh * HD;
    int tid = threadIdx.x;
    __shared__ float qs[HD];
    __shared__ float sc[S];
    __shared__ float red[256];
    if (tid < HD) qs[tid] = qg[g * DM + hoff + tid];
    __syncthreads();

    float lmax = -1e30f;
    for (int i = 0; i < 16; i++) {
        int s = i * 256 + tid;
        const float* kr = kg + (size_t)s * DM + hoff;
        float a = 0.f;
#pragma unroll
        for (int d = 0; d < HD; d++) a += qs[d] * kr[d];
        sc[s] = a;
        lmax = fmaxf(lmax, a);
    }
    red[tid] = lmax; __syncthreads();
    for (int o = 128; o > 0; o >>= 1) { if (tid < o) red[tid] = fmaxf(red[tid], red[tid + o]); __syncthreads(); }
    float mx = red[0]; __syncthreads();

    float lsum = 0.f;
    for (int i = 0; i < 16; i++) {
        int s = i * 256 + tid;
        float p = __expf(sc[s] - mx);
        sc[s] = p;
        lsum += p;
    }
    red[tid] = lsum; __syncthreads();
    for (int o = 128; o > 0; o >>= 1) { if (tid < o) red[tid] += red[tid + o]; __syncthreads(); }
    float inv = 1.f / red[0]; __syncthreads();

    int d = tid & 63;
    int part = tid >> 6;
    float a = 0.f;
    for (int s = part * 1024; s < (part + 1) * 1024; s++)
        a += sc[s] * vg[(size_t)s * DM + hoff + d];
    red[tid] = a; __syncthreads();
    if (tid < 64) {
        float r = red[tid] + red[tid + 64] + red[tid + 128] + red[tid + 192];
        out[(size_t)(g * 512) * DM + hoff + d] = r * inv;
    }
}

// ---------------- output head ----------------
__global__ void head_kernel(const float* __restrict__ h, const float* __restrict__ Wout,
                            const float* __restrict__ bout, float* __restrict__ out)
{
    int g = blockIdx.x;
    int o = threadIdx.x; // 128
    const float* hr = h + (size_t)(g * 512) * DM;
    float a = bout[o];
    for (int d = 0; d < DM; d++) a += hr[d] * Wout[(size_t)d * OUTD + o];
    out[g * OUTD + o] = a;
}

// ---------------- driver ----------------
#define TGEMM_SMEM 71680

extern "C" void kernel_launch(void* const* d_in, const int* in_sizes, int n_in,
                              void* d_out, int out_size)
{
    (void)in_sizes; (void)n_in; (void)out_size;
    const int*   x        = (const int*)  d_in[0];
    const float* word_emb = (const float*)d_in[1];
    const float* pos_emb  = (const float*)d_in[2];
    const float* emb_ln_s = (const float*)d_in[3];
    const float* emb_ln_b = (const float*)d_in[4];
    const float* Wq  = (const float*)d_in[5];   const float* bq  = (const float*)d_in[6];
    const float* Wk  = (const float*)d_in[7];   const float* bk  = (const float*)d_in[8];
    const float* Wv  = (const float*)d_in[9];   const float* bv  = (const float*)d_in[10];
    const float* Wo  = (const float*)d_in[11];  const float* bo  = (const float*)d_in[12];
    const float* Wqg = (const float*)d_in[13];  const float* bqg = (const float*)d_in[14];
    const float* Wkg = (const float*)d_in[15];  const float* bkg = (const float*)d_in[16];
    const float* Wvg = (const float*)d_in[17];  const float* bvg = (const float*)d_in[18];
    const float* ln1s= (const float*)d_in[19];  const float* ln1b= (const float*)d_in[20];
    const float* W1  = (const float*)d_in[21];  const float* b1  = (const float*)d_in[22];
    const float* W2  = (const float*)d_in[23];  const float* b2  = (const float*)d_in[24];
    const float* ln2s= (const float*)d_in[25];  const float* ln2b= (const float*)d_in[26];
    const float* Wout= (const float*)d_in[27];  const float* bout= (const float*)d_in[28];
    float* out = (float*)d_out;

    float *h, *q, *k, *v, *kg, *vg, *attn, *y, *ffn, *qg;
    cudaGetSymbolAddress((void**)&h,    g_h);
    cudaGetSymbolAddress((void**)&q,    g_q);
    cudaGetSymbolAddress((void**)&k,    g_k);
    cudaGetSymbolAddress((void**)&v,    g_v);
    cudaGetSymbolAddress((void**)&kg,   g_kg);
    cudaGetSymbolAddress((void**)&vg,   g_vg);
    cudaGetSymbolAddress((void**)&attn, g_attn);
    cudaGetSymbolAddress((void**)&y,    g_y);
    cudaGetSymbolAddress((void**)&ffn,  g_ffn);
    cudaGetSymbolAddress((void**)&qg,   g_qg);

    cudaFuncSetAttribute(tgemm_kernel, cudaFuncAttributeMaxDynamicSharedMemorySize, TGEMM_SMEM);

    embed_kernel<<<S, 256>>>(x, word_emb, pos_emb, emb_ln_s, emb_ln_b, h);

    dim3 gridP(DM / 128, S / 128);    // 6 x 32
    dim3 gridF1(FF / 128, S / 128);   // 24 x 32
    dim3 gridF2(DM / 128, S / 128);   // 6 x 32
    dim3 gridAtt(CCH, HNUM);          // 16 x 12
    dim3 gridQg(NW, DM / 128);        // 8 x 6
    dim3 gridGA(NW, HNUM);            // 8 x 12

    for (int l = 0; l < LNUM; l++) {
        size_t wO  = (size_t)l * DM * DM;
        size_t bO  = (size_t)l * DM;
        size_t w1O = (size_t)l * DM * FF;
        size_t b1O = (size_t)l * FF;
        size_t w2O = (size_t)l * FF * DM;

        tgemm_kernel<<<gridP, 256, TGEMM_SMEM>>>(h, Wq + wO, bq + bO, q, S, DM, DM, SCALE, 0);
        tgemm_kernel<<<gridP, 256, TGEMM_SMEM>>>(h, Wk + wO, bk + bO, k, S, DM, DM, 1.0f, 0);
        tgemm_kernel<<<gridP, 256, TGEMM_SMEM>>>(h, Wv + wO, bv + bO, v, S, DM, DM, 1.0f, 0);
        local_attn_kernel<<<gridAtt, 256>>>(q, k, v, attn);

        qg_kernel<<<gridQg, 128>>>(h, Wqg + wO, bqg + bO, qg);
        tgemm_kernel<<<gridP, 256, TGEMM_SMEM>>>(h, Wkg + wO, bkg + bO, kg, S, DM, DM, 1.0f, 0);
        tgemm_kernel<<<gridP, 256, TGEMM_SMEM>>>(h, Wvg + wO, bvg + bO, vg, S, DM, DM, 1.0f, 0);
        global_attn_kernel<<<gridGA, 256>>>(qg, kg, vg, attn);

        tgemm_kernel<<<gridP, 256, TGEMM_SMEM>>>(attn, Wo + wO, bo + bO, y, S, DM, DM, 1.0f, 0);
        add_ln_kernel<<<S, 256>>>(h, y, ln1s + bO, ln1b + bO, h);

        tgemm_kernel<<<gridF1, 256, TGEMM_SMEM>>>(h, W1 + w1O, b1 + b1O, ffn, S, FF, DM, 1.0f, 1);
        tgemm_kernel<<<gridF2, 256, TGEMM_SMEM>>>(ffn, W2 + w2O, b2 + bO, y, S, DM, FF, 1.0f, 0);
        add_ln_kernel<<<S, 256>>>(h, y, ln2s + bO, ln2b + bO, h);
    }

    head_kernel<<<NW, 128>>>(h, Wout, bout, out);
}

// round 5
// speedup vs baseline: 1.0390x; 1.0390x over previous
#include <cuda_runtime.h>
#include <cuda_bf16.h>
#include <math.h>
#include <stdint.h>

// ---------------- problem constants ----------------
#define S     4096
#define DM    768
#define FF    3072
#define HNUM  12
#define HD    64
#define WIN   256
#define CCH   16          // chunks
#define NW    8           // global tokens
#define LNUM  12
#define OUTD  128
#define SCALE 0.125f      // 1/sqrt(64)

// ---------------- scratch ----------------
__device__ float g_h   [S*DM];
__device__ float g_q   [S*DM];
__device__ float g_k   [S*DM];
__device__ float g_v   [S*DM];
__device__ float g_kg  [S*DM];
__device__ float g_vg  [S*DM];
__device__ float g_attn[S*DM];
__device__ float g_y   [S*DM];
__device__ float g_ffn [S*FF];
__device__ float g_qg  [NW*DM];

// ---------------- helpers ----------------
__device__ __forceinline__ float gelu_f(float x) {
    float x3 = x * x * x;
    return 0.5f * x * (1.0f + tanhf(0.7978845608028654f * (x + 0.044715f * x3)));
}

__device__ __forceinline__ uint32_t f2tf32(float f) {
    uint32_t r;
    asm("cvt.rna.tf32.f32 %0, %1;" : "=r"(r) : "f"(f));
    return r;
}

__device__ __forceinline__ void cp_async16(void* smem_dst, const void* gmem_src) {
    uint32_t dst = (uint32_t)__cvta_generic_to_shared(smem_dst);
    asm volatile("cp.async.ca.shared.global [%0], [%1], 16;" :: "r"(dst), "l"(gmem_src));
}
#define CP_COMMIT() asm volatile("cp.async.commit_group;" ::)
#define CP_WAIT1()  asm volatile("cp.async.wait_group 1;" ::)

// ---------------- embedding + LN ----------------
__global__ void embed_kernel(const int* __restrict__ x, const float* __restrict__ we,
                             const float* __restrict__ pe, const float* __restrict__ ls,
                             const float* __restrict__ lb, float* __restrict__ h)
{
    int s = blockIdx.x;
    int tid = threadIdx.x;
    int r = s & 511, w = s >> 9;
    int id = (r == 0) ? 0 : x[w * 511 + r - 1];
    __shared__ float red[256];
    float vals[3];
    float sum = 0.f;
#pragma unroll
    for (int i = 0; i < 3; i++) {
        int d = tid + i * 256;
        vals[i] = we[(size_t)id * DM + d] + pe[s * DM + d];
        sum += vals[i];
    }
    red[tid] = sum; __syncthreads();
    for (int o = 128; o > 0; o >>= 1) { if (tid < o) red[tid] += red[tid + o]; __syncthreads(); }
    float mean = red[0] / (float)DM;
    __syncthreads();
    float vsum = 0.f;
#pragma unroll
    for (int i = 0; i < 3; i++) { float t = vals[i] - mean; vsum += t * t; }
    red[tid] = vsum; __syncthreads();
    for (int o = 128; o > 0; o >>= 1) { if (tid < o) red[tid] += red[tid + o]; __syncthreads(); }
    float rstd = rsqrtf(red[0] / (float)DM + 1e-5f);
#pragma unroll
    for (int i = 0; i < 3; i++) {
        int d = tid + i * 256;
        h[s * DM + d] = (vals[i] - mean) * rstd * ls[d] + lb[d];
    }
}

// ---------------- residual add + LN ----------------
__global__ void add_ln_kernel(const float* __restrict__ x, const float* __restrict__ y,
                              const float* __restrict__ ls, const float* __restrict__ lb,
                              float* __restrict__ o)
{
    int s = blockIdx.x;
    int tid = threadIdx.x;
    __shared__ float red[256];
    float vals[3];
    float sum = 0.f;
#pragma unroll
    for (int i = 0; i < 3; i++) {
        int d = tid + i * 256;
        vals[i] = x[(size_t)s * DM + d] + y[(size_t)s * DM + d];
        sum += vals[i];
    }
    red[tid] = sum; __syncthreads();
    for (int off = 128; off > 0; off >>= 1) { if (tid < off) red[tid] += red[tid + off]; __syncthreads(); }
    float mean = red[0] / (float)DM;
    __syncthreads();
    float vsum = 0.f;
#pragma unroll
    for (int i = 0; i < 3; i++) { float t = vals[i] - mean; vsum += t * t; }
    red[tid] = vsum; __syncthreads();
    for (int off = 128; off > 0; off >>= 1) { if (tid < off) red[tid] += red[tid + off]; __syncthreads(); }
    float rstd = rsqrtf(red[0] / (float)DM + 1e-5f);
#pragma unroll
    for (int i = 0; i < 3; i++) {
        int d = tid + i * 256;
        o[(size_t)s * DM + d] = (vals[i] - mean) * rstd * ls[d] + lb[d];
    }
}

// ---------------- tf32 tensor-core GEMM, 3-stage cp.async pipeline ----------------
// C[M,N] = act((A[M,K] @ B[K,N] + bias) * alpha)
// BM=128 BN=128 BK=32, 256 threads = 8 warps, warp tile 64x32.
// smem: 3 stages x (Af[128][36] + Bf[32][136]) fp32 = 107520 bytes. cvt to tf32 at fragment load.
#define STAGES   3
#define STG_F32  8960          // floats per stage
#define BS_OFF   4608          // Af size in floats (128*36)
#define TGEMM_SMEM (STAGES * STG_F32 * 4)

__global__ __launch_bounds__(256)
void tgemm_kernel(const float* __restrict__ A, const float* __restrict__ B,
                  const float* __restrict__ bias, float* __restrict__ C,
                  int M, int N, int K, float alpha, int act)
{
    extern __shared__ float sm[];

    const int tid  = threadIdx.x;
    const int lane = tid & 31;
    const int warp = tid >> 5;
    const int wm = warp >> 2;     // 0..1
    const int wn = warp & 3;      // 0..3
    const int g  = lane >> 2;     // 0..7
    const int t  = lane & 3;      // 0..3

    const int bRow = blockIdx.y * 128;
    const int bCol = blockIdx.x * 128;

    float acc[4][4][4];
#pragma unroll
    for (int i = 0; i < 4; i++)
#pragma unroll
        for (int j = 0; j < 4; j++)
#pragma unroll
            for (int r = 0; r < 4; r++) acc[i][j][r] = 0.f;

    const int a_row = tid >> 1;
    const int a_col = (tid & 1) * 16;
    const float* Abase = A + (size_t)(bRow + a_row) * K + a_col;

    const int nk = K >> 5;

    // prologue: issue stages 0 and 1
#pragma unroll
    for (int s = 0; s < STAGES - 1; s++) {
        float* as = sm + s * STG_F32;
        float* bs = as + BS_OFF;
        const int k0 = s * 32;
#pragma unroll
        for (int i = 0; i < 4; i++)
            cp_async16(as + a_row * 36 + a_col + i * 4, Abase + k0 + i * 4);
#pragma unroll
        for (int p = 0; p < 4; p++) {
            int f4 = p * 256 + tid;
            int r = f4 >> 5;
            int c = (f4 & 31) * 4;
            cp_async16(bs + r * 136 + c, B + (size_t)(k0 + r) * N + bCol + c);
        }
        CP_COMMIT();
    }

    for (int kt = 0; kt < nk; kt++) {
        CP_WAIT1();            // stage kt resident
        __syncthreads();

        // issue loads for stage kt+2 (overwrites stage (kt-1)%3, safe after sync)
        const int pf = kt + STAGES - 1;
        if (pf < nk) {
            float* as = sm + (pf % STAGES) * STG_F32;
            float* bs = as + BS_OFF;
            const int k0 = pf * 32;
#pragma unroll
            for (int i = 0; i < 4; i++)
                cp_async16(as + a_row * 36 + a_col + i * 4, Abase + k0 + i * 4);
#pragma unroll
            for (int p = 0; p < 4; p++) {
                int f4 = p * 256 + tid;
                int r = f4 >> 5;
                int c = (f4 & 31) * 4;
                cp_async16(bs + r * 136 + c, B + (size_t)(k0 + r) * N + bCol + c);
            }
        }
        CP_COMMIT();           // always commit to keep group counting uniform

        // compute on stage kt
        const float* asc = sm + (kt % STAGES) * STG_F32;
        const float* bsc = asc + BS_OFF;
#pragma unroll
        for (int kk = 0; kk < 32; kk += 8) {
            uint32_t af[4][4];
#pragma unroll
            for (int mi = 0; mi < 4; mi++) {
                int r0 = wm * 64 + mi * 16 + g;
                af[mi][0] = f2tf32(asc[r0 * 36 + kk + t]);
                af[mi][1] = f2tf32(asc[(r0 + 8) * 36 + kk + t]);
                af[mi][2] = f2tf32(asc[r0 * 36 + kk + t + 4]);
                af[mi][3] = f2tf32(asc[(r0 + 8) * 36 + kk + t + 4]);
            }
            uint32_t bf[4][2];
#pragma unroll
            for (int ni = 0; ni < 4; ni++) {
                int cn = wn * 32 + ni * 8 + g;
                bf[ni][0] = f2tf32(bsc[(kk + t) * 136 + cn]);
                bf[ni][1] = f2tf32(bsc[(kk + t + 4) * 136 + cn]);
            }
#pragma unroll
            for (int mi = 0; mi < 4; mi++)
#pragma unroll
                for (int ni = 0; ni < 4; ni++) {
                    asm volatile(
                        "mma.sync.aligned.m16n8k8.row.col.f32.tf32.tf32.f32 "
                        "{%0,%1,%2,%3}, {%4,%5,%6,%7}, {%8,%9}, {%0,%1,%2,%3};"
                        : "+f"(acc[mi][ni][0]), "+f"(acc[mi][ni][1]),
                          "+f"(acc[mi][ni][2]), "+f"(acc[mi][ni][3])
                        : "r"(af[mi][0]), "r"(af[mi][1]), "r"(af[mi][2]), "r"(af[mi][3]),
                          "r"(bf[ni][0]), "r"(bf[ni][1]));
                }
        }
    }

    // epilogue
#pragma unroll
    for (int mi = 0; mi < 4; mi++) {
        int row0 = bRow + wm * 64 + mi * 16 + g;
#pragma unroll
        for (int ni = 0; ni < 4; ni++) {
            int col = bCol + wn * 32 + ni * 8 + t * 2;
            float b0 = bias[col], b1 = bias[col + 1];
            float v0 = (acc[mi][ni][0] + b0) * alpha;
            float v1 = (acc[mi][ni][1] + b1) * alpha;
            float v2 = (acc[mi][ni][2] + b0) * alpha;
            float v3 = (acc[mi][ni][3] + b1) * alpha;
            if (act == 1) { v0 = gelu_f(v0); v1 = gelu_f(v1); v2 = gelu_f(v2); v3 = gelu_f(v3); }
            *(float2*)&C[(size_t)row0 * N + col]       = make_float2(v0, v1);
            *(float2*)&C[(size_t)(row0 + 8) * N + col] = make_float2(v2, v3);
        }
    }
}

// ---------------- local (sliding-window + global-key) attention ----------------
__global__ __launch_bounds__(256, 1)
void local_attn_kernel(const float* __restrict__ q, const float* __restrict__ k,
                       const float* __restrict__ v, float* __restrict__ out)
{
    int c = blockIdx.x, hh = blockIdx.y;
    int qi = threadIdx.x;
    int qpos = c * WIN + qi;
    int hoff = hh * HD;

    float qreg[HD];
#pragma unroll
    for (int d = 0; d < HD; d++) qreg[d] = q[(size_t)qpos * DM + hoff + d];

    __shared__ float ks[16][HD];
    __shared__ float vs[16][HD];

    float m = -1e30f, l = 0.f;
    float acc[HD];
#pragma unroll
    for (int d = 0; d < HD; d++) acc[d] = 0.f;

    // ---- global keys (8) ----
    {
        int tt = threadIdx.x;
        if (tt < 128) {
            int gg = tt / 16;
            int d4 = (tt % 16) * 4;
            int gpos = gg * 512;
            *(float4*)&ks[gg][d4] = *(const float4*)&k[(size_t)gpos * DM + hoff + d4];
            *(float4*)&vs[gg][d4] = *(const float4*)&v[(size_t)gpos * DM + hoff + d4];
        }
        __syncthreads();
        float s[8];
        float tmax = m;
#pragma unroll
        for (int j = 0; j < 8; j++) {
            float a = 0.f;
#pragma unroll
            for (int d = 0; d < HD; d++) a += qreg[d] * ks[j][d];
            s[j] = a;
            tmax = fmaxf(tmax, a);
        }
        float sc = __expf(m - tmax);
        l *= sc;
#pragma unroll
        for (int d = 0; d < HD; d++) acc[d] *= sc;
#pragma unroll
        for (int j = 0; j < 8; j++) {
            float p = __expf(s[j] - tmax);
            l += p;
#pragma unroll
            for (int d = 0; d < HD; d++) acc[d] += p * vs[j][d];
        }
        m = tmax;
    }

    // ---- local window: 48 tiles of 16 keys ----
    for (int t0 = 0; t0 < 48; t0++) {
        int tt = threadIdx.x;
        int j = tt / 16;
        int d4 = (tt % 16) * 4;
        int jglob = t0 * 16 + j;
        int kpos = c * WIN + jglob - WIN;
        float4 kv4 = make_float4(0.f, 0.f, 0.f, 0.f);
        float4 vv4 = make_float4(0.f, 0.f, 0.f, 0.f);
        if (kpos >= 0 && kpos < S) {
            kv4 = *(const float4*)&k[(size_t)kpos * DM + hoff + d4];
            vv4 = *(const float4*)&v[(size_t)kpos * DM + hoff + d4];
        }
        __syncthreads();
        *(float4*)&ks[j][d4] = kv4;
        *(float4*)&vs[j][d4] = vv4;
        __syncthreads();

        float s[16];
        float tmax = m;
#pragma unroll
        for (int jj = 0; jj < 16; jj++) {
            int jg = t0 * 16 + jj;
            int kp = c * WIN + jg - WIN;
            bool valid = (jg >= qi) && (jg <= qi + 2 * WIN) && (kp >= 0) && (kp < S);
            float a = 0.f;
#pragma unroll
            for (int d = 0; d < HD; d++) a += qreg[d] * ks[jj][d];
            s[jj] = valid ? a : -1e30f;
            tmax = fmaxf(tmax, s[jj]);
        }
        float sc = __expf(m - tmax);
        l *= sc;
#pragma unroll
        for (int d = 0; d < HD; d++) acc[d] *= sc;
#pragma unroll
        for (int jj = 0; jj < 16; jj++) {
            float p = __expf(s[jj] - tmax);
            l += p;
#pragma unroll
            for (int d = 0; d < HD; d++) acc[d] += p * vs[jj][d];
        }
        m = tmax;
    }

    float inv = 1.f / l;
#pragma unroll
    for (int d = 0; d < HD; d++)
        out[(size_t)qpos * DM + hoff + d] = acc[d] * inv;
}

// ---------------- qg projection ----------------
__global__ void qg_kernel(const float* __restrict__ h, const float* __restrict__ Wqg,
                          const float* __restrict__ bqg, float* __restrict__ qg)
{
    int g = blockIdx.x;
    int o = blockIdx.y * 128 + threadIdx.x;
    const float* hr = h + (size_t)(g * 512) * DM;
    float a = bqg[o];
    for (int d = 0; d < DM; d++) a += hr[d] * Wqg[(size_t)d * DM + o];
    qg[g * DM + o] = a * SCALE;
}

// ---------------- global-token full attention ----------------
__global__ void global_attn_kernel(const float* __restrict__ qg, const float* __restrict__ kg,
                                   const float* __restrict__ vg, float* __restrict__ out)
{
    int g = blockIdx.x, hh = blockIdx.y;
    int hoff = hh * HD;
    int tid = threadIdx.x;
    __shared__ float qs[HD];
    __shared__ float sc[S];
    __shared__ float red[256];
    if (tid < HD) qs[tid] = qg[g * DM + hoff + tid];
    __syncthreads();

    float lmax = -1e30f;
    for (int i = 0; i < 16; i++) {
        int s = i * 256 + tid;
        const float* kr = kg + (size_t)s * DM + hoff;
        float a = 0.f;
#pragma unroll
        for (int d = 0; d < HD; d++) a += qs[d] * kr[d];
        sc[s] = a;
        lmax = fmaxf(lmax, a);
    }
    red[tid] = lmax; __syncthreads();
    for (int o = 128; o > 0; o >>= 1) { if (tid < o) red[tid] = fmaxf(red[tid], red[tid + o]); __syncthreads(); }
    float mx = red[0]; __syncthreads();

    float lsum = 0.f;
    for (int i = 0; i < 16; i++) {
        int s = i * 256 + tid;
        float p = __expf(sc[s] - mx);
        sc[s] = p;
        lsum += p;
    }
    red[tid] = lsum; __syncthreads();
    for (int o = 128; o > 0; o >>= 1) { if (tid < o) red[tid] += red[tid + o]; __syncthreads(); }
    float inv = 1.f / red[0]; __syncthreads();

    int d = tid & 63;
    int part = tid >> 6;
    float a = 0.f;
    for (int s = part * 1024; s < (part + 1) * 1024; s++)
        a += sc[s] * vg[(size_t)s * DM + hoff + d];
    red[tid] = a; __syncthreads();
    if (tid < 64) {
        float r = red[tid] + red[tid + 64] + red[tid + 128] + red[tid + 192];
        out[(size_t)(g * 512) * DM + hoff + d] = r * inv;
    }
}

// ---------------- output head ----------------
__global__ void head_kernel(const float* __restrict__ h, const float* __restrict__ Wout,
                            const float* __restrict__ bout, float* __restrict__ out)
{
    int g = blockIdx.x;
    int o = threadIdx.x; // 128
    const float* hr = h + (size_t)(g * 512) * DM;
    float a = bout[o];
    for (int d = 0; d < DM; d++) a += hr[d] * Wout[(size_t)d * OUTD + o];
    out[g * OUTD + o] = a;
}

// ---------------- driver ----------------
extern "C" void kernel_launch(void* const* d_in, const int* in_sizes, int n_in,
                              void* d_out, int out_size)
{
    (void)in_sizes; (void)n_in; (void)out_size;
    const int*   x        = (const int*)  d_in[0];
    const float* word_emb = (const float*)d_in[1];
    const float* pos_emb  = (const float*)d_in[2];
    const float* emb_ln_s = (const float*)d_in[3];
    const float* emb_ln_b = (const float*)d_in[4];
    const float* Wq  = (const float*)d_in[5];   const float* bq  = (const float*)d_in[6];
    const float* Wk  = (const float*)d_in[7];   const float* bk  = (const float*)d_in[8];
    const float* Wv  = (const float*)d_in[9];   const float* bv  = (const float*)d_in[10];
    const float* Wo  = (const float*)d_in[11];  const float* bo  = (const float*)d_in[12];
    const float* Wqg = (const float*)d_in[13];  const float* bqg = (const float*)d_in[14];
    const float* Wkg = (const float*)d_in[15];  const float* bkg = (const float*)d_in[16];
    const float* Wvg = (const float*)d_in[17];  const float* bvg = (const float*)d_in[18];
    const float* ln1s= (const float*)d_in[19];  const float* ln1b= (const float*)d_in[20];
    const float* W1  = (const float*)d_in[21];  const float* b1  = (const float*)d_in[22];
    const float* W2  = (const float*)d_in[23];  const float* b2  = (const float*)d_in[24];
    const float* ln2s= (const float*)d_in[25];  const float* ln2b= (const float*)d_in[26];
    const float* Wout= (const float*)d_in[27];  const float* bout= (const float*)d_in[28];
    float* out = (float*)d_out;

    float *h, *q, *k, *v, *kg, *vg, *attn, *y, *ffn, *qg;
    cudaGetSymbolAddress((void**)&h,    g_h);
    cudaGetSymbolAddress((void**)&q,    g_q);
    cudaGetSymbolAddress((void**)&k,    g_k);
    cudaGetSymbolAddress((void**)&v,    g_v);
    cudaGetSymbolAddress((void**)&kg,   g_kg);
    cudaGetSymbolAddress((void**)&vg,   g_vg);
    cudaGetSymbolAddress((void**)&attn, g_attn);
    cudaGetSymbolAddress((void**)&y,    g_y);
    cudaGetSymbolAddress((void**)&ffn,  g_ffn);
    cudaGetSymbolAddress((void**)&qg,   g_qg);

    cudaFuncSetAttribute(tgemm_kernel, cudaFuncAttributeMaxDynamicSharedMemorySize, TGEMM_SMEM);

    embed_kernel<<<S, 256>>>(x, word_emb, pos_emb, emb_ln_s, emb_ln_b, h);

    dim3 gridP(DM / 128, S / 128);    // 6 x 32
    dim3 gridF1(FF / 128, S / 128);   // 24 x 32
    dim3 gridF2(DM / 128, S / 128);   // 6 x 32
    dim3 gridAtt(CCH, HNUM);          // 16 x 12
    dim3 gridQg(NW, DM / 128);        // 8 x 6
    dim3 gridGA(NW, HNUM);            // 8 x 12

    for (int l = 0; l < LNUM; l++) {
        size_t wO  = (size_t)l * DM * DM;
        size_t bO  = (size_t)l * DM;
        size_t w1O = (size_t)l * DM * FF;
        size_t b1O = (size_t)l * FF;
        size_t w2O = (size_t)l * FF * DM;

        tgemm_kernel<<<gridP, 256, TGEMM_SMEM>>>(h, Wq + wO, bq + bO, q, S, DM, DM, SCALE, 0);
        tgemm_kernel<<<gridP, 256, TGEMM_SMEM>>>(h, Wk + wO, bk + bO, k, S, DM, DM, 1.0f, 0);
        tgemm_kernel<<<gridP, 256, TGEMM_SMEM>>>(h, Wv + wO, bv + bO, v, S, DM, DM, 1.0f, 0);
        local_attn_kernel<<<gridAtt, 256>>>(q, k, v, attn);

        qg_kernel<<<gridQg, 128>>>(h, Wqg + wO, bqg + bO, qg);
        tgemm_kernel<<<gridP, 256, TGEMM_SMEM>>>(h, Wkg + wO, bkg + bO, kg, S, DM, DM, 1.0f, 0);
        tgemm_kernel<<<gridP, 256, TGEMM_SMEM>>>(h, Wvg + wO, bvg + bO, vg, S, DM, DM, 1.0f, 0);
        global_attn_kernel<<<gridGA, 256>>>(qg, kg, vg, attn);

        tgemm_kernel<<<gridP, 256, TGEMM_SMEM>>>(attn, Wo + wO, bo + bO, y, S, DM, DM, 1.0f, 0);
        add_ln_kernel<<<S, 256>>>(h, y, ln1s + bO, ln1b + bO, h);

        tgemm_kernel<<<gridF1, 256, TGEMM_SMEM>>>(h, W1 + w1O, b1 + b1O, ffn, S, FF, DM, 1.0f, 1);
        tgemm_kernel<<<gridF2, 256, TGEMM_SMEM>>>(ffn, W2 + w2O, b2 + bO, y, S, DM, FF, 1.0f, 0);
        add_ln_kernel<<<S, 256>>>(h, y, ln2s + bO, ln2b + bO, h);
    }

    head_kernel<<<NW, 128>>>(h, Wout, bout, out);
}

// round 6
// speedup vs baseline: 1.2724x; 1.2247x over previous
#include <cuda_runtime.h>
#include <cuda_fp16.h>
#include <math.h>
#include <stdint.h>

// ---------------- problem constants ----------------
#define S     4096
#define DM    768
#define FF    3072
#define HNUM  12
#define HD    64
#define WIN   256
#define CCH   16          // chunks
#define NW    8           // global tokens
#define LNUM  12
#define OUTD  128
#define SCALE 0.125f      // 1/sqrt(64)

// ---------------- scratch ----------------
__device__ float g_h   [S*DM];
__device__ float g_q   [S*DM];
__device__ float g_k   [S*DM];
__device__ float g_v   [S*DM];
__device__ float g_kg  [S*DM];
__device__ float g_vg  [S*DM];
__device__ float g_attn[S*DM];
__device__ float g_y   [S*DM];
__device__ float g_ffn [S*FF];
__device__ float g_qg  [NW*DM];

// fp16 weight copies (converted once per launch)
__device__ __half g_hWq [LNUM*DM*DM];
__device__ __half g_hWk [LNUM*DM*DM];
__device__ __half g_hWv [LNUM*DM*DM];
__device__ __half g_hWo [LNUM*DM*DM];
__device__ __half g_hWkg[LNUM*DM*DM];
__device__ __half g_hWvg[LNUM*DM*DM];
__device__ __half g_hW1 [LNUM*DM*FF];
__device__ __half g_hW2 [LNUM*FF*DM];

// ---------------- helpers ----------------
__device__ __forceinline__ float gelu_f(float x) {
    float x3 = x * x * x;
    return 0.5f * x * (1.0f + tanhf(0.7978845608028654f * (x + 0.044715f * x3)));
}

__device__ __forceinline__ unsigned pack_h2(float a, float b) {
    __half2 p = __float22half2_rn(make_float2(a, b));
    return *reinterpret_cast<unsigned*>(&p);
}

// ---------------- fp32 -> fp16 conversion ----------------
__global__ void f2h_kernel(const float4* __restrict__ in, uint2* __restrict__ out, int n4)
{
    for (int i = blockIdx.x * blockDim.x + threadIdx.x; i < n4; i += gridDim.x * blockDim.x) {
        float4 v = in[i];
        uint2 o;
        o.x = pack_h2(v.x, v.y);
        o.y = pack_h2(v.z, v.w);
        out[i] = o;
    }
}

// ---------------- embedding + LN ----------------
__global__ void embed_kernel(const int* __restrict__ x, const float* __restrict__ we,
                             const float* __restrict__ pe, const float* __restrict__ ls,
                             const float* __restrict__ lb, float* __restrict__ h)
{
    int s = blockIdx.x;
    int tid = threadIdx.x;
    int r = s & 511, w = s >> 9;
    int id = (r == 0) ? 0 : x[w * 511 + r - 1];
    __shared__ float red[256];
    float vals[3];
    float sum = 0.f;
#pragma unroll
    for (int i = 0; i < 3; i++) {
        int d = tid + i * 256;
        vals[i] = we[(size_t)id * DM + d] + pe[s * DM + d];
        sum += vals[i];
    }
    red[tid] = sum; __syncthreads();
    for (int o = 128; o > 0; o >>= 1) { if (tid < o) red[tid] += red[tid + o]; __syncthreads(); }
    float mean = red[0] / (float)DM;
    __syncthreads();
    float vsum = 0.f;
#pragma unroll
    for (int i = 0; i < 3; i++) { float t = vals[i] - mean; vsum += t * t; }
    red[tid] = vsum; __syncthreads();
    for (int o = 128; o > 0; o >>= 1) { if (tid < o) red[tid] += red[tid + o]; __syncthreads(); }
    float rstd = rsqrtf(red[0] / (float)DM + 1e-5f);
#pragma unroll
    for (int i = 0; i < 3; i++) {
        int d = tid + i * 256;
        h[s * DM + d] = (vals[i] - mean) * rstd * ls[d] + lb[d];
    }
}

// ---------------- residual add + LN ----------------
__global__ void add_ln_kernel(const float* __restrict__ x, const float* __restrict__ y,
                              const float* __restrict__ ls, const float* __restrict__ lb,
                              float* __restrict__ o)
{
    int s = blockIdx.x;
    int tid = threadIdx.x;
    __shared__ float red[256];
    float vals[3];
    float sum = 0.f;
#pragma unroll
    for (int i = 0; i < 3; i++) {
        int d = tid + i * 256;
        vals[i] = x[(size_t)s * DM + d] + y[(size_t)s * DM + d];
        sum += vals[i];
    }
    red[tid] = sum; __syncthreads();
    for (int off = 128; off > 0; off >>= 1) { if (tid < off) red[tid] += red[tid + off]; __syncthreads(); }
    float mean = red[0] / (float)DM;
    __syncthreads();
    float vsum = 0.f;
#pragma unroll
    for (int i = 0; i < 3; i++) { float t = vals[i] - mean; vsum += t * t; }
    red[tid] = vsum; __syncthreads();
    for (int off = 128; off > 0; off >>= 1) { if (tid < off) red[tid] += red[tid + off]; __syncthreads(); }
    float rstd = rsqrtf(red[0] / (float)DM + 1e-5f);
#pragma unroll
    for (int i = 0; i < 3; i++) {
        int d = tid + i * 256;
        o[(size_t)s * DM + d] = (vals[i] - mean) * rstd * ls[d] + lb[d];
    }
}

// ---------------- fp16 tensor-core GEMM (batched over blockIdx.z) ----------------
// Cz[M,N] = act((A[M,K](fp32->fp16 staged) @ Bz[K,N](fp16) + biasz) * alphaz)
// BM=128 BN=128 BK=64, 256 threads = 8 warps, warp tile 64x32 (2x4 warp grid)
__global__ __launch_bounds__(256)
void hgemm_kernel(const float* __restrict__ A,
                  const __half* B0, const __half* B1, const __half* B2,
                  const float* bias0, const float* bias1, const float* bias2,
                  float* C0, float* C1, float* C2,
                  int M, int N, int K,
                  float al0, float al1, float al2, int act)
{
    __shared__ __align__(16) __half As[128][72];   // row stride 144B, conflict-free ldmatrix
    __shared__ __align__(16) __half Bs[64][136];   // row stride 272B

    const __half* B = (blockIdx.z == 0) ? B0 : (blockIdx.z == 1) ? B1 : B2;
    const float* bias = (blockIdx.z == 0) ? bias0 : (blockIdx.z == 1) ? bias1 : bias2;
    float* C = (blockIdx.z == 0) ? C0 : (blockIdx.z == 1) ? C1 : C2;
    const float alpha = (blockIdx.z == 0) ? al0 : (blockIdx.z == 1) ? al1 : al2;

    const int tid  = threadIdx.x;
    const int lane = tid & 31;
    const int warp = tid >> 5;
    const int wm = warp >> 2;     // 0..1
    const int wn = warp & 3;      // 0..3

    const int bRow = blockIdx.y * 128;
    const int bCol = blockIdx.x * 128;

    float acc[4][4][4];
#pragma unroll
    for (int i = 0; i < 4; i++)
#pragma unroll
        for (int j = 0; j < 4; j++)
#pragma unroll
            for (int r = 0; r < 4; r++) acc[i][j][r] = 0.f;

    // A-load mapping: thread -> (row, 32-float half)
    const int a_row = tid >> 1;
    const int a_col = (tid & 1) * 32;
    // B-load mapping: 16 chunks of 8 halves per row, 16 rows per pass
    const int b_col = (tid & 15) * 8;
    const int b_row = tid >> 4;

    for (int k0 = 0; k0 < K; k0 += 64) {
        // stage A tile (fp32 -> fp16)
        const float* Ag = A + (size_t)(bRow + a_row) * K + k0 + a_col;
#pragma unroll
        for (int c = 0; c < 32; c += 8) {
            float4 v0 = *(const float4*)(Ag + c);
            float4 v1 = *(const float4*)(Ag + c + 4);
            uint4 pk;
            pk.x = pack_h2(v0.x, v0.y);
            pk.y = pack_h2(v0.z, v0.w);
            pk.z = pack_h2(v1.x, v1.y);
            pk.w = pack_h2(v1.z, v1.w);
            *(uint4*)&As[a_row][a_col + c] = pk;
        }
        // stage B tile (fp16 copy)
#pragma unroll
        for (int p = 0; p < 4; p++) {
            int r = p * 16 + b_row;
            uint4 v = *(const uint4*)(B + (size_t)(k0 + r) * N + bCol + b_col);
            *(uint4*)&Bs[r][b_col] = v;
        }
        __syncthreads();

#pragma unroll
        for (int kk = 0; kk < 64; kk += 16) {
            uint32_t af[4][4];
#pragma unroll
            for (int mi = 0; mi < 4; mi++) {
                uint32_t addr = (uint32_t)__cvta_generic_to_shared(
                    &As[wm * 64 + mi * 16 + (lane & 15)][kk + (lane >> 4) * 8]);
                asm volatile("ldmatrix.sync.aligned.m8n8.x4.shared.b16 {%0,%1,%2,%3}, [%4];"
                             : "=r"(af[mi][0]), "=r"(af[mi][1]), "=r"(af[mi][2]), "=r"(af[mi][3])
                             : "r"(addr));
            }
            uint32_t bfr[4][2];
#pragma unroll
            for (int nb = 0; nb < 2; nb++) {
                uint32_t addr = (uint32_t)__cvta_generic_to_shared(
                    &Bs[kk + (lane & 15)][wn * 32 + nb * 16 + (lane >> 4) * 8]);
                uint32_t r0, r1, r2, r3;
                asm volatile("ldmatrix.sync.aligned.m8n8.x4.trans.shared.b16 {%0,%1,%2,%3}, [%4];"
                             : "=r"(r0), "=r"(r1), "=r"(r2), "=r"(r3)
                             : "r"(addr));
                bfr[nb * 2][0] = r0; bfr[nb * 2][1] = r1;
                bfr[nb * 2 + 1][0] = r2; bfr[nb * 2 + 1][1] = r3;
            }
#pragma unroll
            for (int mi = 0; mi < 4; mi++)
#pragma unroll
                for (int ni = 0; ni < 4; ni++) {
                    asm volatile(
                        "mma.sync.aligned.m16n8k16.row.col.f32.f16.f16.f32 "
                        "{%0,%1,%2,%3}, {%4,%5,%6,%7}, {%8,%9}, {%0,%1,%2,%3};"
                        : "+f"(acc[mi][ni][0]), "+f"(acc[mi][ni][1]),
                          "+f"(acc[mi][ni][2]), "+f"(acc[mi][ni][3])
                        : "r"(af[mi][0]), "r"(af[mi][1]), "r"(af[mi][2]), "r"(af[mi][3]),
                          "r"(bfr[ni][0]), "r"(bfr[ni][1]));
                }
        }
        __syncthreads();
    }

    // epilogue
#pragma unroll
    for (int mi = 0; mi < 4; mi++) {
        int row0 = bRow + wm * 64 + mi * 16 + (lane >> 2);
#pragma unroll
        for (int ni = 0; ni < 4; ni++) {
            int col = bCol + wn * 32 + ni * 8 + (lane & 3) * 2;
            float b0 = bias[col], b1 = bias[col + 1];
            float v0 = (acc[mi][ni][0] + b0) * alpha;
            float v1 = (acc[mi][ni][1] + b1) * alpha;
            float v2 = (acc[mi][ni][2] + b0) * alpha;
            float v3 = (acc[mi][ni][3] + b1) * alpha;
            if (act == 1) { v0 = gelu_f(v0); v1 = gelu_f(v1); v2 = gelu_f(v2); v3 = gelu_f(v3); }
            *(float2*)&C[(size_t)row0 * N + col]       = make_float2(v0, v1);
            *(float2*)&C[(size_t)(row0 + 8) * N + col] = make_float2(v2, v3);
        }
    }
}

// ---------------- local (sliding-window + global-key) attention ----------------
__global__ __launch_bounds__(256, 1)
void local_attn_kernel(const float* __restrict__ q, const float* __restrict__ k,
                       const float* __restrict__ v, float* __restrict__ out)
{
    int c = blockIdx.x, hh = blockIdx.y;
    int qi = threadIdx.x;
    int qpos = c * WIN + qi;
    int hoff = hh * HD;

    float qreg[HD];
#pragma unroll
    for (int d = 0; d < HD; d++) qreg[d] = q[(size_t)qpos * DM + hoff + d];

    __shared__ float ks[16][HD];
    __shared__ float vs[16][HD];

    float m = -1e30f, l = 0.f;
    float acc[HD];
#pragma unroll
    for (int d = 0; d < HD; d++) acc[d] = 0.f;

    // ---- global keys (8) ----
    {
        int tt = threadIdx.x;
        if (tt < 128) {
            int gg = tt / 16;
            int d4 = (tt % 16) * 4;
            int gpos = gg * 512;
            *(float4*)&ks[gg][d4] = *(const float4*)&k[(size_t)gpos * DM + hoff + d4];
            *(float4*)&vs[gg][d4] = *(const float4*)&v[(size_t)gpos * DM + hoff + d4];
        }
        __syncthreads();
        float s[8];
        float tmax = m;
#pragma unroll
        for (int j = 0; j < 8; j++) {
            float a = 0.f;
#pragma unroll
            for (int d = 0; d < HD; d++) a += qreg[d] * ks[j][d];
            s[j] = a;
            tmax = fmaxf(tmax, a);
        }
        float sc = __expf(m - tmax);
        l *= sc;
#pragma unroll
        for (int d = 0; d < HD; d++) acc[d] *= sc;
#pragma unroll
        for (int j = 0; j < 8; j++) {
            float p = __expf(s[j] - tmax);
            l += p;
#pragma unroll
            for (int d = 0; d < HD; d++) acc[d] += p * vs[j][d];
        }
        m = tmax;
    }

    // ---- local window: 48 tiles of 16 keys ----
    for (int t0 = 0; t0 < 48; t0++) {
        int tt = threadIdx.x;
        int j = tt / 16;
        int d4 = (tt % 16) * 4;
        int jglob = t0 * 16 + j;
        int kpos = c * WIN + jglob - WIN;
        float4 kv4 = make_float4(0.f, 0.f, 0.f, 0.f);
        float4 vv4 = make_float4(0.f, 0.f, 0.f, 0.f);
        if (kpos >= 0 && kpos < S) {
            kv4 = *(const float4*)&k[(size_t)kpos * DM + hoff + d4];
            vv4 = *(const float4*)&v[(size_t)kpos * DM + hoff + d4];
        }
        __syncthreads();
        *(float4*)&ks[j][d4] = kv4;
        *(float4*)&vs[j][d4] = vv4;
        __syncthreads();

        float s[16];
        float tmax = m;
#pragma unroll
        for (int jj = 0; jj < 16; jj++) {
            int jg = t0 * 16 + jj;
            int kp = c * WIN + jg - WIN;
            bool valid = (jg >= qi) && (jg <= qi + 2 * WIN) && (kp >= 0) && (kp < S);
            float a = 0.f;
#pragma unroll
            for (int d = 0; d < HD; d++) a += qreg[d] * ks[jj][d];
            s[jj] = valid ? a : -1e30f;
            tmax = fmaxf(tmax, s[jj]);
        }
        float sc = __expf(m - tmax);
        l *= sc;
#pragma unroll
        for (int d = 0; d < HD; d++) acc[d] *= sc;
#pragma unroll
        for (int jj = 0; jj < 16; jj++) {
            float p = __expf(s[jj] - tmax);
            l += p;
#pragma unroll
            for (int d = 0; d < HD; d++) acc[d] += p * vs[jj][d];
        }
        m = tmax;
    }

    float inv = 1.f / l;
#pragma unroll
    for (int d = 0; d < HD; d++)
        out[(size_t)qpos * DM + hoff + d] = acc[d] * inv;
}

// ---------------- qg projection ----------------
__global__ void qg_kernel(const float* __restrict__ h, const float* __restrict__ Wqg,
                          const float* __restrict__ bqg, float* __restrict__ qg)
{
    int g = blockIdx.x;
    int o = blockIdx.y * 128 + threadIdx.x;
    const float* hr = h + (size_t)(g * 512) * DM;
    float a = bqg[o];
    for (int d = 0; d < DM; d++) a += hr[d] * Wqg[(size_t)d * DM + o];
    qg[g * DM + o] = a * SCALE;
}

// ---------------- global-token full attention ----------------
__global__ void global_attn_kernel(const float* __restrict__ qg, const float* __restrict__ kg,
                                   const float* __restrict__ vg, float* __restrict__ out)
{
    int g = blockIdx.x, hh = blockIdx.y;
    int hoff = hh * HD;
    int tid = threadIdx.x;
    __shared__ float qs[HD];
    __shared__ float sc[S];
    __shared__ float red[256];
    if (tid < HD) qs[tid] = qg[g * DM + hoff + tid];
    __syncthreads();

    float lmax = -1e30f;
    for (int i = 0; i < 16; i++) {
        int s = i * 256 + tid;
        const float* kr = kg + (size_t)s * DM + hoff;
        float a = 0.f;
#pragma unroll
        for (int d = 0; d < HD; d++) a += qs[d] * kr[d];
        sc[s] = a;
        lmax = fmaxf(lmax, a);
    }
    red[tid] = lmax; __syncthreads();
    for (int o = 128; o > 0; o >>= 1) { if (tid < o) red[tid] = fmaxf(red[tid], red[tid + o]); __syncthreads(); }
    float mx = red[0]; __syncthreads();

    float lsum = 0.f;
    for (int i = 0; i < 16; i++) {
        int s = i * 256 + tid;
        float p = __expf(sc[s] - mx);
        sc[s] = p;
        lsum += p;
    }
    red[tid] = lsum; __syncthreads();
    for (int o = 128; o > 0; o >>= 1) { if (tid < o) red[tid] += red[tid + o]; __syncthreads(); }
    float inv = 1.f / red[0]; __syncthreads();

    int d = tid & 63;
    int part = tid >> 6;
    float a = 0.f;
    for (int s = part * 1024; s < (part + 1) * 1024; s++)
        a += sc[s] * vg[(size_t)s * DM + hoff + d];
    red[tid] = a; __syncthreads();
    if (tid < 64) {
        float r = red[tid] + red[tid + 64] + red[tid + 128] + red[tid + 192];
        out[(size_t)(g * 512) * DM + hoff + d] = r * inv;
    }
}

// ---------------- output head ----------------
__global__ void head_kernel(const float* __restrict__ h, const float* __restrict__ Wout,
                            const float* __restrict__ bout, float* __restrict__ out)
{
    int g = blockIdx.x;
    int o = threadIdx.x; // 128
    const float* hr = h + (size_t)(g * 512) * DM;
    float a = bout[o];
    for (int d = 0; d < DM; d++) a += hr[d] * Wout[(size_t)d * OUTD + o];
    out[g * OUTD + o] = a;
}

// ---------------- driver ----------------
extern "C" void kernel_launch(void* const* d_in, const int* in_sizes, int n_in,
                              void* d_out, int out_size)
{
    (void)in_sizes; (void)n_in; (void)out_size;
    const int*   x        = (const int*)  d_in[0];
    const float* word_emb = (const float*)d_in[1];
    const float* pos_emb  = (const float*)d_in[2];
    const float* emb_ln_s = (const float*)d_in[3];
    const float* emb_ln_b = (const float*)d_in[4];
    const float* Wq  = (const float*)d_in[5];   const float* bq  = (const float*)d_in[6];
    const float* Wk  = (const float*)d_in[7];   const float* bk  = (const float*)d_in[8];
    const float* Wv  = (const float*)d_in[9];   const float* bv  = (const float*)d_in[10];
    const float* Wo  = (const float*)d_in[11];  const float* bo  = (const float*)d_in[12];
    const float* Wqg = (const float*)d_in[13];  const float* bqg = (const float*)d_in[14];
    const float* Wkg = (const float*)d_in[15];  const float* bkg = (const float*)d_in[16];
    const float* Wvg = (const float*)d_in[17];  const float* bvg = (const float*)d_in[18];
    const float* ln1s= (const float*)d_in[19];  const float* ln1b= (const float*)d_in[20];
    const float* W1  = (const float*)d_in[21];  const float* b1  = (const float*)d_in[22];
    const float* W2  = (const float*)d_in[23];  const float* b2  = (const float*)d_in[24];
    const float* ln2s= (const float*)d_in[25];  const float* ln2b= (const float*)d_in[26];
    const float* Wout= (const float*)d_in[27];  const float* bout= (const float*)d_in[28];
    float* out = (float*)d_out;

    float *h, *q, *k, *v, *kg, *vg, *attn, *y, *ffn, *qg;
    cudaGetSymbolAddress((void**)&h,    g_h);
    cudaGetSymbolAddress((void**)&q,    g_q);
    cudaGetSymbolAddress((void**)&k,    g_k);
    cudaGetSymbolAddress((void**)&v,    g_v);
    cudaGetSymbolAddress((void**)&kg,   g_kg);
    cudaGetSymbolAddress((void**)&vg,   g_vg);
    cudaGetSymbolAddress((void**)&attn, g_attn);
    cudaGetSymbolAddress((void**)&y,    g_y);
    cudaGetSymbolAddress((void**)&ffn,  g_ffn);
    cudaGetSymbolAddress((void**)&qg,   g_qg);

    __half *hWq, *hWk, *hWv, *hWo, *hWkg, *hWvg, *hW1, *hW2;
    cudaGetSymbolAddress((void**)&hWq,  g_hWq);
    cudaGetSymbolAddress((void**)&hWk,  g_hWk);
    cudaGetSymbolAddress((void**)&hWv,  g_hWv);
    cudaGetSymbolAddress((void**)&hWo,  g_hWo);
    cudaGetSymbolAddress((void**)&hWkg, g_hWkg);
    cudaGetSymbolAddress((void**)&hWvg, g_hWvg);
    cudaGetSymbolAddress((void**)&hW1,  g_hW1);
    cudaGetSymbolAddress((void**)&hW2,  g_hW2);

    // weight conversion (bandwidth-bound, ~130us total)
    const int nP4 = LNUM * DM * DM / 4;
    const int nF4 = LNUM * DM * FF / 4;
    f2h_kernel<<<2048, 256>>>((const float4*)Wq,  (uint2*)hWq,  nP4);
    f2h_kernel<<<2048, 256>>>((const float4*)Wk,  (uint2*)hWk,  nP4);
    f2h_kernel<<<2048, 256>>>((const float4*)Wv,  (uint2*)hWv,  nP4);
    f2h_kernel<<<2048, 256>>>((const float4*)Wo,  (uint2*)hWo,  nP4);
    f2h_kernel<<<2048, 256>>>((const float4*)Wkg, (uint2*)hWkg, nP4);
    f2h_kernel<<<2048, 256>>>((const float4*)Wvg, (uint2*)hWvg, nP4);
    f2h_kernel<<<2048, 256>>>((const float4*)W1,  (uint2*)hW1,  nF4);
    f2h_kernel<<<2048, 256>>>((const float4*)W2,  (uint2*)hW2,  nF4);

    embed_kernel<<<S, 256>>>(x, word_emb, pos_emb, emb_ln_s, emb_ln_b, h);

    dim3 gridQKV(DM / 128, S / 128, 3);  // 6 x 32 x 3
    dim3 gridKV (DM / 128, S / 128, 2);  // 6 x 32 x 2
    dim3 gridP  (DM / 128, S / 128, 1);  // 6 x 32
    dim3 gridF1 (FF / 128, S / 128, 1);  // 24 x 32
    dim3 gridF2 (DM / 128, S / 128, 1);  // 6 x 32
    dim3 gridAtt(CCH, HNUM);             // 16 x 12
    dim3 gridQg (NW, DM / 128);          // 8 x 6
    dim3 gridGA (NW, HNUM);              // 8 x 12

    for (int l = 0; l < LNUM; l++) {
        size_t wO  = (size_t)l * DM * DM;
        size_t bO  = (size_t)l * DM;
        size_t w1O = (size_t)l * DM * FF;
        size_t b1O = (size_t)l * FF;
        size_t w2O = (size_t)l * FF * DM;

        // fused Q,K,V projections (grid.z selects)
        hgemm_kernel<<<gridQKV, 256>>>(h,
            hWq + wO, hWk + wO, hWv + wO,
            bq + bO, bk + bO, bv + bO,
            q, k, v, S, DM, DM, SCALE, 1.0f, 1.0f, 0);
        local_attn_kernel<<<gridAtt, 256>>>(q, k, v, attn);

        qg_kernel<<<gridQg, 128>>>(h, Wqg + wO, bqg + bO, qg);
        hgemm_kernel<<<gridKV, 256>>>(h,
            hWkg + wO, hWvg + wO, hWvg + wO,
            bkg + bO, bvg + bO, bvg + bO,
            kg, vg, vg, S, DM, DM, 1.0f, 1.0f, 1.0f, 0);
        global_attn_kernel<<<gridGA, 256>>>(qg, kg, vg, attn);

        hgemm_kernel<<<gridP, 256>>>(attn,
            hWo + wO, hWo + wO, hWo + wO,
            bo + bO, bo + bO, bo + bO,
            y, y, y, S, DM, DM, 1.0f, 1.0f, 1.0f, 0);
        add_ln_kernel<<<S, 256>>>(h, y, ln1s + bO, ln1b + bO, h);

        hgemm_kernel<<<gridF1, 256>>>(h,
            hW1 + w1O, hW1 + w1O, hW1 + w1O,
            b1 + b1O, b1 + b1O, b1 + b1O,
            ffn, ffn, ffn, S, FF, DM, 1.0f, 1.0f, 1.0f, 1);
        hgemm_kernel<<<gridF2, 256>>>(ffn,
            hW2 + w2O, hW2 + w2O, hW2 + w2O,
            b2 + bO, b2 + bO, b2 + bO,
            y, y, y, S, DM, FF, 1.0f, 1.0f, 1.0f, 0);
        add_ln_kernel<<<S, 256>>>(h, y, ln2s + bO, ln2b + bO, h);
    }

    head_kernel<<<NW, 128>>>(h, Wout, bout, out);
}

// round 7
// speedup vs baseline: 1.6242x; 1.2765x over previous
#include <cuda_runtime.h>
#include <cuda_fp16.h>
#include <math.h>
#include <stdint.h>

// ---------------- problem constants ----------------
#define S     4096
#define DM    768
#define FF    3072
#define HNUM  12
#define HD    64
#define WIN   256
#define CCH   16          // chunks
#define NW    8           // global tokens
#define LNUM  12
#define OUTD  128
#define SCALE 0.125f      // 1/sqrt(64)

// ---------------- scratch ----------------
__device__ float g_h    [S*DM];
__device__ float g_q    [S*DM];
__device__ float g_k    [S*DM];
__device__ float g_v    [S*DM];
__device__ float g_kg   [S*DM];
__device__ float g_vg   [S*DM];
__device__ float g_y    [S*DM];
__device__ float g_qg   [NW*DM];
__device__ __half g_h16   [S*DM];
__device__ __half g_attn16[S*DM];
__device__ __half g_ffn16 [S*FF];

// fp16 weight copies (converted once per launch)
__device__ __half g_hWq [LNUM*DM*DM];
__device__ __half g_hWk [LNUM*DM*DM];
__device__ __half g_hWv [LNUM*DM*DM];
__device__ __half g_hWo [LNUM*DM*DM];
__device__ __half g_hWkg[LNUM*DM*DM];
__device__ __half g_hWvg[LNUM*DM*DM];
__device__ __half g_hW1 [LNUM*DM*FF];
__device__ __half g_hW2 [LNUM*FF*DM];

// ---------------- helpers ----------------
__device__ __forceinline__ float gelu_f(float x) {
    float x3 = x * x * x;
    return 0.5f * x * (1.0f + tanhf(0.7978845608028654f * (x + 0.044715f * x3)));
}

__device__ __forceinline__ unsigned pack_h2(float a, float b) {
    __half2 p = __float22half2_rn(make_float2(a, b));
    return *reinterpret_cast<unsigned*>(&p);
}

__device__ __forceinline__ void cp_async16(void* smem_dst, const void* gmem_src) {
    uint32_t dst = (uint32_t)__cvta_generic_to_shared(smem_dst);
    asm volatile("cp.async.ca.shared.global [%0], [%1], 16;" :: "r"(dst), "l"(gmem_src));
}

// ---------------- fp32 -> fp16 conversion ----------------
__global__ void f2h_kernel(const float4* __restrict__ in, uint2* __restrict__ out, int n4)
{
    for (int i = blockIdx.x * blockDim.x + threadIdx.x; i < n4; i += gridDim.x * blockDim.x) {
        float4 v = in[i];
        uint2 o;
        o.x = pack_h2(v.x, v.y);
        o.y = pack_h2(v.z, v.w);
        out[i] = o;
    }
}

// ---------------- embedding + LN (writes fp32 + fp16 shadow) ----------------
__global__ void embed_kernel(const int* __restrict__ x, const float* __restrict__ we,
                             const float* __restrict__ pe, const float* __restrict__ ls,
                             const float* __restrict__ lb, float* __restrict__ h,
                             __half* __restrict__ h16)
{
    int s = blockIdx.x;
    int tid = threadIdx.x;
    int r = s & 511, w = s >> 9;
    int id = (r == 0) ? 0 : x[w * 511 + r - 1];
    __shared__ float red[256];
    float vals[3];
    float sum = 0.f;
#pragma unroll
    for (int i = 0; i < 3; i++) {
        int d = tid + i * 256;
        vals[i] = we[(size_t)id * DM + d] + pe[s * DM + d];
        sum += vals[i];
    }
    red[tid] = sum; __syncthreads();
    for (int o = 128; o > 0; o >>= 1) { if (tid < o) red[tid] += red[tid + o]; __syncthreads(); }
    float mean = red[0] / (float)DM;
    __syncthreads();
    float vsum = 0.f;
#pragma unroll
    for (int i = 0; i < 3; i++) { float t = vals[i] - mean; vsum += t * t; }
    red[tid] = vsum; __syncthreads();
    for (int o = 128; o > 0; o >>= 1) { if (tid < o) red[tid] += red[tid + o]; __syncthreads(); }
    float rstd = rsqrtf(red[0] / (float)DM + 1e-5f);
#pragma unroll
    for (int i = 0; i < 3; i++) {
        int d = tid + i * 256;
        float o = (vals[i] - mean) * rstd * ls[d] + lb[d];
        h[s * DM + d] = o;
        h16[s * DM + d] = __float2half(o);
    }
}

// ---------------- residual add + LN (fp32 + fp16 shadow) ----------------
__global__ void add_ln_kernel(const float* __restrict__ x, const float* __restrict__ y,
                              const float* __restrict__ ls, const float* __restrict__ lb,
                              float* __restrict__ o, __half* __restrict__ o16)
{
    int s = blockIdx.x;
    int tid = threadIdx.x;
    __shared__ float red[256];
    float vals[3];
    float sum = 0.f;
#pragma unroll
    for (int i = 0; i < 3; i++) {
        int d = tid + i * 256;
        vals[i] = x[(size_t)s * DM + d] + y[(size_t)s * DM + d];
        sum += vals[i];
    }
    red[tid] = sum; __syncthreads();
    for (int off = 128; off > 0; off >>= 1) { if (tid < off) red[tid] += red[tid + off]; __syncthreads(); }
    float mean = red[0] / (float)DM;
    __syncthreads();
    float vsum = 0.f;
#pragma unroll
    for (int i = 0; i < 3; i++) { float t = vals[i] - mean; vsum += t * t; }
    red[tid] = vsum; __syncthreads();
    for (int off = 128; off > 0; off >>= 1) { if (tid < off) red[tid] += red[tid + off]; __syncthreads(); }
    float rstd = rsqrtf(red[0] / (float)DM + 1e-5f);
#pragma unroll
    for (int i = 0; i < 3; i++) {
        int d = tid + i * 256;
        float ov = (vals[i] - mean) * rstd * ls[d] + lb[d];
        o[(size_t)s * DM + d] = ov;
        o16[(size_t)s * DM + d] = __float2half(ov);
    }
}

// ---------------- fp16 tensor-core GEMM, cp.async 2-stage, batched over z ----------------
// Cz = act((A[M,K](fp16) @ Bz[K,N](fp16) + biasz) * alphaz)
// BM=128 BN=128 BK=64, 256 threads, warp tile 64x32.
// smem halves per stage: A 128*72=9216, B 64*136=8704; 2 stages = 71680 bytes.
#define AS_H    9216
#define STG_H   17920
#define TGEMM_SMEM (2 * STG_H * 2)

__global__ __launch_bounds__(256)
void hgemm_kernel(const __half* __restrict__ A,
                  const __half* B0, const __half* B1, const __half* B2,
                  const float* bias0, const float* bias1, const float* bias2,
                  void* C0, void* C1, void* C2,
                  int M, int N, int K,
                  float al0, float al1, float al2, int act, int outHalf)
{
    extern __shared__ __half sm[];

    const __half* B = (blockIdx.z == 0) ? B0 : (blockIdx.z == 1) ? B1 : B2;
    const float* bias = (blockIdx.z == 0) ? bias0 : (blockIdx.z == 1) ? bias1 : bias2;
    void* C = (blockIdx.z == 0) ? C0 : (blockIdx.z == 1) ? C1 : C2;
    const float alpha = (blockIdx.z == 0) ? al0 : (blockIdx.z == 1) ? al1 : al2;

    const int tid  = threadIdx.x;
    const int lane = tid & 31;
    const int warp = tid >> 5;
    const int wm = warp >> 2;
    const int wn = warp & 3;

    const int bRow = blockIdx.y * 128;
    const int bCol = blockIdx.x * 128;

    float acc[4][4][4];
#pragma unroll
    for (int i = 0; i < 4; i++)
#pragma unroll
        for (int j = 0; j < 4; j++)
#pragma unroll
            for (int r = 0; r < 4; r++) acc[i][j][r] = 0.f;

    const int nk = K >> 6;

    // stage-issue helper indices (A: 1024 16B-chunks; B: 1024 16B-chunks)
    // A: id>>3 = row(0..127), (id&7)*8 = col;  B: id>>4 = row(0..63), (id&15)*8 = col
    // prologue: stage 0
    {
        __half* as = sm;
        __half* bs = sm + AS_H;
#pragma unroll
        for (int p = 0; p < 4; p++) {
            int id = p * 256 + tid;
            int r = id >> 3, c = (id & 7) * 8;
            cp_async16(as + r * 72 + c, A + (size_t)(bRow + r) * K + c);
        }
#pragma unroll
        for (int p = 0; p < 4; p++) {
            int id = p * 256 + tid;
            int r = id >> 4, c = (id & 15) * 8;
            cp_async16(bs + r * 136 + c, B + (size_t)r * N + bCol + c);
        }
        asm volatile("cp.async.commit_group;" ::);
    }

    for (int kt = 0; kt < nk; kt++) {
        asm volatile("cp.async.wait_group 0;" ::);
        __syncthreads();   // stage kt resident; all warps done with stage kt-1 buffer

        // issue stage kt+1 into the other buffer (overlaps MMAs below)
        if (kt + 1 < nk) {
            const int k0 = (kt + 1) << 6;
            __half* as = sm + ((kt + 1) & 1) * STG_H;
            __half* bs = as + AS_H;
#pragma unroll
            for (int p = 0; p < 4; p++) {
                int id = p * 256 + tid;
                int r = id >> 3, c = (id & 7) * 8;
                cp_async16(as + r * 72 + c, A + (size_t)(bRow + r) * K + k0 + c);
            }
#pragma unroll
            for (int p = 0; p < 4; p++) {
                int id = p * 256 + tid;
                int r = id >> 4, c = (id & 15) * 8;
                cp_async16(bs + r * 136 + c, B + (size_t)(k0 + r) * N + bCol + c);
            }
            asm volatile("cp.async.commit_group;" ::);
        }

        const __half* as = sm + (kt & 1) * STG_H;
        const __half* bs = as + AS_H;
#pragma unroll
        for (int kk = 0; kk < 64; kk += 16) {
            uint32_t af[4][4];
#pragma unroll
            for (int mi = 0; mi < 4; mi++) {
                uint32_t addr = (uint32_t)__cvta_generic_to_shared(
                    as + (wm * 64 + mi * 16 + (lane & 15)) * 72 + kk + (lane >> 4) * 8);
                asm volatile("ldmatrix.sync.aligned.m8n8.x4.shared.b16 {%0,%1,%2,%3}, [%4];"
                             : "=r"(af[mi][0]), "=r"(af[mi][1]), "=r"(af[mi][2]), "=r"(af[mi][3])
                             : "r"(addr));
            }
            uint32_t bfr[4][2];
#pragma unroll
            for (int nb = 0; nb < 2; nb++) {
                uint32_t addr = (uint32_t)__cvta_generic_to_shared(
                    bs + (kk + (lane & 15)) * 136 + wn * 32 + nb * 16 + (lane >> 4) * 8);
                uint32_t r0, r1, r2, r3;
                asm volatile("ldmatrix.sync.aligned.m8n8.x4.trans.shared.b16 {%0,%1,%2,%3}, [%4];"
                             : "=r"(r0), "=r"(r1), "=r"(r2), "=r"(r3)
                             : "r"(addr));
                bfr[nb * 2][0] = r0; bfr[nb * 2][1] = r1;
                bfr[nb * 2 + 1][0] = r2; bfr[nb * 2 + 1][1] = r3;
            }
#pragma unroll
            for (int mi = 0; mi < 4; mi++)
#pragma unroll
                for (int ni = 0; ni < 4; ni++) {
                    asm volatile(
                        "mma.sync.aligned.m16n8k16.row.col.f32.f16.f16.f32 "
                        "{%0,%1,%2,%3}, {%4,%5,%6,%7}, {%8,%9}, {%0,%1,%2,%3};"
                        : "+f"(acc[mi][ni][0]), "+f"(acc[mi][ni][1]),
                          "+f"(acc[mi][ni][2]), "+f"(acc[mi][ni][3])
                        : "r"(af[mi][0]), "r"(af[mi][1]), "r"(af[mi][2]), "r"(af[mi][3]),
                          "r"(bfr[ni][0]), "r"(bfr[ni][1]));
                }
        }
        __syncthreads();   // all warps done with stage kt before it is overwritten
    }

    // epilogue
#pragma unroll
    for (int mi = 0; mi < 4; mi++) {
        int row0 = bRow + wm * 64 + mi * 16 + (lane >> 2);
#pragma unroll
        for (int ni = 0; ni < 4; ni++) {
            int col = bCol + wn * 32 + ni * 8 + (lane & 3) * 2;
            float b0 = bias[col], b1 = bias[col + 1];
            float v0 = (acc[mi][ni][0] + b0) * alpha;
            float v1 = (acc[mi][ni][1] + b1) * alpha;
            float v2 = (acc[mi][ni][2] + b0) * alpha;
            float v3 = (acc[mi][ni][3] + b1) * alpha;
            if (act == 1) { v0 = gelu_f(v0); v1 = gelu_f(v1); v2 = gelu_f(v2); v3 = gelu_f(v3); }
            if (outHalf) {
                __half* Ch = (__half*)C;
                *(uint32_t*)&Ch[(size_t)row0 * N + col]       = pack_h2(v0, v1);
                *(uint32_t*)&Ch[(size_t)(row0 + 8) * N + col] = pack_h2(v2, v3);
            } else {
                float* Cf = (float*)C;
                *(float2*)&Cf[(size_t)row0 * N + col]       = make_float2(v0, v1);
                *(float2*)&Cf[(size_t)(row0 + 8) * N + col] = make_float2(v2, v3);
            }
        }
    }
}

// ---------------- local (sliding-window + global-key) attention ----------------
__global__ __launch_bounds__(256, 1)
void local_attn_kernel(const float* __restrict__ q, const float* __restrict__ k,
                       const float* __restrict__ v, __half* __restrict__ out)
{
    int c = blockIdx.x, hh = blockIdx.y;
    int qi = threadIdx.x;
    int qpos = c * WIN + qi;
    int hoff = hh * HD;

    float qreg[HD];
#pragma unroll
    for (int d = 0; d < HD; d++) qreg[d] = q[(size_t)qpos * DM + hoff + d];

    __shared__ float ks[16][HD];
    __shared__ float vs[16][HD];

    float m = -1e30f, l = 0.f;
    float acc[HD];
#pragma unroll
    for (int d = 0; d < HD; d++) acc[d] = 0.f;

    // ---- global keys (8) ----
    {
        int tt = threadIdx.x;
        if (tt < 128) {
            int gg = tt / 16;
            int d4 = (tt % 16) * 4;
            int gpos = gg * 512;
            *(float4*)&ks[gg][d4] = *(const float4*)&k[(size_t)gpos * DM + hoff + d4];
            *(float4*)&vs[gg][d4] = *(const float4*)&v[(size_t)gpos * DM + hoff + d4];
        }
        __syncthreads();
        float s[8];
        float tmax = m;
#pragma unroll
        for (int j = 0; j < 8; j++) {
            float a = 0.f;
#pragma unroll
            for (int d = 0; d < HD; d++) a += qreg[d] * ks[j][d];
            s[j] = a;
            tmax = fmaxf(tmax, a);
        }
        float sc = __expf(m - tmax);
        l *= sc;
#pragma unroll
        for (int d = 0; d < HD; d++) acc[d] *= sc;
#pragma unroll
        for (int j = 0; j < 8; j++) {
            float p = __expf(s[j] - tmax);
            l += p;
#pragma unroll
            for (int d = 0; d < HD; d++) acc[d] += p * vs[j][d];
        }
        m = tmax;
    }

    // ---- local window: 48 tiles of 16 keys ----
    for (int t0 = 0; t0 < 48; t0++) {
        int tt = threadIdx.x;
        int j = tt / 16;
        int d4 = (tt % 16) * 4;
        int jglob = t0 * 16 + j;
        int kpos = c * WIN + jglob - WIN;
        float4 kv4 = make_float4(0.f, 0.f, 0.f, 0.f);
        float4 vv4 = make_float4(0.f, 0.f, 0.f, 0.f);
        if (kpos >= 0 && kpos < S) {
            kv4 = *(const float4*)&k[(size_t)kpos * DM + hoff + d4];
            vv4 = *(const float4*)&v[(size_t)kpos * DM + hoff + d4];
        }
        __syncthreads();
        *(float4*)&ks[j][d4] = kv4;
        *(float4*)&vs[j][d4] = vv4;
        __syncthreads();

        float s[16];
        float tmax = m;
#pragma unroll
        for (int jj = 0; jj < 16; jj++) {
            int jg = t0 * 16 + jj;
            int kp = c * WIN + jg - WIN;
            bool valid = (jg >= qi) && (jg <= qi + 2 * WIN) && (kp >= 0) && (kp < S);
            float a = 0.f;
#pragma unroll
            for (int d = 0; d < HD; d++) a += qreg[d] * ks[jj][d];
            s[jj] = valid ? a : -1e30f;
            tmax = fmaxf(tmax, s[jj]);
        }
        float sc = __expf(m - tmax);
        l *= sc;
#pragma unroll
        for (int d = 0; d < HD; d++) acc[d] *= sc;
#pragma unroll
        for (int jj = 0; jj < 16; jj++) {
            float p = __expf(s[jj] - tmax);
            l += p;
#pragma unroll
            for (int d = 0; d < HD; d++) acc[d] += p * vs[jj][d];
        }
        m = tmax;
    }

    float inv = 1.f / l;
#pragma unroll
    for (int d = 0; d < HD; d++)
        out[(size_t)qpos * DM + hoff + d] = __float2half(acc[d] * inv);
}

// ---------------- qg projection ----------------
__global__ void qg_kernel(const float* __restrict__ h, const float* __restrict__ Wqg,
                          const float* __restrict__ bqg, float* __restrict__ qg)
{
    int g = blockIdx.x;
    int o = blockIdx.y * 128 + threadIdx.x;
    const float* hr = h + (size_t)(g * 512) * DM;
    float a = bqg[o];
    for (int d = 0; d < DM; d++) a += hr[d] * Wqg[(size_t)d * DM + o];
    qg[g * DM + o] = a * SCALE;
}

// ---------------- global-token full attention (overwrites GPOS rows, fp16 out) ----------------
__global__ void global_attn_kernel(const float* __restrict__ qg, const float* __restrict__ kg,
                                   const float* __restrict__ vg, __half* __restrict__ out)
{
    int g = blockIdx.x, hh = blockIdx.y;
    int hoff = hh * HD;
    int tid = threadIdx.x;
    __shared__ float qs[HD];
    __shared__ float sc[S];
    __shared__ float red[256];
    if (tid < HD) qs[tid] = qg[g * DM + hoff + tid];
    __syncthreads();

    float lmax = -1e30f;
    for (int i = 0; i < 16; i++) {
        int s = i * 256 + tid;
        const float* kr = kg + (size_t)s * DM + hoff;
        float a = 0.f;
#pragma unroll
        for (int d = 0; d < HD; d++) a += qs[d] * kr[d];
        sc[s] = a;
        lmax = fmaxf(lmax, a);
    }
    red[tid] = lmax; __syncthreads();
    for (int o = 128; o > 0; o >>= 1) { if (tid < o) red[tid] = fmaxf(red[tid], red[tid + o]); __syncthreads(); }
    float mx = red[0]; __syncthreads();

    float lsum = 0.f;
    for (int i = 0; i < 16; i++) {
        int s = i * 256 + tid;
        float p = __expf(sc[s] - mx);
        sc[s] = p;
        lsum += p;
    }
    red[tid] = lsum; __syncthreads();
    for (int o = 128; o > 0; o >>= 1) { if (tid < o) red[tid] += red[tid + o]; __syncthreads(); }
    float inv = 1.f / red[0]; __syncthreads();

    int d = tid & 63;
    int part = tid >> 6;
    float a = 0.f;
    for (int s = part * 1024; s < (part + 1) * 1024; s++)
        a += sc[s] * vg[(size_t)s * DM + hoff + d];
    red[tid] = a; __syncthreads();
    if (tid < 64) {
        float r = red[tid] + red[tid + 64] + red[tid + 128] + red[tid + 192];
        out[(size_t)(g * 512) * DM + hoff + d] = __float2half(r * inv);
    }
}

// ---------------- output head ----------------
__global__ void head_kernel(const float* __restrict__ h, const float* __restrict__ Wout,
                            const float* __restrict__ bout, float* __restrict__ out)
{
    int g = blockIdx.x;
    int o = threadIdx.x; // 128
    const float* hr = h + (size_t)(g * 512) * DM;
    float a = bout[o];
    for (int d = 0; d < DM; d++) a += hr[d] * Wout[(size_t)d * OUTD + o];
    out[g * OUTD + o] = a;
}

// ---------------- driver ----------------
extern "C" void kernel_launch(void* const* d_in, const int* in_sizes, int n_in,
                              void* d_out, int out_size)
{
    (void)in_sizes; (void)n_in; (void)out_size;
    const int*   x        = (const int*)  d_in[0];
    const float* word_emb = (const float*)d_in[1];
    const float* pos_emb  = (const float*)d_in[2];
    const float* emb_ln_s = (const float*)d_in[3];
    const float* emb_ln_b = (const float*)d_in[4];
    const float* Wq  = (const float*)d_in[5];   const float* bq  = (const float*)d_in[6];
    const float* Wk  = (const float*)d_in[7];   const float* bk  = (const float*)d_in[8];
    const float* Wv  = (const float*)d_in[9];   const float* bv  = (const float*)d_in[10];
    const float* Wo  = (const float*)d_in[11];  const float* bo  = (const float*)d_in[12];
    const float* Wqg = (const float*)d_in[13];  const float* bqg = (const float*)d_in[14];
    const float* Wkg = (const float*)d_in[15];  const float* bkg = (const float*)d_in[16];
    const float* Wvg = (const float*)d_in[17];  const float* bvg = (const float*)d_in[18];
    const float* ln1s= (const float*)d_in[19];  const float* ln1b= (const float*)d_in[20];
    const float* W1  = (const float*)d_in[21];  const float* b1  = (const float*)d_in[22];
    const float* W2  = (const float*)d_in[23];  const float* b2  = (const float*)d_in[24];
    const float* ln2s= (const float*)d_in[25];  const float* ln2b= (const float*)d_in[26];
    const float* Wout= (const float*)d_in[27];  const float* bout= (const float*)d_in[28];
    float* out = (float*)d_out;

    float *h, *q, *k, *v, *kg, *vg, *y, *qg;
    __half *h16, *attn16, *ffn16;
    cudaGetSymbolAddress((void**)&h,    g_h);
    cudaGetSymbolAddress((void**)&q,    g_q);
    cudaGetSymbolAddress((void**)&k,    g_k);
    cudaGetSymbolAddress((void**)&v,    g_v);
    cudaGetSymbolAddress((void**)&kg,   g_kg);
    cudaGetSymbolAddress((void**)&vg,   g_vg);
    cudaGetSymbolAddress((void**)&y,    g_y);
    cudaGetSymbolAddress((void**)&qg,   g_qg);
    cudaGetSymbolAddress((void**)&h16,    g_h16);
    cudaGetSymbolAddress((void**)&attn16, g_attn16);
    cudaGetSymbolAddress((void**)&ffn16,  g_ffn16);

    __half *hWq, *hWk, *hWv, *hWo, *hWkg, *hWvg, *hW1, *hW2;
    cudaGetSymbolAddress((void**)&hWq,  g_hWq);
    cudaGetSymbolAddress((void**)&hWk,  g_hWk);
    cudaGetSymbolAddress((void**)&hWv,  g_hWv);
    cudaGetSymbolAddress((void**)&hWo,  g_hWo);
    cudaGetSymbolAddress((void**)&hWkg, g_hWkg);
    cudaGetSymbolAddress((void**)&hWvg, g_hWvg);
    cudaGetSymbolAddress((void**)&hW1,  g_hW1);
    cudaGetSymbolAddress((void**)&hW2,  g_hW2);

    cudaFuncSetAttribute(hgemm_kernel, cudaFuncAttributeMaxDynamicSharedMemorySize, TGEMM_SMEM);

    const int nP4 = LNUM * DM * DM / 4;
    const int nF4 = LNUM * DM * FF / 4;
    f2h_kernel<<<2048, 256>>>((const float4*)Wq,  (uint2*)hWq,  nP4);
    f2h_kernel<<<2048, 256>>>((const float4*)Wk,  (uint2*)hWk,  nP4);
    f2h_kernel<<<2048, 256>>>((const float4*)Wv,  (uint2*)hWv,  nP4);
    f2h_kernel<<<2048, 256>>>((const float4*)Wo,  (uint2*)hWo,  nP4);
    f2h_kernel<<<2048, 256>>>((const float4*)Wkg, (uint2*)hWkg, nP4);
    f2h_kernel<<<2048, 256>>>((const float4*)Wvg, (uint2*)hWvg, nP4);
    f2h_kernel<<<2048, 256>>>((const float4*)W1,  (uint2*)hW1,  nF4);
    f2h_kernel<<<2048, 256>>>((const float4*)W2,  (uint2*)hW2,  nF4);

    embed_kernel<<<S, 256>>>(x, word_emb, pos_emb, emb_ln_s, emb_ln_b, h, h16);

    dim3 gridQKV(DM / 128, S / 128, 3);
    dim3 gridKV (DM / 128, S / 128, 2);
    dim3 gridP  (DM / 128, S / 128, 1);
    dim3 gridF1 (FF / 128, S / 128, 1);
    dim3 gridF2 (DM / 128, S / 128, 1);
    dim3 gridAtt(CCH, HNUM);
    dim3 gridQg (NW, DM / 128);
    dim3 gridGA (NW, HNUM);

    for (int l = 0; l < LNUM; l++) {
        size_t wO  = (size_t)l * DM * DM;
        size_t bO  = (size_t)l * DM;
        size_t w1O = (size_t)l * DM * FF;
        size_t b1O = (size_t)l * FF;
        size_t w2O = (size_t)l * FF * DM;

        hgemm_kernel<<<gridQKV, 256, TGEMM_SMEM>>>(h16,
            hWq + wO, hWk + wO, hWv + wO,
            bq + bO, bk + bO, bv + bO,
            q, k, v, S, DM, DM, SCALE, 1.0f, 1.0f, 0, 0);
        local_attn_kernel<<<gridAtt, 256>>>(q, k, v, attn16);

        qg_kernel<<<gridQg, 128>>>(h, Wqg + wO, bqg + bO, qg);
        hgemm_kernel<<<gridKV, 256, TGEMM_SMEM>>>(h16,
            hWkg + wO, hWvg + wO, hWvg + wO,
            bkg + bO, bvg + bO, bvg + bO,
            kg, vg, vg, S, DM, DM, 1.0f, 1.0f, 1.0f, 0, 0);
        global_attn_kernel<<<gridGA, 256>>>(qg, kg, vg, attn16);

        hgemm_kernel<<<gridP, 256, TGEMM_SMEM>>>(attn16,
            hWo + wO, hWo + wO, hWo + wO,
            bo + bO, bo + bO, bo + bO,
            y, y, y, S, DM, DM, 1.0f, 1.0f, 1.0f, 0, 0);
        add_ln_kernel<<<S, 256>>>(h, y, ln1s + bO, ln1b + bO, h, h16);

        hgemm_kernel<<<gridF1, 256, TGEMM_SMEM>>>(h16,
            hW1 + w1O, hW1 + w1O, hW1 + w1O,
            b1 + b1O, b1 + b1O, b1 + b1O,
            ffn16, ffn16, ffn16, S, FF, DM, 1.0f, 1.0f, 1.0f, 1, 1);
        hgemm_kernel<<<gridF2, 256, TGEMM_SMEM>>>(ffn16,
            hW2 + w2O, hW2 + w2O, hW2 + w2O,
            b2 + bO, b2 + bO, b2 + bO,
            y, y, y, S, DM, FF, 1.0f, 1.0f, 1.0f, 0, 0);
        add_ln_kernel<<<S, 256>>>(h, y, ln2s + bO, ln2b + bO, h, h16);
    }

    head_kernel<<<NW, 128>>>(h, Wout, bout, out);
}

// round 9
// speedup vs baseline: 2.6830x; 1.6519x over previous
#include <cuda_runtime.h>
#include <cuda_fp16.h>
#include <math.h>
#include <stdint.h>

// ---------------- problem constants ----------------
#define S     4096
#define DM    768
#define FF    3072
#define HNUM  12
#define HD    64
#define WIN   256
#define CCH   16
#define NW    8
#define LNUM  12
#define OUTD  128
#define SCALE 0.125f

// ---------------- scratch ----------------
__device__ float g_h    [S*DM];
__device__ float g_kg   [S*DM];
__device__ float g_vg   [S*DM];
__device__ float g_y    [S*DM];
__device__ float g_qg   [NW*DM];
__device__ __half g_h16   [S*DM];
__device__ __half g_q16   [S*DM];
__device__ __half g_k16   [S*DM];
__device__ __half g_v16   [S*DM];
__device__ __half g_attn16[S*DM];
__device__ __half g_ffn16 [S*FF];

// fp16 weight copies
__device__ __half g_hWq [LNUM*DM*DM];
__device__ __half g_hWk [LNUM*DM*DM];
__device__ __half g_hWv [LNUM*DM*DM];
__device__ __half g_hWo [LNUM*DM*DM];
__device__ __half g_hWkg[LNUM*DM*DM];
__device__ __half g_hWvg[LNUM*DM*DM];
__device__ __half g_hW1 [LNUM*DM*FF];
__device__ __half g_hW2 [LNUM*FF*DM];

// ---------------- helpers ----------------
__device__ __forceinline__ float gelu_f(float x) {
    float x3 = x * x * x;
    return 0.5f * x * (1.0f + tanhf(0.7978845608028654f * (x + 0.044715f * x3)));
}

__device__ __forceinline__ unsigned pack_h2(float a, float b) {
    __half2 p = __float22half2_rn(make_float2(a, b));
    return *reinterpret_cast<unsigned*>(&p);
}

__device__ __forceinline__ void cp_async16(void* smem_dst, const void* gmem_src) {
    uint32_t dst = (uint32_t)__cvta_generic_to_shared(smem_dst);
    asm volatile("cp.async.ca.shared.global [%0], [%1], 16;" :: "r"(dst), "l"(gmem_src));
}

// ---------------- fp32 -> fp16 conversion ----------------
__global__ void f2h_kernel(const float4* __restrict__ in, uint2* __restrict__ out, int n4)
{
    for (int i = blockIdx.x * blockDim.x + threadIdx.x; i < n4; i += gridDim.x * blockDim.x) {
        float4 v = in[i];
        uint2 o;
        o.x = pack_h2(v.x, v.y);
        o.y = pack_h2(v.z, v.w);
        out[i] = o;
    }
}

// ---------------- embedding + LN ----------------
__global__ void embed_kernel(const int* __restrict__ x, const float* __restrict__ we,
                             const float* __restrict__ pe, const float* __restrict__ ls,
                             const float* __restrict__ lb, float* __restrict__ h,
                             __half* __restrict__ h16)
{
    int s = blockIdx.x;
    int tid = threadIdx.x;
    int r = s & 511, w = s >> 9;
    int id = (r == 0) ? 0 : x[w * 511 + r - 1];
    __shared__ float red[256];
    float vals[3];
    float sum = 0.f;
#pragma unroll
    for (int i = 0; i < 3; i++) {
        int d = tid + i * 256;
        vals[i] = we[(size_t)id * DM + d] + pe[s * DM + d];
        sum += vals[i];
    }
    red[tid] = sum; __syncthreads();
    for (int o = 128; o > 0; o >>= 1) { if (tid < o) red[tid] += red[tid + o]; __syncthreads(); }
    float mean = red[0] / (float)DM;
    __syncthreads();
    float vsum = 0.f;
#pragma unroll
    for (int i = 0; i < 3; i++) { float t = vals[i] - mean; vsum += t * t; }
    red[tid] = vsum; __syncthreads();
    for (int o = 128; o > 0; o >>= 1) { if (tid < o) red[tid] += red[tid + o]; __syncthreads(); }
    float rstd = rsqrtf(red[0] / (float)DM + 1e-5f);
#pragma unroll
    for (int i = 0; i < 3; i++) {
        int d = tid + i * 256;
        float o = (vals[i] - mean) * rstd * ls[d] + lb[d];
        h[s * DM + d] = o;
        h16[s * DM + d] = __float2half(o);
    }
}

// ---------------- residual add + LN ----------------
__global__ void add_ln_kernel(const float* __restrict__ x, const float* __restrict__ y,
                              const float* __restrict__ ls, const float* __restrict__ lb,
                              float* __restrict__ o, __half* __restrict__ o16)
{
    int s = blockIdx.x;
    int tid = threadIdx.x;
    __shared__ float red[256];
    float vals[3];
    float sum = 0.f;
#pragma unroll
    for (int i = 0; i < 3; i++) {
        int d = tid + i * 256;
        vals[i] = x[(size_t)s * DM + d] + y[(size_t)s * DM + d];
        sum += vals[i];
    }
    red[tid] = sum; __syncthreads();
    for (int off = 128; off > 0; off >>= 1) { if (tid < off) red[tid] += red[tid + off]; __syncthreads(); }
    float mean = red[0] / (float)DM;
    __syncthreads();
    float vsum = 0.f;
#pragma unroll
    for (int i = 0; i < 3; i++) { float t = vals[i] - mean; vsum += t * t; }
    red[tid] = vsum; __syncthreads();
    for (int off = 128; off > 0; off >>= 1) { if (tid < off) red[tid] += red[tid + off]; __syncthreads(); }
    float rstd = rsqrtf(red[0] / (float)DM + 1e-5f);
#pragma unroll
    for (int i = 0; i < 3; i++) {
        int d = tid + i * 256;
        float ov = (vals[i] - mean) * rstd * ls[d] + lb[d];
        o[(size_t)s * DM + d] = ov;
        o16[(size_t)s * DM + d] = __float2half(ov);
    }
}

// ---------------- fp16 tensor-core GEMM, cp.async 2-stage, batched over z ----------------
#define AS_H    9216
#define STG_H   17920
#define TGEMM_SMEM (2 * STG_H * 2)

__global__ __launch_bounds__(256)
void hgemm_kernel(const __half* __restrict__ A,
                  const __half* B0, const __half* B1, const __half* B2,
                  const float* bias0, const float* bias1, const float* bias2,
                  void* C0, void* C1, void* C2,
                  int M, int N, int K,
                  float al0, float al1, float al2, int act, int outHalf)
{
    extern __shared__ __half sm[];

    const __half* B = (blockIdx.z == 0) ? B0 : (blockIdx.z == 1) ? B1 : B2;
    const float* bias = (blockIdx.z == 0) ? bias0 : (blockIdx.z == 1) ? bias1 : bias2;
    void* C = (blockIdx.z == 0) ? C0 : (blockIdx.z == 1) ? C1 : C2;
    const float alpha = (blockIdx.z == 0) ? al0 : (blockIdx.z == 1) ? al1 : al2;

    const int tid  = threadIdx.x;
    const int lane = tid & 31;
    const int warp = tid >> 5;
    const int wm = warp >> 2;
    const int wn = warp & 3;

    const int bRow = blockIdx.y * 128;
    const int bCol = blockIdx.x * 128;

    float acc[4][4][4];
#pragma unroll
    for (int i = 0; i < 4; i++)
#pragma unroll
        for (int j = 0; j < 4; j++)
#pragma unroll
            for (int r = 0; r < 4; r++) acc[i][j][r] = 0.f;

    const int nk = K >> 6;

    {
        __half* as = sm;
        __half* bs = sm + AS_H;
#pragma unroll
        for (int p = 0; p < 4; p++) {
            int id = p * 256 + tid;
            int r = id >> 3, c = (id & 7) * 8;
            cp_async16(as + r * 72 + c, A + (size_t)(bRow + r) * K + c);
        }
#pragma unroll
        for (int p = 0; p < 4; p++) {
            int id = p * 256 + tid;
            int r = id >> 4, c = (id & 15) * 8;
            cp_async16(bs + r * 136 + c, B + (size_t)r * N + bCol + c);
        }
        asm volatile("cp.async.commit_group;" ::);
    }

    for (int kt = 0; kt < nk; kt++) {
        asm volatile("cp.async.wait_group 0;" ::);
        __syncthreads();

        if (kt + 1 < nk) {
            const int k0 = (kt + 1) << 6;
            __half* as = sm + ((kt + 1) & 1) * STG_H;
            __half* bs = as + AS_H;
#pragma unroll
            for (int p = 0; p < 4; p++) {
                int id = p * 256 + tid;
                int r = id >> 3, c = (id & 7) * 8;
                cp_async16(as + r * 72 + c, A + (size_t)(bRow + r) * K + k0 + c);
            }
#pragma unroll
            for (int p = 0; p < 4; p++) {
                int id = p * 256 + tid;
                int r = id >> 4, c = (id & 15) * 8;
                cp_async16(bs + r * 136 + c, B + (size_t)(k0 + r) * N + bCol + c);
            }
            asm volatile("cp.async.commit_group;" ::);
        }

        const __half* as = sm + (kt & 1) * STG_H;
        const __half* bs = as + AS_H;
#pragma unroll
        for (int kk = 0; kk < 64; kk += 16) {
            uint32_t af[4][4];
#pragma unroll
            for (int mi = 0; mi < 4; mi++) {
                uint32_t addr = (uint32_t)__cvta_generic_to_shared(
                    as + (wm * 64 + mi * 16 + (lane & 15)) * 72 + kk + (lane >> 4) * 8);
                asm volatile("ldmatrix.sync.aligned.m8n8.x4.shared.b16 {%0,%1,%2,%3}, [%4];"
                             : "=r"(af[mi][0]), "=r"(af[mi][1]), "=r"(af[mi][2]), "=r"(af[mi][3])
                             : "r"(addr));
            }
            uint32_t bfr[4][2];
#pragma unroll
            for (int nb = 0; nb < 2; nb++) {
                uint32_t addr = (uint32_t)__cvta_generic_to_shared(
                    bs + (kk + (lane & 15)) * 136 + wn * 32 + nb * 16 + (lane >> 4) * 8);
                uint32_t r0, r1, r2, r3;
                asm volatile("ldmatrix.sync.aligned.m8n8.x4.trans.shared.b16 {%0,%1,%2,%3}, [%4];"
                             : "=r"(r0), "=r"(r1), "=r"(r2), "=r"(r3)
                             : "r"(addr));
                bfr[nb * 2][0] = r0; bfr[nb * 2][1] = r1;
                bfr[nb * 2 + 1][0] = r2; bfr[nb * 2 + 1][1] = r3;
            }
#pragma unroll
            for (int mi = 0; mi < 4; mi++)
#pragma unroll
                for (int ni = 0; ni < 4; ni++) {
                    asm volatile(
                        "mma.sync.aligned.m16n8k16.row.col.f32.f16.f16.f32 "
                        "{%0,%1,%2,%3}, {%4,%5,%6,%7}, {%8,%9}, {%0,%1,%2,%3};"
                        : "+f"(acc[mi][ni][0]), "+f"(acc[mi][ni][1]),
                          "+f"(acc[mi][ni][2]), "+f"(acc[mi][ni][3])
                        : "r"(af[mi][0]), "r"(af[mi][1]), "r"(af[mi][2]), "r"(af[mi][3]),
                          "r"(bfr[ni][0]), "r"(bfr[ni][1]));
                }
        }
        __syncthreads();
    }

#pragma unroll
    for (int mi = 0; mi < 4; mi++) {
        int row0 = bRow + wm * 64 + mi * 16 + (lane >> 2);
#pragma unroll
        for (int ni = 0; ni < 4; ni++) {
            int col = bCol + wn * 32 + ni * 8 + (lane & 3) * 2;
            float b0 = bias[col], b1 = bias[col + 1];
            float v0 = (acc[mi][ni][0] + b0) * alpha;
            float v1 = (acc[mi][ni][1] + b1) * alpha;
            float v2 = (acc[mi][ni][2] + b0) * alpha;
            float v3 = (acc[mi][ni][3] + b1) * alpha;
            if (act == 1) { v0 = gelu_f(v0); v1 = gelu_f(v1); v2 = gelu_f(v2); v3 = gelu_f(v3); }
            if (outHalf) {
                __half* Ch = (__half*)C;
                *(uint32_t*)&Ch[(size_t)row0 * N + col]       = pack_h2(v0, v1);
                *(uint32_t*)&Ch[(size_t)(row0 + 8) * N + col] = pack_h2(v2, v3);
            } else {
                float* Cf = (float*)C;
                *(float2*)&Cf[(size_t)row0 * N + col]       = make_float2(v0, v1);
                *(float2*)&Cf[(size_t)(row0 + 8) * N + col] = make_float2(v2, v3);
            }
        }
    }
}

// ---------------- local attention via tensor cores (flash-style) ----------------
__global__ __launch_bounds__(256, 1)
void local_attn_mma(const __half* __restrict__ q, const __half* __restrict__ k,
                    const __half* __restrict__ v, __half* __restrict__ out)
{
    const int c = blockIdx.x, hh = blockIdx.y;
    const int tid = threadIdx.x;
    const int lane = tid & 31, warp = tid >> 5;
    const int hoff = hh * HD;

    __shared__ __align__(16) __half Qs[256][72];
    __shared__ __align__(16) __half Ks[16][72];
    __shared__ __align__(16) __half Vs[16][72];

    // stage Q[256][64]
    for (int i = tid; i < 2048; i += 256) {
        int row = i >> 3, ch = (i & 7) * 8;
        *(uint4*)&Qs[row][ch] = *(const uint4*)&q[(size_t)(c * WIN + row) * DM + hoff + ch];
    }
    __syncthreads();

    uint32_t qf[2][4][4];
#pragma unroll
    for (int mi = 0; mi < 2; mi++)
#pragma unroll
        for (int kt = 0; kt < 4; kt++) {
            uint32_t addr = (uint32_t)__cvta_generic_to_shared(
                &Qs[warp * 32 + mi * 16 + (lane & 15)][kt * 16 + (lane >> 4) * 8]);
            asm volatile("ldmatrix.sync.aligned.m8n8.x4.shared.b16 {%0,%1,%2,%3}, [%4];"
                         : "=r"(qf[mi][kt][0]), "=r"(qf[mi][kt][1]),
                           "=r"(qf[mi][kt][2]), "=r"(qf[mi][kt][3])
                         : "r"(addr));
        }

    float mrow[2][2], lrow[2][2];
    float acc[2][8][4];
#pragma unroll
    for (int mi = 0; mi < 2; mi++)
#pragma unroll
        for (int h = 0; h < 2; h++) { mrow[mi][h] = -1e30f; lrow[mi][h] = 0.f; }
#pragma unroll
    for (int mi = 0; mi < 2; mi++)
#pragma unroll
        for (int n8 = 0; n8 < 8; n8++)
#pragma unroll
            for (int r = 0; r < 4; r++) acc[mi][n8][r] = 0.f;

    for (int t0 = 0; t0 <= 48; t0++) {
        {
            int hs = tid >> 7;
            int idx = tid & 127;
            int j = idx >> 3, ch = (idx & 7) * 8;
            int kpos; bool valid;
            if (t0 == 0) { kpos = j * 512; valid = (j < 8); }
            else {
                int jg = (t0 - 1) * 16 + j;
                kpos = c * WIN + jg - WIN;
                valid = (kpos >= 0 && kpos < S);
            }
            uint4 val = make_uint4(0, 0, 0, 0);
            if (valid) {
                const __half* src = hs ? v : k;
                val = *(const uint4*)&src[(size_t)kpos * DM + hoff + ch];
            }
            if (hs) *(uint4*)&Vs[j][ch] = val;
            else    *(uint4*)&Ks[j][ch] = val;
        }
        __syncthreads();

        // K b-fragments for S = Q K^T (k dim = head dim, runs along columns of Ks)
        uint32_t kf[4][4];
#pragma unroll
        for (int kt = 0; kt < 4; kt++) {
            uint32_t addr = (uint32_t)__cvta_generic_to_shared(
                &Ks[lane & 15][kt * 16 + (lane >> 4) * 8]);
            asm volatile("ldmatrix.sync.aligned.m8n8.x4.shared.b16 {%0,%1,%2,%3}, [%4];"
                         : "=r"(kf[kt][0]), "=r"(kf[kt][1]), "=r"(kf[kt][2]), "=r"(kf[kt][3])
                         : "r"(addr));
        }

        float sc[2][2][4];
#pragma unroll
        for (int mi = 0; mi < 2; mi++)
#pragma unroll
            for (int ni = 0; ni < 2; ni++)
#pragma unroll
                for (int r = 0; r < 4; r++) sc[mi][ni][r] = 0.f;
#pragma unroll
        for (int mi = 0; mi < 2; mi++)
#pragma unroll
            for (int kt = 0; kt < 4; kt++) {
                asm volatile(
                    "mma.sync.aligned.m16n8k16.row.col.f32.f16.f16.f32 "
                    "{%0,%1,%2,%3}, {%4,%5,%6,%7}, {%8,%9}, {%0,%1,%2,%3};"
                    : "+f"(sc[mi][0][0]), "+f"(sc[mi][0][1]), "+f"(sc[mi][0][2]), "+f"(sc[mi][0][3])
                    : "r"(qf[mi][kt][0]), "r"(qf[mi][kt][1]), "r"(qf[mi][kt][2]), "r"(qf[mi][kt][3]),
                      "r"(kf[kt][0]), "r"(kf[kt][2]));
                asm volatile(
                    "mma.sync.aligned.m16n8k16.row.col.f32.f16.f16.f32 "
                    "{%0,%1,%2,%3}, {%4,%5,%6,%7}, {%8,%9}, {%0,%1,%2,%3};"
                    : "+f"(sc[mi][1][0]), "+f"(sc[mi][1][1]), "+f"(sc[mi][1][2]), "+f"(sc[mi][1][3])
                    : "r"(qf[mi][kt][0]), "r"(qf[mi][kt][1]), "r"(qf[mi][kt][2]), "r"(qf[mi][kt][3]),
                      "r"(kf[kt][1]), "r"(kf[kt][3]));
            }

        // mask + online softmax + P a-frags
        uint32_t pa[2][4];
#pragma unroll
        for (int mi = 0; mi < 2; mi++) {
#pragma unroll
            for (int h = 0; h < 2; h++) {
                int qi = warp * 32 + mi * 16 + (lane >> 2) + h * 8;
                float s0 = sc[mi][0][2 * h], s1 = sc[mi][0][2 * h + 1];
                float s2 = sc[mi][1][2 * h], s3 = sc[mi][1][2 * h + 1];
                int j0 = (lane & 3) * 2;
#pragma unroll
                for (int e = 0; e < 4; e++) {
                    int jj = (e >> 1) * 8 + j0 + (e & 1);
                    bool valid;
                    if (t0 == 0) valid = (jj < 8);
                    else {
                        int jg = (t0 - 1) * 16 + jj;
                        int kp = c * WIN + jg - WIN;
                        valid = (jg >= qi) && (jg <= qi + 2 * WIN) && (kp >= 0) && (kp < S);
                    }
                    float* sp = (e == 0) ? &s0 : (e == 1) ? &s1 : (e == 2) ? &s2 : &s3;
                    if (!valid) *sp = -1e30f;
                }
                float rmax = fmaxf(fmaxf(s0, s1), fmaxf(s2, s3));
                rmax = fmaxf(rmax, __shfl_xor_sync(0xffffffffu, rmax, 1));
                rmax = fmaxf(rmax, __shfl_xor_sync(0xffffffffu, rmax, 2));
                float mnew = fmaxf(mrow[mi][h], rmax);
                float scale = __expf(mrow[mi][h] - mnew);
                float p0 = __expf(s0 - mnew), p1 = __expf(s1 - mnew);
                float p2 = __expf(s2 - mnew), p3 = __expf(s3 - mnew);
                float ls = p0 + p1 + p2 + p3;
                ls += __shfl_xor_sync(0xffffffffu, ls, 1);
                ls += __shfl_xor_sync(0xffffffffu, ls, 2);
                lrow[mi][h] = lrow[mi][h] * scale + ls;
                mrow[mi][h] = mnew;
#pragma unroll
                for (int n8 = 0; n8 < 8; n8++) {
                    acc[mi][n8][2 * h]     *= scale;
                    acc[mi][n8][2 * h + 1] *= scale;
                }
                pa[mi][h]     = pack_h2(p0, p1);
                pa[mi][h + 2] = pack_h2(p2, p3);
            }
        }

        // V b-frags + AV MMAs.
        // Vs rows = keys = MMA k-dim → sub-matrices: m0(k0-7,n0-7) m1(k8-15,n0-7)
        // m2(k0-7,n8-15) m3(k8-15,n8-15). Pairs: {r0,r1} low-n, {r2,r3} high-n.
#pragma unroll
        for (int nb = 0; nb < 4; nb++) {
            uint32_t addr = (uint32_t)__cvta_generic_to_shared(
                &Vs[lane & 15][nb * 16 + (lane >> 4) * 8]);
            uint32_t r0, r1, r2, r3;
            asm volatile("ldmatrix.sync.aligned.m8n8.x4.trans.shared.b16 {%0,%1,%2,%3}, [%4];"
                         : "=r"(r0), "=r"(r1), "=r"(r2), "=r"(r3)
                         : "r"(addr));
#pragma unroll
            for (int mi = 0; mi < 2; mi++) {
                asm volatile(
                    "mma.sync.aligned.m16n8k16.row.col.f32.f16.f16.f32 "
                    "{%0,%1,%2,%3}, {%4,%5,%6,%7}, {%8,%9}, {%0,%1,%2,%3};"
                    : "+f"(acc[mi][nb*2][0]), "+f"(acc[mi][nb*2][1]),
                      "+f"(acc[mi][nb*2][2]), "+f"(acc[mi][nb*2][3])
                    : "r"(pa[mi][0]), "r"(pa[mi][1]), "r"(pa[mi][2]), "r"(pa[mi][3]),
                      "r"(r0), "r"(r1));
                asm volatile(
                    "mma.sync.aligned.m16n8k16.row.col.f32.f16.f16.f32 "
                    "{%0,%1,%2,%3}, {%4,%5,%6,%7}, {%8,%9}, {%0,%1,%2,%3};"
                    : "+f"(acc[mi][nb*2+1][0]), "+f"(acc[mi][nb*2+1][1]),
                      "+f"(acc[mi][nb*2+1][2]), "+f"(acc[mi][nb*2+1][3])
                    : "r"(pa[mi][0]), "r"(pa[mi][1]), "r"(pa[mi][2]), "r"(pa[mi][3]),
                      "r"(r2), "r"(r3));
            }
        }
        __syncthreads();
    }

    // epilogue
#pragma unroll
    for (int mi = 0; mi < 2; mi++)
#pragma unroll
        for (int h = 0; h < 2; h++) {
            float inv = 1.f / lrow[mi][h];
            int row = warp * 32 + mi * 16 + (lane >> 2) + h * 8;
            size_t base = (size_t)(c * WIN + row) * DM + hoff;
#pragma unroll
            for (int n8 = 0; n8 < 8; n8++) {
                int dim = n8 * 8 + (lane & 3) * 2;
                *(uint32_t*)&out[base + dim] =
                    pack_h2(acc[mi][n8][2 * h] * inv, acc[mi][n8][2 * h + 1] * inv);
            }
        }
}

// ---------------- qg projection ----------------
__global__ void qg_kernel(const float* __restrict__ h, const float* __restrict__ Wqg,
                          const float* __restrict__ bqg, float* __restrict__ qg)
{
    int g = blockIdx.x;
    int o = blockIdx.y * 128 + threadIdx.x;
    const float* hr = h + (size_t)(g * 512) * DM;
    float a = bqg[o];
    for (int d = 0; d < DM; d++) a += hr[d] * Wqg[(size_t)d * DM + o];
    qg[g * DM + o] = a * SCALE;
}

// ---------------- global-token full attention ----------------
__global__ void global_attn_kernel(const float* __restrict__ qg, const float* __restrict__ kg,
                                   const float* __restrict__ vg, __half* __restrict__ out)
{
    int g = blockIdx.x, hh = blockIdx.y;
    int hoff = hh * HD;
    int tid = threadIdx.x;
    __shared__ float qs[HD];
    __shared__ float sc[S];
    __shared__ float red[256];
    if (tid < HD) qs[tid] = qg[g * DM + hoff + tid];
    __syncthreads();

    float lmax = -1e30f;
    for (int i = 0; i < 16; i++) {
        int s = i * 256 + tid;
        const float* kr = kg + (size_t)s * DM + hoff;
        float a = 0.f;
#pragma unroll
        for (int d = 0; d < HD; d++) a += qs[d] * kr[d];
        sc[s] = a;
        lmax = fmaxf(lmax, a);
    }
    red[tid] = lmax; __syncthreads();
    for (int o = 128; o > 0; o >>= 1) { if (tid < o) red[tid] = fmaxf(red[tid], red[tid + o]); __syncthreads(); }
    float mx = red[0]; __syncthreads();

    float lsum = 0.f;
    for (int i = 0; i < 16; i++) {
        int s = i * 256 + tid;
        float p = __expf(sc[s] - mx);
        sc[s] = p;
        lsum += p;
    }
    red[tid] = lsum; __syncthreads();
    for (int o = 128; o > 0; o >>= 1) { if (tid < o) red[tid] += red[tid + o]; __syncthreads(); }
    float inv = 1.f / red[0]; __syncthreads();

    int d = tid & 63;
    int part = tid >> 6;
    float a = 0.f;
    for (int s = part * 1024; s < (part + 1) * 1024; s++)
        a += sc[s] * vg[(size_t)s * DM + hoff + d];
    red[tid] = a; __syncthreads();
    if (tid < 64) {
        float r = red[tid] + red[tid + 64] + red[tid + 128] + red[tid + 192];
        out[(size_t)(g * 512) * DM + hoff + d] = __float2half(r * inv);
    }
}

// ---------------- output head ----------------
__global__ void head_kernel(const float* __restrict__ h, const float* __restrict__ Wout,
                            const float* __restrict__ bout, float* __restrict__ out)
{
    int g = blockIdx.x;
    int o = threadIdx.x;
    const float* hr = h + (size_t)(g * 512) * DM;
    float a = bout[o];
    for (int d = 0; d < DM; d++) a += hr[d] * Wout[(size_t)d * OUTD + o];
    out[g * OUTD + o] = a;
}

// ---------------- driver ----------------
extern "C" void kernel_launch(void* const* d_in, const int* in_sizes, int n_in,
                              void* d_out, int out_size)
{
    (void)in_sizes; (void)n_in; (void)out_size;
    const int*   x        = (const int*)  d_in[0];
    const float* word_emb = (const float*)d_in[1];
    const float* pos_emb  = (const float*)d_in[2];
    const float* emb_ln_s = (const float*)d_in[3];
    const float* emb_ln_b = (const float*)d_in[4];
    const float* Wq  = (const float*)d_in[5];   const float* bq  = (const float*)d_in[6];
    const float* Wk  = (const float*)d_in[7];   const float* bk  = (const float*)d_in[8];
    const float* Wv  = (const float*)d_in[9];   const float* bv  = (const float*)d_in[10];
    const float* Wo  = (const float*)d_in[11];  const float* bo  = (const float*)d_in[12];
    const float* Wqg = (const float*)d_in[13];  const float* bqg = (const float*)d_in[14];
    const float* Wkg = (const float*)d_in[15];  const float* bkg = (const float*)d_in[16];
    const float* Wvg = (const float*)d_in[17];  const float* bvg = (const float*)d_in[18];
    const float* ln1s= (const float*)d_in[19];  const float* ln1b= (const float*)d_in[20];
    const float* W1  = (const float*)d_in[21];  const float* b1  = (const float*)d_in[22];
    const float* W2  = (const float*)d_in[23];  const float* b2  = (const float*)d_in[24];
    const float* ln2s= (const float*)d_in[25];  const float* ln2b= (const float*)d_in[26];
    const float* Wout= (const float*)d_in[27];  const float* bout= (const float*)d_in[28];
    float* out = (float*)d_out;

    float *h, *kg, *vg, *y, *qg;
    __half *h16, *q16, *k16, *v16, *attn16, *ffn16;
    cudaGetSymbolAddress((void**)&h,    g_h);
    cudaGetSymbolAddress((void**)&kg,   g_kg);
    cudaGetSymbolAddress((void**)&vg,   g_vg);
    cudaGetSymbolAddress((void**)&y,    g_y);
    cudaGetSymbolAddress((void**)&qg,   g_qg);
    cudaGetSymbolAddress((void**)&h16,    g_h16);
    cudaGetSymbolAddress((void**)&q16,    g_q16);
    cudaGetSymbolAddress((void**)&k16,    g_k16);
    cudaGetSymbolAddress((void**)&v16,    g_v16);
    cudaGetSymbolAddress((void**)&attn16, g_attn16);
    cudaGetSymbolAddress((void**)&ffn16,  g_ffn16);

    __half *hWq, *hWk, *hWv, *hWo, *hWkg, *hWvg, *hW1, *hW2;
    cudaGetSymbolAddress((void**)&hWq,  g_hWq);
    cudaGetSymbolAddress((void**)&hWk,  g_hWk);
    cudaGetSymbolAddress((void**)&hWv,  g_hWv);
    cudaGetSymbolAddress((void**)&hWo,  g_hWo);
    cudaGetSymbolAddress((void**)&hWkg, g_hWkg);
    cudaGetSymbolAddress((void**)&hWvg, g_hWvg);
    cudaGetSymbolAddress((void**)&hW1,  g_hW1);
    cudaGetSymbolAddress((void**)&hW2,  g_hW2);

    cudaFuncSetAttribute(hgemm_kernel, cudaFuncAttributeMaxDynamicSharedMemorySize, TGEMM_SMEM);

    const int nP4 = LNUM * DM * DM / 4;
    const int nF4 = LNUM * DM * FF / 4;
    f2h_kernel<<<2048, 256>>>((const float4*)Wq,  (uint2*)hWq,  nP4);
    f2h_kernel<<<2048, 256>>>((const float4*)Wk,  (uint2*)hWk,  nP4);
    f2h_kernel<<<2048, 256>>>((const float4*)Wv,  (uint2*)hWv,  nP4);
    f2h_kernel<<<2048, 256>>>((const float4*)Wo,  (uint2*)hWo,  nP4);
    f2h_kernel<<<2048, 256>>>((const float4*)Wkg, (uint2*)hWkg, nP4);
    f2h_kernel<<<2048, 256>>>((const float4*)Wvg, (uint2*)hWvg, nP4);
    f2h_kernel<<<2048, 256>>>((const float4*)W1,  (uint2*)hW1,  nF4);
    f2h_kernel<<<2048, 256>>>((const float4*)W2,  (uint2*)hW2,  nF4);

    embed_kernel<<<S, 256>>>(x, word_emb, pos_emb, emb_ln_s, emb_ln_b, h, h16);

    dim3 gridQKV(DM / 128, S / 128, 3);
    dim3 gridKV (DM / 128, S / 128, 2);
    dim3 gridP  (DM / 128, S / 128, 1);
    dim3 gridF1 (FF / 128, S / 128, 1);
    dim3 gridF2 (DM / 128, S / 128, 1);
    dim3 gridAtt(CCH, HNUM);
    dim3 gridQg (NW, DM / 128);
    dim3 gridGA (NW, HNUM);

    for (int l = 0; l < LNUM; l++) {
        size_t wO  = (size_t)l * DM * DM;
        size_t bO  = (size_t)l * DM;
        size_t w1O = (size_t)l * DM * FF;
        size_t b1O = (size_t)l * FF;
        size_t w2O = (size_t)l * FF * DM;

        hgemm_kernel<<<gridQKV, 256, TGEMM_SMEM>>>(h16,
            hWq + wO, hWk + wO, hWv + wO,
            bq + bO, bk + bO, bv + bO,
            q16, k16, v16, S, DM, DM, SCALE, 1.0f, 1.0f, 0, 1);
        local_attn_mma<<<gridAtt, 256>>>(q16, k16, v16, attn16);

        qg_kernel<<<gridQg, 128>>>(h, Wqg + wO, bqg + bO, qg);
        hgemm_kernel<<<gridKV, 256, TGEMM_SMEM>>>(h16,
            hWkg + wO, hWvg + wO, hWvg + wO,
            bkg + bO, bvg + bO, bvg + bO,
            kg, vg, vg, S, DM, DM, 1.0f, 1.0f, 1.0f, 0, 0);
        global_attn_kernel<<<gridGA, 256>>>(qg, kg, vg, attn16);

        hgemm_kernel<<<gridP, 256, TGEMM_SMEM>>>(attn16,
            hWo + wO, hWo + wO, hWo + wO,
            bo + bO, bo + bO, bo + bO,
            y, y, y, S, DM, DM, 1.0f, 1.0f, 1.0f, 0, 0);
        add_ln_kernel<<<S, 256>>>(h, y, ln1s + bO, ln1b + bO, h, h16);

        hgemm_kernel<<<gridF1, 256, TGEMM_SMEM>>>(h16,
            hW1 + w1O, hW1 + w1O, hW1 + w1O,
            b1 + b1O, b1 + b1O, b1 + b1O,
            ffn16, ffn16, ffn16, S, FF, DM, 1.0f, 1.0f, 1.0f, 1, 1);
        hgemm_kernel<<<gridF2, 256, TGEMM_SMEM>>>(ffn16,
            hW2 + w2O, hW2 + w2O, hW2 + w2O,
            b2 + bO, b2 + bO, b2 + bO,
            y, y, y, S, DM, FF, 1.0f, 1.0f, 1.0f, 0, 0);
        add_ln_kernel<<<S, 256>>>(h, y, ln2s + bO, ln2b + bO, h, h16);
    }

    head_kernel<<<NW, 128>>>(h, Wout, bout, out);
}

// round 10
// speedup vs baseline: 2.6909x; 1.0029x over previous
#include <cuda_runtime.h>
#include <cuda_fp16.h>
#include <math.h>
#include <stdint.h>

// ---------------- problem constants ----------------
#define S     4096
#define DM    768
#define FF    3072
#define HNUM  12
#define HD    64
#define WIN   256
#define CCH   16
#define NW    8
#define LNUM  12
#define OUTD  128
#define SCALE 0.125f

// ---------------- scratch ----------------
__device__ float g_h    [S*DM];
__device__ float g_kg   [S*DM];
__device__ float g_vg   [S*DM];
__device__ float g_y    [S*DM];
__device__ float g_qg   [NW*DM];
__device__ __half g_h16   [S*DM];
__device__ __half g_q16   [S*DM];
__device__ __half g_k16   [S*DM];
__device__ __half g_v16   [S*DM];
__device__ __half g_attn16[S*DM];
__device__ __half g_ffn16 [S*FF];

// fp16 weight copies
__device__ __half g_hWq [LNUM*DM*DM];
__device__ __half g_hWk [LNUM*DM*DM];
__device__ __half g_hWv [LNUM*DM*DM];
__device__ __half g_hWo [LNUM*DM*DM];
__device__ __half g_hWkg[LNUM*DM*DM];
__device__ __half g_hWvg[LNUM*DM*DM];
__device__ __half g_hW1 [LNUM*DM*FF];
__device__ __half g_hW2 [LNUM*FF*DM];

// ---------------- helpers ----------------
__device__ __forceinline__ float gelu_f(float x) {
    float x3 = x * x * x;
    return 0.5f * x * (1.0f + tanhf(0.7978845608028654f * (x + 0.044715f * x3)));
}

__device__ __forceinline__ unsigned pack_h2(float a, float b) {
    __half2 p = __float22half2_rn(make_float2(a, b));
    return *reinterpret_cast<unsigned*>(&p);
}

__device__ __forceinline__ void cp_async16(void* smem_dst, const void* gmem_src) {
    uint32_t dst = (uint32_t)__cvta_generic_to_shared(smem_dst);
    asm volatile("cp.async.ca.shared.global [%0], [%1], 16;" :: "r"(dst), "l"(gmem_src));
}

// ---------------- fp32 -> fp16 conversion ----------------
__global__ void f2h_kernel(const float4* __restrict__ in, uint2* __restrict__ out, int n4)
{
    for (int i = blockIdx.x * blockDim.x + threadIdx.x; i < n4; i += gridDim.x * blockDim.x) {
        float4 v = in[i];
        uint2 o;
        o.x = pack_h2(v.x, v.y);
        o.y = pack_h2(v.z, v.w);
        out[i] = o;
    }
}

// ---------------- embedding + LN ----------------
__global__ void embed_kernel(const int* __restrict__ x, const float* __restrict__ we,
                             const float* __restrict__ pe, const float* __restrict__ ls,
                             const float* __restrict__ lb, float* __restrict__ h,
                             __half* __restrict__ h16)
{
    int s = blockIdx.x;
    int tid = threadIdx.x;
    int r = s & 511, w = s >> 9;
    int id = (r == 0) ? 0 : x[w * 511 + r - 1];
    __shared__ float red[256];
    float vals[3];
    float sum = 0.f;
#pragma unroll
    for (int i = 0; i < 3; i++) {
        int d = tid + i * 256;
        vals[i] = we[(size_t)id * DM + d] + pe[s * DM + d];
        sum += vals[i];
    }
    red[tid] = sum; __syncthreads();
    for (int o = 128; o > 0; o >>= 1) { if (tid < o) red[tid] += red[tid + o]; __syncthreads(); }
    float mean = red[0] / (float)DM;
    __syncthreads();
    float vsum = 0.f;
#pragma unroll
    for (int i = 0; i < 3; i++) { float t = vals[i] - mean; vsum += t * t; }
    red[tid] = vsum; __syncthreads();
    for (int o = 128; o > 0; o >>= 1) { if (tid < o) red[tid] += red[tid + o]; __syncthreads(); }
    float rstd = rsqrtf(red[0] / (float)DM + 1e-5f);
#pragma unroll
    for (int i = 0; i < 3; i++) {
        int d = tid + i * 256;
        float o = (vals[i] - mean) * rstd * ls[d] + lb[d];
        h[s * DM + d] = o;
        h16[s * DM + d] = __float2half(o);
    }
}

// ---------------- residual add + LN ----------------
__global__ void add_ln_kernel(const float* __restrict__ x, const float* __restrict__ y,
                              const float* __restrict__ ls, const float* __restrict__ lb,
                              float* __restrict__ o, __half* __restrict__ o16)
{
    int s = blockIdx.x;
    int tid = threadIdx.x;
    __shared__ float red[256];
    float vals[3];
    float sum = 0.f;
#pragma unroll
    for (int i = 0; i < 3; i++) {
        int d = tid + i * 256;
        vals[i] = x[(size_t)s * DM + d] + y[(size_t)s * DM + d];
        sum += vals[i];
    }
    red[tid] = sum; __syncthreads();
    for (int off = 128; off > 0; off >>= 1) { if (tid < off) red[tid] += red[tid + off]; __syncthreads(); }
    float mean = red[0] / (float)DM;
    __syncthreads();
    float vsum = 0.f;
#pragma unroll
    for (int i = 0; i < 3; i++) { float t = vals[i] - mean; vsum += t * t; }
    red[tid] = vsum; __syncthreads();
    for (int off = 128; off > 0; off >>= 1) { if (tid < off) red[tid] += red[tid + off]; __syncthreads(); }
    float rstd = rsqrtf(red[0] / (float)DM + 1e-5f);
#pragma unroll
    for (int i = 0; i < 3; i++) {
        int d = tid + i * 256;
        float ov = (vals[i] - mean) * rstd * ls[d] + lb[d];
        o[(size_t)s * DM + d] = ov;
        o16[(size_t)s * DM + d] = __float2half(ov);
    }
}

// ---------------- fp16 tensor-core GEMM, cp.async 2-stage, batched over z ----------------
#define AS_H    9216
#define STG_H   17920
#define TGEMM_SMEM (2 * STG_H * 2)

__global__ __launch_bounds__(256, 2)
void hgemm_kernel(const __half* __restrict__ A,
                  const __half* B0, const __half* B1, const __half* B2,
                  const float* bias0, const float* bias1, const float* bias2,
                  void* C0, void* C1, void* C2,
                  int M, int N, int K,
                  float al0, float al1, float al2, int act, int outHalf)
{
    extern __shared__ __half sm[];

    const __half* B = (blockIdx.z == 0) ? B0 : (blockIdx.z == 1) ? B1 : B2;
    const float* bias = (blockIdx.z == 0) ? bias0 : (blockIdx.z == 1) ? bias1 : bias2;
    void* C = (blockIdx.z == 0) ? C0 : (blockIdx.z == 1) ? C1 : C2;
    const float alpha = (blockIdx.z == 0) ? al0 : (blockIdx.z == 1) ? al1 : al2;

    const int tid  = threadIdx.x;
    const int lane = tid & 31;
    const int warp = tid >> 5;
    const int wm = warp >> 2;
    const int wn = warp & 3;

    const int bRow = blockIdx.y * 128;
    const int bCol = blockIdx.x * 128;

    float acc[4][4][4];
#pragma unroll
    for (int i = 0; i < 4; i++)
#pragma unroll
        for (int j = 0; j < 4; j++)
#pragma unroll
            for (int r = 0; r < 4; r++) acc[i][j][r] = 0.f;

    const int nk = K >> 6;

    {
        __half* as = sm;
        __half* bs = sm + AS_H;
#pragma unroll
        for (int p = 0; p < 4; p++) {
            int id = p * 256 + tid;
            int r = id >> 3, c = (id & 7) * 8;
            cp_async16(as + r * 72 + c, A + (size_t)(bRow + r) * K + c);
        }
#pragma unroll
        for (int p = 0; p < 4; p++) {
            int id = p * 256 + tid;
            int r = id >> 4, c = (id & 15) * 8;
            cp_async16(bs + r * 136 + c, B + (size_t)r * N + bCol + c);
        }
        asm volatile("cp.async.commit_group;" ::);
    }

    for (int kt = 0; kt < nk; kt++) {
        asm volatile("cp.async.wait_group 0;" ::);
        __syncthreads();

        if (kt + 1 < nk) {
            const int k0 = (kt + 1) << 6;
            __half* as = sm + ((kt + 1) & 1) * STG_H;
            __half* bs = as + AS_H;
#pragma unroll
            for (int p = 0; p < 4; p++) {
                int id = p * 256 + tid;
                int r = id >> 3, c = (id & 7) * 8;
                cp_async16(as + r * 72 + c, A + (size_t)(bRow + r) * K + k0 + c);
            }
#pragma unroll
            for (int p = 0; p < 4; p++) {
                int id = p * 256 + tid;
                int r = id >> 4, c = (id & 15) * 8;
                cp_async16(bs + r * 136 + c, B + (size_t)(k0 + r) * N + bCol + c);
            }
            asm volatile("cp.async.commit_group;" ::);
        }

        const __half* as = sm + (kt & 1) * STG_H;
        const __half* bs = as + AS_H;
#pragma unroll
        for (int kk = 0; kk < 64; kk += 16) {
            uint32_t af[4][4];
#pragma unroll
            for (int mi = 0; mi < 4; mi++) {
                uint32_t addr = (uint32_t)__cvta_generic_to_shared(
                    as + (wm * 64 + mi * 16 + (lane & 15)) * 72 + kk + (lane >> 4) * 8);
                asm volatile("ldmatrix.sync.aligned.m8n8.x4.shared.b16 {%0,%1,%2,%3}, [%4];"
                             : "=r"(af[mi][0]), "=r"(af[mi][1]), "=r"(af[mi][2]), "=r"(af[mi][3])
                             : "r"(addr));
            }
            uint32_t bfr[4][2];
#pragma unroll
            for (int nb = 0; nb < 2; nb++) {
                uint32_t addr = (uint32_t)__cvta_generic_to_shared(
                    bs + (kk + (lane & 15)) * 136 + wn * 32 + nb * 16 + (lane >> 4) * 8);
                uint32_t r0, r1, r2, r3;
                asm volatile("ldmatrix.sync.aligned.m8n8.x4.trans.shared.b16 {%0,%1,%2,%3}, [%4];"
                             : "=r"(r0), "=r"(r1), "=r"(r2), "=r"(r3)
                             : "r"(addr));
                bfr[nb * 2][0] = r0; bfr[nb * 2][1] = r1;
                bfr[nb * 2 + 1][0] = r2; bfr[nb * 2 + 1][1] = r3;
            }
#pragma unroll
            for (int mi = 0; mi < 4; mi++)
#pragma unroll
                for (int ni = 0; ni < 4; ni++) {
                    asm volatile(
                        "mma.sync.aligned.m16n8k16.row.col.f32.f16.f16.f32 "
                        "{%0,%1,%2,%3}, {%4,%5,%6,%7}, {%8,%9}, {%0,%1,%2,%3};"
                        : "+f"(acc[mi][ni][0]), "+f"(acc[mi][ni][1]),
                          "+f"(acc[mi][ni][2]), "+f"(acc[mi][ni][3])
                        : "r"(af[mi][0]), "r"(af[mi][1]), "r"(af[mi][2]), "r"(af[mi][3]),
                          "r"(bfr[ni][0]), "r"(bfr[ni][1]));
                }
        }
        __syncthreads();
    }

#pragma unroll
    for (int mi = 0; mi < 4; mi++) {
        int row0 = bRow + wm * 64 + mi * 16 + (lane >> 2);
#pragma unroll
        for (int ni = 0; ni < 4; ni++) {
            int col = bCol + wn * 32 + ni * 8 + (lane & 3) * 2;
            float b0 = bias[col], b1 = bias[col + 1];
            float v0 = (acc[mi][ni][0] + b0) * alpha;
            float v1 = (acc[mi][ni][1] + b1) * alpha;
            float v2 = (acc[mi][ni][2] + b0) * alpha;
            float v3 = (acc[mi][ni][3] + b1) * alpha;
            if (act == 1) { v0 = gelu_f(v0); v1 = gelu_f(v1); v2 = gelu_f(v2); v3 = gelu_f(v3); }
            if (outHalf) {
                __half* Ch = (__half*)C;
                *(uint32_t*)&Ch[(size_t)row0 * N + col]       = pack_h2(v0, v1);
                *(uint32_t*)&Ch[(size_t)(row0 + 8) * N + col] = pack_h2(v2, v3);
            } else {
                float* Cf = (float*)C;
                *(float2*)&Cf[(size_t)row0 * N + col]       = make_float2(v0, v1);
                *(float2*)&Cf[(size_t)(row0 + 8) * N + col] = make_float2(v2, v3);
            }
        }
    }
}

// ---------------- local attention via tensor cores (flash-style) ----------------
__global__ __launch_bounds__(256, 1)
void local_attn_mma(const __half* __restrict__ q, const __half* __restrict__ k,
                    const __half* __restrict__ v, __half* __restrict__ out)
{
    const int c = blockIdx.x, hh = blockIdx.y;
    const int tid = threadIdx.x;
    const int lane = tid & 31, warp = tid >> 5;
    const int hoff = hh * HD;

    __shared__ __align__(16) __half Qs[256][72];
    __shared__ __align__(16) __half Ks[16][72];
    __shared__ __align__(16) __half Vs[16][72];

    for (int i = tid; i < 2048; i += 256) {
        int row = i >> 3, ch = (i & 7) * 8;
        *(uint4*)&Qs[row][ch] = *(const uint4*)&q[(size_t)(c * WIN + row) * DM + hoff + ch];
    }
    __syncthreads();

    uint32_t qf[2][4][4];
#pragma unroll
    for (int mi = 0; mi < 2; mi++)
#pragma unroll
        for (int kt = 0; kt < 4; kt++) {
            uint32_t addr = (uint32_t)__cvta_generic_to_shared(
                &Qs[warp * 32 + mi * 16 + (lane & 15)][kt * 16 + (lane >> 4) * 8]);
            asm volatile("ldmatrix.sync.aligned.m8n8.x4.shared.b16 {%0,%1,%2,%3}, [%4];"
                         : "=r"(qf[mi][kt][0]), "=r"(qf[mi][kt][1]),
                           "=r"(qf[mi][kt][2]), "=r"(qf[mi][kt][3])
                         : "r"(addr));
        }

    float mrow[2][2], lrow[2][2];
    float acc[2][8][4];
#pragma unroll
    for (int mi = 0; mi < 2; mi++)
#pragma unroll
        for (int h = 0; h < 2; h++) { mrow[mi][h] = -1e30f; lrow[mi][h] = 0.f; }
#pragma unroll
    for (int mi = 0; mi < 2; mi++)
#pragma unroll
        for (int n8 = 0; n8 < 8; n8++)
#pragma unroll
            for (int r = 0; r < 4; r++) acc[mi][n8][r] = 0.f;

    for (int t0 = 0; t0 <= 48; t0++) {
        {
            int hs = tid >> 7;
            int idx = tid & 127;
            int j = idx >> 3, ch = (idx & 7) * 8;
            int kpos; bool valid;
            if (t0 == 0) { kpos = j * 512; valid = (j < 8); }
            else {
                int jg = (t0 - 1) * 16 + j;
                kpos = c * WIN + jg - WIN;
                valid = (kpos >= 0 && kpos < S);
            }
            uint4 val = make_uint4(0, 0, 0, 0);
            if (valid) {
                const __half* src = hs ? v : k;
                val = *(const uint4*)&src[(size_t)kpos * DM + hoff + ch];
            }
            if (hs) *(uint4*)&Vs[j][ch] = val;
            else    *(uint4*)&Ks[j][ch] = val;
        }
        __syncthreads();

        uint32_t kf[4][4];
#pragma unroll
        for (int kt = 0; kt < 4; kt++) {
            uint32_t addr = (uint32_t)__cvta_generic_to_shared(
                &Ks[lane & 15][kt * 16 + (lane >> 4) * 8]);
            asm volatile("ldmatrix.sync.aligned.m8n8.x4.shared.b16 {%0,%1,%2,%3}, [%4];"
                         : "=r"(kf[kt][0]), "=r"(kf[kt][1]), "=r"(kf[kt][2]), "=r"(kf[kt][3])
                         : "r"(addr));
        }

        float sc[2][2][4];
#pragma unroll
        for (int mi = 0; mi < 2; mi++)
#pragma unroll
            for (int ni = 0; ni < 2; ni++)
#pragma unroll
                for (int r = 0; r < 4; r++) sc[mi][ni][r] = 0.f;
#pragma unroll
        for (int mi = 0; mi < 2; mi++)
#pragma unroll
            for (int kt = 0; kt < 4; kt++) {
                asm volatile(
                    "mma.sync.aligned.m16n8k16.row.col.f32.f16.f16.f32 "
                    "{%0,%1,%2,%3}, {%4,%5,%6,%7}, {%8,%9}, {%0,%1,%2,%3};"
                    : "+f"(sc[mi][0][0]), "+f"(sc[mi][0][1]), "+f"(sc[mi][0][2]), "+f"(sc[mi][0][3])
                    : "r"(qf[mi][kt][0]), "r"(qf[mi][kt][1]), "r"(qf[mi][kt][2]), "r"(qf[mi][kt][3]),
                      "r"(kf[kt][0]), "r"(kf[kt][2]));
                asm volatile(
                    "mma.sync.aligned.m16n8k16.row.col.f32.f16.f16.f32 "
                    "{%0,%1,%2,%3}, {%4,%5,%6,%7}, {%8,%9}, {%0,%1,%2,%3};"
                    : "+f"(sc[mi][1][0]), "+f"(sc[mi][1][1]), "+f"(sc[mi][1][2]), "+f"(sc[mi][1][3])
                    : "r"(qf[mi][kt][0]), "r"(qf[mi][kt][1]), "r"(qf[mi][kt][2]), "r"(qf[mi][kt][3]),
                      "r"(kf[kt][1]), "r"(kf[kt][3]));
            }

        uint32_t pa[2][4];
#pragma unroll
        for (int mi = 0; mi < 2; mi++) {
#pragma unroll
            for (int h = 0; h < 2; h++) {
                int qi = warp * 32 + mi * 16 + (lane >> 2) + h * 8;
                float s0 = sc[mi][0][2 * h], s1 = sc[mi][0][2 * h + 1];
                float s2 = sc[mi][1][2 * h], s3 = sc[mi][1][2 * h + 1];
                int j0 = (lane & 3) * 2;
#pragma unroll
                for (int e = 0; e < 4; e++) {
                    int jj = (e >> 1) * 8 + j0 + (e & 1);
                    bool valid;
                    if (t0 == 0) valid = (jj < 8);
                    else {
                        int jg = (t0 - 1) * 16 + jj;
                        int kp = c * WIN + jg - WIN;
                        valid = (jg >= qi) && (jg <= qi + 2 * WIN) && (kp >= 0) && (kp < S);
                    }
                    float* sp = (e == 0) ? &s0 : (e == 1) ? &s1 : (e == 2) ? &s2 : &s3;
                    if (!valid) *sp = -1e30f;
                }
                float rmax = fmaxf(fmaxf(s0, s1), fmaxf(s2, s3));
                rmax = fmaxf(rmax, __shfl_xor_sync(0xffffffffu, rmax, 1));
                rmax = fmaxf(rmax, __shfl_xor_sync(0xffffffffu, rmax, 2));
                float mnew = fmaxf(mrow[mi][h], rmax);
                float scale = __expf(mrow[mi][h] - mnew);
                float p0 = __expf(s0 - mnew), p1 = __expf(s1 - mnew);
                float p2 = __expf(s2 - mnew), p3 = __expf(s3 - mnew);
                float ls = p0 + p1 + p2 + p3;
                ls += __shfl_xor_sync(0xffffffffu, ls, 1);
                ls += __shfl_xor_sync(0xffffffffu, ls, 2);
                lrow[mi][h] = lrow[mi][h] * scale + ls;
                mrow[mi][h] = mnew;
#pragma unroll
                for (int n8 = 0; n8 < 8; n8++) {
                    acc[mi][n8][2 * h]     *= scale;
                    acc[mi][n8][2 * h + 1] *= scale;
                }
                pa[mi][h]     = pack_h2(p0, p1);
                pa[mi][h + 2] = pack_h2(p2, p3);
            }
        }

#pragma unroll
        for (int nb = 0; nb < 4; nb++) {
            uint32_t addr = (uint32_t)__cvta_generic_to_shared(
                &Vs[lane & 15][nb * 16 + (lane >> 4) * 8]);
            uint32_t r0, r1, r2, r3;
            asm volatile("ldmatrix.sync.aligned.m8n8.x4.trans.shared.b16 {%0,%1,%2,%3}, [%4];"
                         : "=r"(r0), "=r"(r1), "=r"(r2), "=r"(r3)
                         : "r"(addr));
#pragma unroll
            for (int mi = 0; mi < 2; mi++) {
                asm volatile(
                    "mma.sync.aligned.m16n8k16.row.col.f32.f16.f16.f32 "
                    "{%0,%1,%2,%3}, {%4,%5,%6,%7}, {%8,%9}, {%0,%1,%2,%3};"
                    : "+f"(acc[mi][nb*2][0]), "+f"(acc[mi][nb*2][1]),
                      "+f"(acc[mi][nb*2][2]), "+f"(acc[mi][nb*2][3])
                    : "r"(pa[mi][0]), "r"(pa[mi][1]), "r"(pa[mi][2]), "r"(pa[mi][3]),
                      "r"(r0), "r"(r1));
                asm volatile(
                    "mma.sync.aligned.m16n8k16.row.col.f32.f16.f16.f32 "
                    "{%0,%1,%2,%3}, {%4,%5,%6,%7}, {%8,%9}, {%0,%1,%2,%3};"
                    : "+f"(acc[mi][nb*2+1][0]), "+f"(acc[mi][nb*2+1][1]),
                      "+f"(acc[mi][nb*2+1][2]), "+f"(acc[mi][nb*2+1][3])
                    : "r"(pa[mi][0]), "r"(pa[mi][1]), "r"(pa[mi][2]), "r"(pa[mi][3]),
                      "r"(r2), "r"(r3));
            }
        }
        __syncthreads();
    }

#pragma unroll
    for (int mi = 0; mi < 2; mi++)
#pragma unroll
        for (int h = 0; h < 2; h++) {
            float inv = 1.f / lrow[mi][h];
            int row = warp * 32 + mi * 16 + (lane >> 2) + h * 8;
            size_t base = (size_t)(c * WIN + row) * DM + hoff;
#pragma unroll
            for (int n8 = 0; n8 < 8; n8++) {
                int dim = n8 * 8 + (lane & 3) * 2;
                *(uint32_t*)&out[base + dim] =
                    pack_h2(acc[mi][n8][2 * h] * inv, acc[mi][n8][2 * h + 1] * inv);
            }
        }
}

// ---------------- qg projection ----------------
__global__ void qg_kernel(const float* __restrict__ h, const float* __restrict__ Wqg,
                          const float* __restrict__ bqg, float* __restrict__ qg)
{
    int g = blockIdx.x;
    int o = blockIdx.y * 128 + threadIdx.x;
    const float* hr = h + (size_t)(g * 512) * DM;
    float a = bqg[o];
    for (int d = 0; d < DM; d++) a += hr[d] * Wqg[(size_t)d * DM + o];
    qg[g * DM + o] = a * SCALE;
}

// ---------------- global-token full attention ----------------
__global__ void global_attn_kernel(const float* __restrict__ qg, const float* __restrict__ kg,
                                   const float* __restrict__ vg, __half* __restrict__ out)
{
    int g = blockIdx.x, hh = blockIdx.y;
    int hoff = hh * HD;
    int tid = threadIdx.x;
    __shared__ float qs[HD];
    __shared__ float sc[S];
    __shared__ float red[256];
    if (tid < HD) qs[tid] = qg[g * DM + hoff + tid];
    __syncthreads();

    float lmax = -1e30f;
    for (int i = 0; i < 16; i++) {
        int s = i * 256 + tid;
        const float* kr = kg + (size_t)s * DM + hoff;
        float a = 0.f;
#pragma unroll
        for (int d = 0; d < HD; d++) a += qs[d] * kr[d];
        sc[s] = a;
        lmax = fmaxf(lmax, a);
    }
    red[tid] = lmax; __syncthreads();
    for (int o = 128; o > 0; o >>= 1) { if (tid < o) red[tid] = fmaxf(red[tid], red[tid + o]); __syncthreads(); }
    float mx = red[0]; __syncthreads();

    float lsum = 0.f;
    for (int i = 0; i < 16; i++) {
        int s = i * 256 + tid;
        float p = __expf(sc[s] - mx);
        sc[s] = p;
        lsum += p;
    }
    red[tid] = lsum; __syncthreads();
    for (int o = 128; o > 0; o >>= 1) { if (tid < o) red[tid] += red[tid + o]; __syncthreads(); }
    float inv = 1.f / red[0]; __syncthreads();

    int d = tid & 63;
    int part = tid >> 6;
    float a = 0.f;
    for (int s = part * 1024; s < (part + 1) * 1024; s++)
        a += sc[s] * vg[(size_t)s * DM + hoff + d];
    red[tid] = a; __syncthreads();
    if (tid < 64) {
        float r = red[tid] + red[tid + 64] + red[tid + 128] + red[tid + 192];
        out[(size_t)(g * 512) * DM + hoff + d] = __float2half(r * inv);
    }
}

// ---------------- output head ----------------
__global__ void head_kernel(const float* __restrict__ h, const float* __restrict__ Wout,
                            const float* __restrict__ bout, float* __restrict__ out)
{
    int g = blockIdx.x;
    int o = threadIdx.x;
    const float* hr = h + (size_t)(g * 512) * DM;
    float a = bout[o];
    for (int d = 0; d < DM; d++) a += hr[d] * Wout[(size_t)d * OUTD + o];
    out[g * OUTD + o] = a;
}

// ---------------- driver ----------------
extern "C" void kernel_launch(void* const* d_in, const int* in_sizes, int n_in,
                              void* d_out, int out_size)
{
    (void)in_sizes; (void)n_in; (void)out_size;
    const int*   x        = (const int*)  d_in[0];
    const float* word_emb = (const float*)d_in[1];
    const float* pos_emb  = (const float*)d_in[2];
    const float* emb_ln_s = (const float*)d_in[3];
    const float* emb_ln_b = (const float*)d_in[4];
    const float* Wq  = (const float*)d_in[5];   const float* bq  = (const float*)d_in[6];
    const float* Wk  = (const float*)d_in[7];   const float* bk  = (const float*)d_in[8];
    const float* Wv  = (const float*)d_in[9];   const float* bv  = (const float*)d_in[10];
    const float* Wo  = (const float*)d_in[11];  const float* bo  = (const float*)d_in[12];
    const float* Wqg = (const float*)d_in[13];  const float* bqg = (const float*)d_in[14];
    const float* Wkg = (const float*)d_in[15];  const float* bkg = (const float*)d_in[16];
    const float* Wvg = (const float*)d_in[17];  const float* bvg = (const float*)d_in[18];
    const float* ln1s= (const float*)d_in[19];  const float* ln1b= (const float*)d_in[20];
    const float* W1  = (const float*)d_in[21];  const float* b1  = (const float*)d_in[22];
    const float* W2  = (const float*)d_in[23];  const float* b2  = (const float*)d_in[24];
    const float* ln2s= (const float*)d_in[25];  const float* ln2b= (const float*)d_in[26];
    const float* Wout= (const float*)d_in[27];  const float* bout= (const float*)d_in[28];
    float* out = (float*)d_out;

    float *h, *kg, *vg, *y, *qg;
    __half *h16, *q16, *k16, *v16, *attn16, *ffn16;
    cudaGetSymbolAddress((void**)&h,    g_h);
    cudaGetSymbolAddress((void**)&kg,   g_kg);
    cudaGetSymbolAddress((void**)&vg,   g_vg);
    cudaGetSymbolAddress((void**)&y,    g_y);
    cudaGetSymbolAddress((void**)&qg,   g_qg);
    cudaGetSymbolAddress((void**)&h16,    g_h16);
    cudaGetSymbolAddress((void**)&q16,    g_q16);
    cudaGetSymbolAddress((void**)&k16,    g_k16);
    cudaGetSymbolAddress((void**)&v16,    g_v16);
    cudaGetSymbolAddress((void**)&attn16, g_attn16);
    cudaGetSymbolAddress((void**)&ffn16,  g_ffn16);

    __half *hWq, *hWk, *hWv, *hWo, *hWkg, *hWvg, *hW1, *hW2;
    cudaGetSymbolAddress((void**)&hWq,  g_hWq);
    cudaGetSymbolAddress((void**)&hWk,  g_hWk);
    cudaGetSymbolAddress((void**)&hWv,  g_hWv);
    cudaGetSymbolAddress((void**)&hWo,  g_hWo);
    cudaGetSymbolAddress((void**)&hWkg, g_hWkg);
    cudaGetSymbolAddress((void**)&hWvg, g_hWvg);
    cudaGetSymbolAddress((void**)&hW1,  g_hW1);
    cudaGetSymbolAddress((void**)&hW2,  g_hW2);

    cudaFuncSetAttribute(hgemm_kernel, cudaFuncAttributeMaxDynamicSharedMemorySize, TGEMM_SMEM);

    const int nP4 = LNUM * DM * DM / 4;
    const int nF4 = LNUM * DM * FF / 4;
    f2h_kernel<<<2048, 256>>>((const float4*)Wq,  (uint2*)hWq,  nP4);
    f2h_kernel<<<2048, 256>>>((const float4*)Wk,  (uint2*)hWk,  nP4);
    f2h_kernel<<<2048, 256>>>((const float4*)Wv,  (uint2*)hWv,  nP4);
    f2h_kernel<<<2048, 256>>>((const float4*)Wo,  (uint2*)hWo,  nP4);
    f2h_kernel<<<2048, 256>>>((const float4*)Wkg, (uint2*)hWkg, nP4);
    f2h_kernel<<<2048, 256>>>((const float4*)Wvg, (uint2*)hWvg, nP4);
    f2h_kernel<<<2048, 256>>>((const float4*)W1,  (uint2*)hW1,  nF4);
    f2h_kernel<<<2048, 256>>>((const float4*)W2,  (uint2*)hW2,  nF4);

    embed_kernel<<<S, 256>>>(x, word_emb, pos_emb, emb_ln_s, emb_ln_b, h, h16);

    dim3 gridQKV(DM / 128, S / 128, 3);
    dim3 gridKV (DM / 128, S / 128, 2);
    dim3 gridP  (DM / 128, S / 128, 1);
    dim3 gridF1 (FF / 128, S / 128, 1);
    dim3 gridF2 (DM / 128, S / 128, 1);
    dim3 gridAtt(CCH, HNUM);
    dim3 gridQg (NW, DM / 128);
    dim3 gridGA (NW, HNUM);

    for (int l = 0; l < LNUM; l++) {
        size_t wO  = (size_t)l * DM * DM;
        size_t bO  = (size_t)l * DM;
        size_t w1O = (size_t)l * DM * FF;
        size_t b1O = (size_t)l * FF;
        size_t w2O = (size_t)l * FF * DM;

        hgemm_kernel<<<gridQKV, 256, TGEMM_SMEM>>>(h16,
            hWq + wO, hWk + wO, hWv + wO,
            bq + bO, bk + bO, bv + bO,
            q16, k16, v16, S, DM, DM, SCALE, 1.0f, 1.0f, 0, 1);
        local_attn_mma<<<gridAtt, 256>>>(q16, k16, v16, attn16);

        qg_kernel<<<gridQg, 128>>>(h, Wqg + wO, bqg + bO, qg);
        hgemm_kernel<<<gridKV, 256, TGEMM_SMEM>>>(h16,
            hWkg + wO, hWvg + wO, hWvg + wO,
            bkg + bO, bvg + bO, bvg + bO,
            kg, vg, vg, S, DM, DM, 1.0f, 1.0f, 1.0f, 0, 0);
        global_attn_kernel<<<gridGA, 256>>>(qg, kg, vg, attn16);

        hgemm_kernel<<<gridP, 256, TGEMM_SMEM>>>(attn16,
            hWo + wO, hWo + wO, hWo + wO,
            bo + bO, bo + bO, bo + bO,
            y, y, y, S, DM, DM, 1.0f, 1.0f, 1.0f, 0, 0);
        add_ln_kernel<<<S, 256>>>(h, y, ln1s + bO, ln1b + bO, h, h16);

        hgemm_kernel<<<gridF1, 256, TGEMM_SMEM>>>(h16,
            hW1 + w1O, hW1 + w1O, hW1 + w1O,
            b1 + b1O, b1 + b1O, b1 + b1O,
            ffn16, ffn16, ffn16, S, FF, DM, 1.0f, 1.0f, 1.0f, 1, 1);
        hgemm_kernel<<<gridF2, 256, TGEMM_SMEM>>>(ffn16,
            hW2 + w2O, hW2 + w2O, hW2 + w2O,
            b2 + bO, b2 + bO, b2 + bO,
            y, y, y, S, DM, FF, 1.0f, 1.0f, 1.0f, 0, 0);
        add_ln_kernel<<<S, 256>>>(h, y, ln2s + bO, ln2b + bO, h, h16);
    }

    head_kernel<<<NW, 128>>>(h, Wout, bout, out);
}

// round 12
// speedup vs baseline: 3.1375x; 1.1660x over previous
#include <cuda_runtime.h>
#include <cuda_fp16.h>
#include <math.h>
#include <stdint.h>

// ---------------- problem constants ----------------
#define S     4096
#define DM    768
#define FF    3072
#define HNUM  12
#define HD    64
#define WIN   256
#define CCH   16
#define NW    8
#define LNUM  12
#define OUTD  128
#define SCALE 0.125f

// ---------------- scratch ----------------
__device__ float g_h    [S*DM];
__device__ float g_kg   [S*DM];
__device__ float g_vg   [S*DM];
__device__ float g_y    [S*DM];
__device__ __half g_h16   [S*DM];
__device__ __half g_q16   [S*DM];
__device__ __half g_k16   [S*DM];
__device__ __half g_v16   [S*DM];
__device__ __half g_attn16[S*DM];
__device__ __half g_ffn16 [S*FF];

// fp16 weight copies
__device__ __half g_hWq [LNUM*DM*DM];
__device__ __half g_hWk [LNUM*DM*DM];
__device__ __half g_hWv [LNUM*DM*DM];
__device__ __half g_hWo [LNUM*DM*DM];
__device__ __half g_hWkg[LNUM*DM*DM];
__device__ __half g_hWvg[LNUM*DM*DM];
__device__ __half g_hW1 [LNUM*DM*FF];
__device__ __half g_hW2 [LNUM*FF*DM];

// ---------------- helpers ----------------
__device__ __forceinline__ float gelu_f(float x) {
    float x3 = x * x * x;
    return 0.5f * x * (1.0f + tanhf(0.7978845608028654f * (x + 0.044715f * x3)));
}

__device__ __forceinline__ unsigned pack_h2(float a, float b) {
    __half2 p = __float22half2_rn(make_float2(a, b));
    return *reinterpret_cast<unsigned*>(&p);
}

__device__ __forceinline__ void cp_async16(void* smem_dst, const void* gmem_src) {
    uint32_t dst = (uint32_t)__cvta_generic_to_shared(smem_dst);
    asm volatile("cp.async.ca.shared.global [%0], [%1], 16;" :: "r"(dst), "l"(gmem_src));
}

// ---------------- fp32 -> fp16 conversion ----------------
__global__ void f2h_kernel(const float4* __restrict__ in, uint2* __restrict__ out, int n4)
{
    for (int i = blockIdx.x * blockDim.x + threadIdx.x; i < n4; i += gridDim.x * blockDim.x) {
        float4 v = in[i];
        uint2 o;
        o.x = pack_h2(v.x, v.y);
        o.y = pack_h2(v.z, v.w);
        out[i] = o;
    }
}

// ---------------- embedding + LN ----------------
__global__ void embed_kernel(const int* __restrict__ x, const float* __restrict__ we,
                             const float* __restrict__ pe, const float* __restrict__ ls,
                             const float* __restrict__ lb, float* __restrict__ h,
                             __half* __restrict__ h16)
{
    int s = blockIdx.x;
    int tid = threadIdx.x;
    int r = s & 511, w = s >> 9;
    int id = (r == 0) ? 0 : x[w * 511 + r - 1];
    __shared__ float red[256];
    float vals[3];
    float sum = 0.f;
#pragma unroll
    for (int i = 0; i < 3; i++) {
        int d = tid + i * 256;
        vals[i] = we[(size_t)id * DM + d] + pe[s * DM + d];
        sum += vals[i];
    }
    red[tid] = sum; __syncthreads();
    for (int o = 128; o > 0; o >>= 1) { if (tid < o) red[tid] += red[tid + o]; __syncthreads(); }
    float mean = red[0] / (float)DM;
    __syncthreads();
    float vsum = 0.f;
#pragma unroll
    for (int i = 0; i < 3; i++) { float t = vals[i] - mean; vsum += t * t; }
    red[tid] = vsum; __syncthreads();
    for (int o = 128; o > 0; o >>= 1) { if (tid < o) red[tid] += red[tid + o]; __syncthreads(); }
    float rstd = rsqrtf(red[0] / (float)DM + 1e-5f);
#pragma unroll
    for (int i = 0; i < 3; i++) {
        int d = tid + i * 256;
        float o = (vals[i] - mean) * rstd * ls[d] + lb[d];
        h[s * DM + d] = o;
        h16[s * DM + d] = __float2half(o);
    }
}

// ---------------- residual add + LN ----------------
__global__ void add_ln_kernel(const float* __restrict__ x, const float* __restrict__ y,
                              const float* __restrict__ ls, const float* __restrict__ lb,
                              float* __restrict__ o, __half* __restrict__ o16)
{
    int s = blockIdx.x;
    int tid = threadIdx.x;
    __shared__ float red[256];
    float vals[3];
    float sum = 0.f;
#pragma unroll
    for (int i = 0; i < 3; i++) {
        int d = tid + i * 256;
        vals[i] = x[(size_t)s * DM + d] + y[(size_t)s * DM + d];
        sum += vals[i];
    }
    red[tid] = sum; __syncthreads();
    for (int off = 128; off > 0; off >>= 1) { if (tid < off) red[tid] += red[tid + off]; __syncthreads(); }
    float mean = red[0] / (float)DM;
    __syncthreads();
    float vsum = 0.f;
#pragma unroll
    for (int i = 0; i < 3; i++) { float t = vals[i] - mean; vsum += t * t; }
    red[tid] = vsum; __syncthreads();
    for (int off = 128; off > 0; off >>= 1) { if (tid < off) red[tid] += red[tid + off]; __syncthreads(); }
    float rstd = rsqrtf(red[0] / (float)DM + 1e-5f);
#pragma unroll
    for (int i = 0; i < 3; i++) {
        int d = tid + i * 256;
        float ov = (vals[i] - mean) * rstd * ls[d] + lb[d];
        o[(size_t)s * DM + d] = ov;
        o16[(size_t)s * DM + d] = __float2half(ov);
    }
}

// ---------------- fp16 tensor-core GEMM, cp.async 2-stage, batched over z (up to 5) ----------------
#define AS_H    9216
#define STG_H   17920
#define TGEMM_SMEM (2 * STG_H * 2)

__global__ __launch_bounds__(256, 2)
void hgemm_kernel(const __half* __restrict__ A,
                  const __half* B0, const __half* B1, const __half* B2,
                  const __half* B3, const __half* B4,
                  const float* bias0, const float* bias1, const float* bias2,
                  const float* bias3, const float* bias4,
                  void* C0, void* C1, void* C2, void* C3, void* C4,
                  int M, int N, int K,
                  float al0, int act, int outHalfMask)
{
    extern __shared__ __half sm[];

    const int z = blockIdx.z;
    const __half* B = (z == 0) ? B0 : (z == 1) ? B1 : (z == 2) ? B2 : (z == 3) ? B3 : B4;
    const float* bias = (z == 0) ? bias0 : (z == 1) ? bias1 : (z == 2) ? bias2 : (z == 3) ? bias3 : bias4;
    void* C = (z == 0) ? C0 : (z == 1) ? C1 : (z == 2) ? C2 : (z == 3) ? C3 : C4;
    const float alpha = (z == 0) ? al0 : 1.0f;
    const int outHalf = (outHalfMask >> z) & 1;

    const int tid  = threadIdx.x;
    const int lane = tid & 31;
    const int warp = tid >> 5;
    const int wm = warp >> 2;
    const int wn = warp & 3;

    const int bRow = blockIdx.y * 128;
    const int bCol = blockIdx.x * 128;

    float acc[4][4][4];
#pragma unroll
    for (int i = 0; i < 4; i++)
#pragma unroll
        for (int j = 0; j < 4; j++)
#pragma unroll
            for (int r = 0; r < 4; r++) acc[i][j][r] = 0.f;

    const int nk = K >> 6;

    {
        __half* as = sm;
        __half* bs = sm + AS_H;
#pragma unroll
        for (int p = 0; p < 4; p++) {
            int id = p * 256 + tid;
            int r = id >> 3, c = (id & 7) * 8;
            cp_async16(as + r * 72 + c, A + (size_t)(bRow + r) * K + c);
        }
#pragma unroll
        for (int p = 0; p < 4; p++) {
            int id = p * 256 + tid;
            int r = id >> 4, c = (id & 15) * 8;
            cp_async16(bs + r * 136 + c, B + (size_t)r * N + bCol + c);
        }
        asm volatile("cp.async.commit_group;" ::);
    }

    for (int kt = 0; kt < nk; kt++) {
        asm volatile("cp.async.wait_group 0;" ::);
        __syncthreads();

        if (kt + 1 < nk) {
            const int k0 = (kt + 1) << 6;
            __half* as = sm + ((kt + 1) & 1) * STG_H;
            __half* bs = as + AS_H;
#pragma unroll
            for (int p = 0; p < 4; p++) {
                int id = p * 256 + tid;
                int r = id >> 3, c = (id & 7) * 8;
                cp_async16(as + r * 72 + c, A + (size_t)(bRow + r) * K + k0 + c);
            }
#pragma unroll
            for (int p = 0; p < 4; p++) {
                int id = p * 256 + tid;
                int r = id >> 4, c = (id & 15) * 8;
                cp_async16(bs + r * 136 + c, B + (size_t)(k0 + r) * N + bCol + c);
            }
            asm volatile("cp.async.commit_group;" ::);
        }

        const __half* as = sm + (kt & 1) * STG_H;
        const __half* bs = as + AS_H;
#pragma unroll
        for (int kk = 0; kk < 64; kk += 16) {
            uint32_t af[4][4];
#pragma unroll
            for (int mi = 0; mi < 4; mi++) {
                uint32_t addr = (uint32_t)__cvta_generic_to_shared(
                    as + (wm * 64 + mi * 16 + (lane & 15)) * 72 + kk + (lane >> 4) * 8);
                asm volatile("ldmatrix.sync.aligned.m8n8.x4.shared.b16 {%0,%1,%2,%3}, [%4];"
                             : "=r"(af[mi][0]), "=r"(af[mi][1]), "=r"(af[mi][2]), "=r"(af[mi][3])
                             : "r"(addr));
            }
            uint32_t bfr[4][2];
#pragma unroll
            for (int nb = 0; nb < 2; nb++) {
                uint32_t addr = (uint32_t)__cvta_generic_to_shared(
                    bs + (kk + (lane & 15)) * 136 + wn * 32 + nb * 16 + (lane >> 4) * 8);
                uint32_t r0, r1, r2, r3;
                asm volatile("ldmatrix.sync.aligned.m8n8.x4.trans.shared.b16 {%0,%1,%2,%3}, [%4];"
                             : "=r"(r0), "=r"(r1), "=r"(r2), "=r"(r3)
                             : "r"(addr));
                bfr[nb * 2][0] = r0; bfr[nb * 2][1] = r1;
                bfr[nb * 2 + 1][0] = r2; bfr[nb * 2 + 1][1] = r3;
            }
#pragma unroll
            for (int mi = 0; mi < 4; mi++)
#pragma unroll
                for (int ni = 0; ni < 4; ni++) {
                    asm volatile(
                        "mma.sync.aligned.m16n8k16.row.col.f32.f16.f16.f32 "
                        "{%0,%1,%2,%3}, {%4,%5,%6,%7}, {%8,%9}, {%0,%1,%2,%3};"
                        : "+f"(acc[mi][ni][0]), "+f"(acc[mi][ni][1]),
                          "+f"(acc[mi][ni][2]), "+f"(acc[mi][ni][3])
                        : "r"(af[mi][0]), "r"(af[mi][1]), "r"(af[mi][2]), "r"(af[mi][3]),
                          "r"(bfr[ni][0]), "r"(bfr[ni][1]));
                }
        }
        __syncthreads();
    }

#pragma unroll
    for (int mi = 0; mi < 4; mi++) {
        int row0 = bRow + wm * 64 + mi * 16 + (lane >> 2);
#pragma unroll
        for (int ni = 0; ni < 4; ni++) {
            int col = bCol + wn * 32 + ni * 8 + (lane & 3) * 2;
            float b0 = bias[col], b1 = bias[col + 1];
            float v0 = (acc[mi][ni][0] + b0) * alpha;
            float v1 = (acc[mi][ni][1] + b1) * alpha;
            float v2 = (acc[mi][ni][2] + b0) * alpha;
            float v3 = (acc[mi][ni][3] + b1) * alpha;
            if (act == 1) { v0 = gelu_f(v0); v1 = gelu_f(v1); v2 = gelu_f(v2); v3 = gelu_f(v3); }
            if (outHalf) {
                __half* Ch = (__half*)C;
                *(uint32_t*)&Ch[(size_t)row0 * N + col]       = pack_h2(v0, v1);
                *(uint32_t*)&Ch[(size_t)(row0 + 8) * N + col] = pack_h2(v2, v3);
            } else {
                float* Cf = (float*)C;
                *(float2*)&Cf[(size_t)row0 * N + col]       = make_float2(v0, v1);
                *(float2*)&Cf[(size_t)(row0 + 8) * N + col] = make_float2(v2, v3);
            }
        }
    }
}

// ---------------- local attention via tensor cores (flash-style), 128 queries/block ----------------
// grid (2*CCH, HNUM), 256 threads = 8 warps; warp handles 16 query rows.
__global__ __launch_bounds__(256)
void local_attn_mma(const __half* __restrict__ q, const __half* __restrict__ k,
                    const __half* __restrict__ v, __half* __restrict__ out)
{
    const int bx = blockIdx.x;
    const int c = bx >> 1, half = bx & 1;
    const int hh = blockIdx.y;
    const int tid = threadIdx.x;
    const int lane = tid & 31, warp = tid >> 5;
    const int hoff = hh * HD;
    const int qbase = c * WIN + half * 128;   // first global query row of this block

    __shared__ __align__(16) __half Qs[128][72];
    __shared__ __align__(16) __half Ks[16][72];
    __shared__ __align__(16) __half Vs[16][72];

    // stage Q[128][64]
    for (int i = tid; i < 1024; i += 256) {
        int row = i >> 3, ch = (i & 7) * 8;
        *(uint4*)&Qs[row][ch] = *(const uint4*)&q[(size_t)(qbase + row) * DM + hoff + ch];
    }
    __syncthreads();

    // Q a-frags: warp rows warp*16..+15
    uint32_t qf[4][4];
#pragma unroll
    for (int kt = 0; kt < 4; kt++) {
        uint32_t addr = (uint32_t)__cvta_generic_to_shared(
            &Qs[warp * 16 + (lane & 15)][kt * 16 + (lane >> 4) * 8]);
        asm volatile("ldmatrix.sync.aligned.m8n8.x4.shared.b16 {%0,%1,%2,%3}, [%4];"
                     : "=r"(qf[kt][0]), "=r"(qf[kt][1]), "=r"(qf[kt][2]), "=r"(qf[kt][3])
                     : "r"(addr));
    }

    float mrow[2] = { -1e30f, -1e30f }, lrow[2] = { 0.f, 0.f };
    float acc[8][4];
#pragma unroll
    for (int n8 = 0; n8 < 8; n8++)
#pragma unroll
        for (int r = 0; r < 4; r++) acc[n8][r] = 0.f;

    for (int t0 = 0; t0 <= 48; t0++) {
        // stage K/V tile (16 keys x 64 dims)
        {
            int hs = tid >> 7;
            int idx = tid & 127;
            int j = idx >> 3, ch = (idx & 7) * 8;
            int kpos; bool valid;
            if (t0 == 0) { kpos = j * 512; valid = (j < 8); }
            else {
                int jg = (t0 - 1) * 16 + j;
                kpos = c * WIN + jg - WIN;
                valid = (kpos >= 0 && kpos < S);
            }
            uint4 val = make_uint4(0, 0, 0, 0);
            if (valid) {
                const __half* src = hs ? v : k;
                val = *(const uint4*)&src[(size_t)kpos * DM + hoff + ch];
            }
            if (hs) *(uint4*)&Vs[j][ch] = val;
            else    *(uint4*)&Ks[j][ch] = val;
        }
        __syncthreads();

        uint32_t kf[4][4];
#pragma unroll
        for (int kt = 0; kt < 4; kt++) {
            uint32_t addr = (uint32_t)__cvta_generic_to_shared(
                &Ks[lane & 15][kt * 16 + (lane >> 4) * 8]);
            asm volatile("ldmatrix.sync.aligned.m8n8.x4.shared.b16 {%0,%1,%2,%3}, [%4];"
                         : "=r"(kf[kt][0]), "=r"(kf[kt][1]), "=r"(kf[kt][2]), "=r"(kf[kt][3])
                         : "r"(addr));
        }

        float sc[2][4];
#pragma unroll
        for (int ni = 0; ni < 2; ni++)
#pragma unroll
            for (int r = 0; r < 4; r++) sc[ni][r] = 0.f;
#pragma unroll
        for (int kt = 0; kt < 4; kt++) {
            asm volatile(
                "mma.sync.aligned.m16n8k16.row.col.f32.f16.f16.f32 "
                "{%0,%1,%2,%3}, {%4,%5,%6,%7}, {%8,%9}, {%0,%1,%2,%3};"
                : "+f"(sc[0][0]), "+f"(sc[0][1]), "+f"(sc[0][2]), "+f"(sc[0][3])
                : "r"(qf[kt][0]), "r"(qf[kt][1]), "r"(qf[kt][2]), "r"(qf[kt][3]),
                  "r"(kf[kt][0]), "r"(kf[kt][2]));
            asm volatile(
                "mma.sync.aligned.m16n8k16.row.col.f32.f16.f16.f32 "
                "{%0,%1,%2,%3}, {%4,%5,%6,%7}, {%8,%9}, {%0,%1,%2,%3};"
                : "+f"(sc[1][0]), "+f"(sc[1][1]), "+f"(sc[1][2]), "+f"(sc[1][3])
                : "r"(qf[kt][0]), "r"(qf[kt][1]), "r"(qf[kt][2]), "r"(qf[kt][3]),
                  "r"(kf[kt][1]), "r"(kf[kt][3]));
        }

        // mask + online softmax + P a-frags
        uint32_t pa[4];
#pragma unroll
        for (int h = 0; h < 2; h++) {
            int qi = half * 128 + warp * 16 + (lane >> 2) + h * 8;  // within-chunk query index
            float s0 = sc[0][2 * h], s1 = sc[0][2 * h + 1];
            float s2 = sc[1][2 * h], s3 = sc[1][2 * h + 1];
            int j0 = (lane & 3) * 2;
#pragma unroll
            for (int e = 0; e < 4; e++) {
                int jj = (e >> 1) * 8 + j0 + (e & 1);
                bool valid;
                if (t0 == 0) valid = (jj < 8);
                else {
                    int jg = (t0 - 1) * 16 + jj;
                    int kp = c * WIN + jg - WIN;
                    valid = (jg >= qi) && (jg <= qi + 2 * WIN) && (kp >= 0) && (kp < S);
                }
                float* sp = (e == 0) ? &s0 : (e == 1) ? &s1 : (e == 2) ? &s2 : &s3;
                if (!valid) *sp = -1e30f;
            }
            float rmax = fmaxf(fmaxf(s0, s1), fmaxf(s2, s3));
            rmax = fmaxf(rmax, __shfl_xor_sync(0xffffffffu, rmax, 1));
            rmax = fmaxf(rmax, __shfl_xor_sync(0xffffffffu, rmax, 2));
            float mnew = fmaxf(mrow[h], rmax);
            float scale = __expf(mrow[h] - mnew);
            float p0 = __expf(s0 - mnew), p1 = __expf(s1 - mnew);
            float p2 = __expf(s2 - mnew), p3 = __expf(s3 - mnew);
            float ls = p0 + p1 + p2 + p3;
            ls += __shfl_xor_sync(0xffffffffu, ls, 1);
            ls += __shfl_xor_sync(0xffffffffu, ls, 2);
            lrow[h] = lrow[h] * scale + ls;
            mrow[h] = mnew;
#pragma unroll
            for (int n8 = 0; n8 < 8; n8++) {
                acc[n8][2 * h]     *= scale;
                acc[n8][2 * h + 1] *= scale;
            }
            pa[h]     = pack_h2(p0, p1);
            pa[h + 2] = pack_h2(p2, p3);
        }

        // V b-frags + AV MMAs ({r0,r1} low-n, {r2,r3} high-n)
#pragma unroll
        for (int nb = 0; nb < 4; nb++) {
            uint32_t addr = (uint32_t)__cvta_generic_to_shared(
                &Vs[lane & 15][nb * 16 + (lane >> 4) * 8]);
            uint32_t r0, r1, r2, r3;
            asm volatile("ldmatrix.sync.aligned.m8n8.x4.trans.shared.b16 {%0,%1,%2,%3}, [%4];"
                         : "=r"(r0), "=r"(r1), "=r"(r2), "=r"(r3)
                         : "r"(addr));
            asm volatile(
                "mma.sync.aligned.m16n8k16.row.col.f32.f16.f16.f32 "
                "{%0,%1,%2,%3}, {%4,%5,%6,%7}, {%8,%9}, {%0,%1,%2,%3};"
                : "+f"(acc[nb*2][0]), "+f"(acc[nb*2][1]), "+f"(acc[nb*2][2]), "+f"(acc[nb*2][3])
                : "r"(pa[0]), "r"(pa[1]), "r"(pa[2]), "r"(pa[3]),
                  "r"(r0), "r"(r1));
            asm volatile(
                "mma.sync.aligned.m16n8k16.row.col.f32.f16.f16.f32 "
                "{%0,%1,%2,%3}, {%4,%5,%6,%7}, {%8,%9}, {%0,%1,%2,%3};"
                : "+f"(acc[nb*2+1][0]), "+f"(acc[nb*2+1][1]), "+f"(acc[nb*2+1][2]), "+f"(acc[nb*2+1][3])
                : "r"(pa[0]), "r"(pa[1]), "r"(pa[2]), "r"(pa[3]),
                  "r"(r2), "r"(r3));
        }
        __syncthreads();
    }

    // epilogue
#pragma unroll
    for (int h = 0; h < 2; h++) {
        float inv = 1.f / lrow[h];
        int row = warp * 16 + (lane >> 2) + h * 8;
        size_t base = (size_t)(qbase + row) * DM + hoff;
#pragma unroll
        for (int n8 = 0; n8 < 8; n8++) {
            int dim = n8 * 8 + (lane & 3) * 2;
            *(uint32_t*)&out[base + dim] =
                pack_h2(acc[n8][2 * h] * inv, acc[n8][2 * h + 1] * inv);
        }
    }
}

// ---------------- global-token full attention (qg fused in) ----------------
__global__ void global_attn_kernel(const float* __restrict__ h, const float* __restrict__ Wqg,
                                   const float* __restrict__ bqg,
                                   const float* __restrict__ kg, const float* __restrict__ vg,
                                   __half* __restrict__ out)
{
    int g = blockIdx.x, hh = blockIdx.y;
    int hoff = hh * HD;
    int tid = threadIdx.x;
    __shared__ float qs[HD];
    __shared__ float sc[S];
    __shared__ float red[256];

    // fused qg: qs[d] = (h[g*512,:] . Wqg[:, hoff+d] + bqg[hoff+d]) * SCALE
    {
        int d = tid & 63, part = tid >> 6;
        const float* hr = h + (size_t)(g * 512) * DM;
        float a = 0.f;
        for (int kk = part * 192; kk < (part + 1) * 192; kk++)
            a += hr[kk] * Wqg[(size_t)kk * DM + hoff + d];
        red[tid] = a; __syncthreads();
        if (tid < 64)
            qs[tid] = (red[tid] + red[tid + 64] + red[tid + 128] + red[tid + 192]
                       + bqg[hoff + tid]) * SCALE;
        __syncthreads();
    }

    float lmax = -1e30f;
    for (int i = 0; i < 16; i++) {
        int s = i * 256 + tid;
        const float* kr = kg + (size_t)s * DM + hoff;
        float a = 0.f;
#pragma unroll
        for (int d = 0; d < HD; d++) a += qs[d] * kr[d];
        sc[s] = a;
        lmax = fmaxf(lmax, a);
    }
    red[tid] = lmax; __syncthreads();
    for (int o = 128; o > 0; o >>= 1) { if (tid < o) red[tid] = fmaxf(red[tid], red[tid + o]); __syncthreads(); }
    float mx = red[0]; __syncthreads();

    float lsum = 0.f;
    for (int i = 0; i < 16; i++) {
        int s = i * 256 + tid;
        float p = __expf(sc[s] - mx);
        sc[s] = p;
        lsum += p;
    }
    red[tid] = lsum; __syncthreads();
    for (int o = 128; o > 0; o >>= 1) { if (tid < o) red[tid] += red[tid + o]; __syncthreads(); }
    float inv = 1.f / red[0]; __syncthreads();

    int d = tid & 63;
    int part = tid >> 6;
    float a = 0.f;
    for (int s = part * 1024; s < (part + 1) * 1024; s++)
        a += sc[s] * vg[(size_t)s * DM + hoff + d];
    red[tid] = a; __syncthreads();
    if (tid < 64) {
        float r = red[tid] + red[tid + 64] + red[tid + 128] + red[tid + 192];
        out[(size_t)(g * 512) * DM + hoff + d] = __float2half(r * inv);
    }
}

// ---------------- output head ----------------
__global__ void head_kernel(const float* __restrict__ h, const float* __restrict__ Wout,
                            const float* __restrict__ bout, float* __restrict__ out)
{
    int g = blockIdx.x;
    int o = threadIdx.x;
    const float* hr = h + (size_t)(g * 512) * DM;
    float a = bout[o];
    for (int d = 0; d < DM; d++) a += hr[d] * Wout[(size_t)d * OUTD + o];
    out[g * OUTD + o] = a;
}

// ---------------- driver ----------------
extern "C" void kernel_launch(void* const* d_in, const int* in_sizes, int n_in,
                              void* d_out, int out_size)
{
    (void)in_sizes; (void)n_in; (void)out_size;
    const int*   x        = (const int*)  d_in[0];
    const float* word_emb = (const float*)d_in[1];
    const float* pos_emb  = (const float*)d_in[2];
    const float* emb_ln_s = (const float*)d_in[3];
    const float* emb_ln_b = (const float*)d_in[4];
    const float* Wq  = (const float*)d_in[5];   const float* bq  = (const float*)d_in[6];
    const float* Wk  = (const float*)d_in[7];   const float* bk  = (const float*)d_in[8];
    const float* Wv  = (const float*)d_in[9];   const float* bv  = (const float*)d_in[10];
    const float* Wo  = (const float*)d_in[11];  const float* bo  = (const float*)d_in[12];
    const float* Wqg = (const float*)d_in[13];  const float* bqg = (const float*)d_in[14];
    const float* Wkg = (const float*)d_in[15];  const float* bkg = (const float*)d_in[16];
    const float* Wvg = (const float*)d_in[17];  const float* bvg = (const float*)d_in[18];
    const float* ln1s= (const float*)d_in[19];  const float* ln1b= (const float*)d_in[20];
    const float* W1  = (const float*)d_in[21];  const float* b1  = (const float*)d_in[22];
    const float* W2  = (const float*)d_in[23];  const float* b2  = (const float*)d_in[24];
    const float* ln2s= (const float*)d_in[25];  const float* ln2b= (const float*)d_in[26];
    const float* Wout= (const float*)d_in[27];  const float* bout= (const float*)d_in[28];
    float* out = (float*)d_out;

    float *h, *kg, *vg, *y;
    __half *h16, *q16, *k16, *v16, *attn16, *ffn16;
    cudaGetSymbolAddress((void**)&h,    g_h);
    cudaGetSymbolAddress((void**)&kg,   g_kg);
    cudaGetSymbolAddress((void**)&vg,   g_vg);
    cudaGetSymbolAddress((void**)&y,    g_y);
    cudaGetSymbolAddress((void**)&h16,    g_h16);
    cudaGetSymbolAddress((void**)&q16,    g_q16);
    cudaGetSymbolAddress((void**)&k16,    g_k16);
    cudaGetSymbolAddress((void**)&v16,    g_v16);
    cudaGetSymbolAddress((void**)&attn16, g_attn16);
    cudaGetSymbolAddress((void**)&ffn16,  g_ffn16);

    __half *hWq, *hWk, *hWv, *hWo, *hWkg, *hWvg, *hW1, *hW2;
    cudaGetSymbolAddress((void**)&hWq,  g_hWq);
    cudaGetSymbolAddress((void**)&hWk,  g_hWk);
    cudaGetSymbolAddress((void**)&hWv,  g_hWv);
    cudaGetSymbolAddress((void**)&hWo,  g_hWo);
    cudaGetSymbolAddress((void**)&hWkg, g_hWkg);
    cudaGetSymbolAddress((void**)&hWvg, g_hWvg);
    cudaGetSymbolAddress((void**)&hW1,  g_hW1);
    cudaGetSymbolAddress((void**)&hW2,  g_hW2);

    cudaFuncSetAttribute(hgemm_kernel, cudaFuncAttributeMaxDynamicSharedMemorySize, TGEMM_SMEM);

    const int nP4 = LNUM * DM * DM / 4;
    const int nF4 = LNUM * DM * FF / 4;
    f2h_kernel<<<2048, 256>>>((const float4*)Wq,  (uint2*)hWq,  nP4);
    f2h_kernel<<<2048, 256>>>((const float4*)Wk,  (uint2*)hWk,  nP4);
    f2h_kernel<<<2048, 256>>>((const float4*)Wv,  (uint2*)hWv,  nP4);
    f2h_kernel<<<2048, 256>>>((const float4*)Wo,  (uint2*)hWo,  nP4);
    f2h_kernel<<<2048, 256>>>((const float4*)Wkg, (uint2*)hWkg, nP4);
    f2h_kernel<<<2048, 256>>>((const float4*)Wvg, (uint2*)hWvg, nP4);
    f2h_kernel<<<2048, 256>>>((const float4*)W1,  (uint2*)hW1,  nF4);
    f2h_kernel<<<2048, 256>>>((const float4*)W2,  (uint2*)hW2,  nF4);

    embed_kernel<<<S, 256>>>(x, word_emb, pos_emb, emb_ln_s, emb_ln_b, h, h16);

    dim3 grid5  (DM / 128, S / 128, 5);
    dim3 gridP  (DM / 128, S / 128, 1);
    dim3 gridF1 (FF / 128, S / 128, 1);
    dim3 gridF2 (DM / 128, S / 128, 1);
    dim3 gridAtt(2 * CCH, HNUM);
    dim3 gridGA (NW, HNUM);

    for (int l = 0; l < LNUM; l++) {
        size_t wO  = (size_t)l * DM * DM;
        size_t bO  = (size_t)l * DM;
        size_t w1O = (size_t)l * DM * FF;
        size_t b1O = (size_t)l * FF;
        size_t w2O = (size_t)l * FF * DM;

        // fused Q,K,V,Kg,Vg projections. outHalf mask: z0-2 -> fp16, z3-4 -> fp32
        hgemm_kernel<<<grid5, 256, TGEMM_SMEM>>>(h16,
            hWq + wO, hWk + wO, hWv + wO, hWkg + wO, hWvg + wO,
            bq + bO, bk + bO, bv + bO, bkg + bO, bvg + bO,
            q16, k16, v16, kg, vg,
            S, DM, DM, SCALE, 0, 0b00111);
        local_attn_mma<<<gridAtt, 256>>>(q16, k16, v16, attn16);
        global_attn_kernel<<<gridGA, 256>>>(h, Wqg + wO, bqg + bO, kg, vg, attn16);

        hgemm_kernel<<<gridP, 256, TGEMM_SMEM>>>(attn16,
            hWo + wO, hWo + wO, hWo + wO, hWo + wO, hWo + wO,
            bo + bO, bo + bO, bo + bO, bo + bO, bo + bO,
            y, y, y, y, y,
            S, DM, DM, 1.0f, 0, 0);
        add_ln_kernel<<<S, 256>>>(h, y, ln1s + bO, ln1b + bO, h, h16);

        hgemm_kernel<<<gridF1, 256, TGEMM_SMEM>>>(h16,
            hW1 + w1O, hW1 + w1O, hW1 + w1O, hW1 + w1O, hW1 + w1O,
            b1 + b1O, b1 + b1O, b1 + b1O, b1 + b1O, b1 + b1O,
            ffn16, ffn16, ffn16, ffn16, ffn16,
            S, FF, DM, 1.0f, 1, 0b11111);
        hgemm_kernel<<<gridF2, 256, TGEMM_SMEM>>>(ffn16,
            hW2 + w2O, hW2 + w2O, hW2 + w2O, hW2 + w2O, hW2 + w2O,
            b2 + bO, b2 + bO, b2 + bO, b2 + bO, b2 + bO,
            y, y, y, y, y,
            S, DM, FF, 1.0f, 0, 0);
        add_ln_kernel<<<S, 256>>>(h, y, ln2s + bO, ln2b + bO, h, h16);
    }

    head_kernel<<<NW, 128>>>(h, Wout, bout, out);
}

// round 13
// speedup vs baseline: 3.5776x; 1.1403x over previous
#include <cuda_runtime.h>
#include <cuda_fp16.h>
#include <math.h>
#include <stdint.h>

// ---------------- problem constants ----------------
#define S     4096
#define DM    768
#define FF    3072
#define HNUM  12
#define HD    64
#define WIN   256
#define CCH   16
#define NW    8
#define LNUM  12
#define OUTD  128
#define SCALE 0.125f

// ---------------- scratch ----------------
__device__ float g_h    [S*DM];
__device__ float g_y    [S*DM];
__device__ __half g_h16   [S*DM];
__device__ __half g_q16   [S*DM];
__device__ __half g_k16   [S*DM];
__device__ __half g_v16   [S*DM];
__device__ __half g_kg16  [S*DM];
__device__ __half g_vg16  [S*DM];
__device__ __half g_attn16[S*DM];
__device__ __half g_ffn16 [S*FF];

// fp16 weight copies
__device__ __half g_hWq [LNUM*DM*DM];
__device__ __half g_hWk [LNUM*DM*DM];
__device__ __half g_hWv [LNUM*DM*DM];
__device__ __half g_hWo [LNUM*DM*DM];
__device__ __half g_hWkg[LNUM*DM*DM];
__device__ __half g_hWvg[LNUM*DM*DM];
__device__ __half g_hW1 [LNUM*DM*FF];
__device__ __half g_hW2 [LNUM*FF*DM];

// ---------------- helpers ----------------
__device__ __forceinline__ float gelu_f(float x) {
    float x3 = x * x * x;
    return 0.5f * x * (1.0f + tanhf(0.7978845608028654f * (x + 0.044715f * x3)));
}

__device__ __forceinline__ unsigned pack_h2(float a, float b) {
    __half2 p = __float22half2_rn(make_float2(a, b));
    return *reinterpret_cast<unsigned*>(&p);
}

__device__ __forceinline__ void cp_async16(void* smem_dst, const void* gmem_src) {
    uint32_t dst = (uint32_t)__cvta_generic_to_shared(smem_dst);
    asm volatile("cp.async.ca.shared.global [%0], [%1], 16;" :: "r"(dst), "l"(gmem_src));
}

// cp.async with zero-fill: copies src_sz bytes (0 or 16), zero-fills the rest
__device__ __forceinline__ void cp_async16z(void* smem_dst, const void* gmem_src, int src_sz) {
    uint32_t dst = (uint32_t)__cvta_generic_to_shared(smem_dst);
    asm volatile("cp.async.ca.shared.global [%0], [%1], 16, %2;"
                 :: "r"(dst), "l"(gmem_src), "r"(src_sz));
}

// ---------------- fp32 -> fp16 conversion, batched over z ----------------
__global__ void f2h_kernel6(const float4* in0, const float4* in1, const float4* in2,
                            const float4* in3, const float4* in4, const float4* in5,
                            uint2* out0, uint2* out1, uint2* out2,
                            uint2* out3, uint2* out4, uint2* out5, int n4)
{
    int z = blockIdx.z;
    const float4* in = (z == 0) ? in0 : (z == 1) ? in1 : (z == 2) ? in2 :
                       (z == 3) ? in3 : (z == 4) ? in4 : in5;
    uint2* out = (z == 0) ? out0 : (z == 1) ? out1 : (z == 2) ? out2 :
                 (z == 3) ? out3 : (z == 4) ? out4 : out5;
    for (int i = blockIdx.x * blockDim.x + threadIdx.x; i < n4; i += gridDim.x * blockDim.x) {
        float4 v = in[i];
        uint2 o;
        o.x = pack_h2(v.x, v.y);
        o.y = pack_h2(v.z, v.w);
        out[i] = o;
    }
}

__global__ void f2h_kernel(const float4* __restrict__ in, uint2* __restrict__ out, int n4)
{
    for (int i = blockIdx.x * blockDim.x + threadIdx.x; i < n4; i += gridDim.x * blockDim.x) {
        float4 v = in[i];
        uint2 o;
        o.x = pack_h2(v.x, v.y);
        o.y = pack_h2(v.z, v.w);
        out[i] = o;
    }
}

// ---------------- embedding + LN ----------------
__global__ void embed_kernel(const int* __restrict__ x, const float* __restrict__ we,
                             const float* __restrict__ pe, const float* __restrict__ ls,
                             const float* __restrict__ lb, float* __restrict__ h,
                             __half* __restrict__ h16)
{
    int s = blockIdx.x;
    int tid = threadIdx.x;
    int r = s & 511, w = s >> 9;
    int id = (r == 0) ? 0 : x[w * 511 + r - 1];
    __shared__ float red[256];
    float vals[3];
    float sum = 0.f;
#pragma unroll
    for (int i = 0; i < 3; i++) {
        int d = tid + i * 256;
        vals[i] = we[(size_t)id * DM + d] + pe[s * DM + d];
        sum += vals[i];
    }
    red[tid] = sum; __syncthreads();
    for (int o = 128; o > 0; o >>= 1) { if (tid < o) red[tid] += red[tid + o]; __syncthreads(); }
    float mean = red[0] / (float)DM;
    __syncthreads();
    float vsum = 0.f;
#pragma unroll
    for (int i = 0; i < 3; i++) { float t = vals[i] - mean; vsum += t * t; }
    red[tid] = vsum; __syncthreads();
    for (int o = 128; o > 0; o >>= 1) { if (tid < o) red[tid] += red[tid + o]; __syncthreads(); }
    float rstd = rsqrtf(red[0] / (float)DM + 1e-5f);
#pragma unroll
    for (int i = 0; i < 3; i++) {
        int d = tid + i * 256;
        float o = (vals[i] - mean) * rstd * ls[d] + lb[d];
        h[s * DM + d] = o;
        h16[s * DM + d] = __float2half(o);
    }
}

// ---------------- residual add + LN ----------------
__global__ void add_ln_kernel(const float* __restrict__ x, const float* __restrict__ y,
                              const float* __restrict__ ls, const float* __restrict__ lb,
                              float* __restrict__ o, __half* __restrict__ o16)
{
    int s = blockIdx.x;
    int tid = threadIdx.x;
    __shared__ float red[256];
    float vals[3];
    float sum = 0.f;
#pragma unroll
    for (int i = 0; i < 3; i++) {
        int d = tid + i * 256;
        vals[i] = x[(size_t)s * DM + d] + y[(size_t)s * DM + d];
        sum += vals[i];
    }
    red[tid] = sum; __syncthreads();
    for (int off = 128; off > 0; off >>= 1) { if (tid < off) red[tid] += red[tid + off]; __syncthreads(); }
    float mean = red[0] / (float)DM;
    __syncthreads();
    float vsum = 0.f;
#pragma unroll
    for (int i = 0; i < 3; i++) { float t = vals[i] - mean; vsum += t * t; }
    red[tid] = vsum; __syncthreads();
    for (int off = 128; off > 0; off >>= 1) { if (tid < off) red[tid] += red[tid + off]; __syncthreads(); }
    float rstd = rsqrtf(red[0] / (float)DM + 1e-5f);
#pragma unroll
    for (int i = 0; i < 3; i++) {
        int d = tid + i * 256;
        float ov = (vals[i] - mean) * rstd * ls[d] + lb[d];
        o[(size_t)s * DM + d] = ov;
        o16[(size_t)s * DM + d] = __float2half(ov);
    }
}

// ---------------- fp16 tensor-core GEMM, cp.async 2-stage, batched over z (up to 5) ----------------
#define AS_H    9216
#define STG_H   17920
#define TGEMM_SMEM (2 * STG_H * 2)

__global__ __launch_bounds__(256, 2)
void hgemm_kernel(const __half* __restrict__ A,
                  const __half* B0, const __half* B1, const __half* B2,
                  const __half* B3, const __half* B4,
                  const float* bias0, const float* bias1, const float* bias2,
                  const float* bias3, const float* bias4,
                  void* C0, void* C1, void* C2, void* C3, void* C4,
                  int M, int N, int K,
                  float al0, int act, int outHalfMask)
{
    extern __shared__ __half sm[];

    const int z = blockIdx.z;
    const __half* B = (z == 0) ? B0 : (z == 1) ? B1 : (z == 2) ? B2 : (z == 3) ? B3 : B4;
    const float* bias = (z == 0) ? bias0 : (z == 1) ? bias1 : (z == 2) ? bias2 : (z == 3) ? bias3 : bias4;
    void* C = (z == 0) ? C0 : (z == 1) ? C1 : (z == 2) ? C2 : (z == 3) ? C3 : C4;
    const float alpha = (z == 0) ? al0 : 1.0f;
    const int outHalf = (outHalfMask >> z) & 1;

    const int tid  = threadIdx.x;
    const int lane = tid & 31;
    const int warp = tid >> 5;
    const int wm = warp >> 2;
    const int wn = warp & 3;

    const int bRow = blockIdx.y * 128;
    const int bCol = blockIdx.x * 128;

    float acc[4][4][4];
#pragma unroll
    for (int i = 0; i < 4; i++)
#pragma unroll
        for (int j = 0; j < 4; j++)
#pragma unroll
            for (int r = 0; r < 4; r++) acc[i][j][r] = 0.f;

    const int nk = K >> 6;

    {
        __half* as = sm;
        __half* bs = sm + AS_H;
#pragma unroll
        for (int p = 0; p < 4; p++) {
            int id = p * 256 + tid;
            int r = id >> 3, c = (id & 7) * 8;
            cp_async16(as + r * 72 + c, A + (size_t)(bRow + r) * K + c);
        }
#pragma unroll
        for (int p = 0; p < 4; p++) {
            int id = p * 256 + tid;
            int r = id >> 4, c = (id & 15) * 8;
            cp_async16(bs + r * 136 + c, B + (size_t)r * N + bCol + c);
        }
        asm volatile("cp.async.commit_group;" ::);
    }

    for (int kt = 0; kt < nk; kt++) {
        asm volatile("cp.async.wait_group 0;" ::);
        __syncthreads();

        if (kt + 1 < nk) {
            const int k0 = (kt + 1) << 6;
            __half* as = sm + ((kt + 1) & 1) * STG_H;
            __half* bs = as + AS_H;
#pragma unroll
            for (int p = 0; p < 4; p++) {
                int id = p * 256 + tid;
                int r = id >> 3, c = (id & 7) * 8;
                cp_async16(as + r * 72 + c, A + (size_t)(bRow + r) * K + k0 + c);
            }
#pragma unroll
            for (int p = 0; p < 4; p++) {
                int id = p * 256 + tid;
                int r = id >> 4, c = (id & 15) * 8;
                cp_async16(bs + r * 136 + c, B + (size_t)(k0 + r) * N + bCol + c);
            }
            asm volatile("cp.async.commit_group;" ::);
        }

        const __half* as = sm + (kt & 1) * STG_H;
        const __half* bs = as + AS_H;
#pragma unroll
        for (int kk = 0; kk < 64; kk += 16) {
            uint32_t af[4][4];
#pragma unroll
            for (int mi = 0; mi < 4; mi++) {
                uint32_t addr = (uint32_t)__cvta_generic_to_shared(
                    as + (wm * 64 + mi * 16 + (lane & 15)) * 72 + kk + (lane >> 4) * 8);
                asm volatile("ldmatrix.sync.aligned.m8n8.x4.shared.b16 {%0,%1,%2,%3}, [%4];"
                             : "=r"(af[mi][0]), "=r"(af[mi][1]), "=r"(af[mi][2]), "=r"(af[mi][3])
                             : "r"(addr));
            }
            uint32_t bfr[4][2];
#pragma unroll
            for (int nb = 0; nb < 2; nb++) {
                uint32_t addr = (uint32_t)__cvta_generic_to_shared(
                    bs + (kk + (lane & 15)) * 136 + wn * 32 + nb * 16 + (lane >> 4) * 8);
                uint32_t r0, r1, r2, r3;
                asm volatile("ldmatrix.sync.aligned.m8n8.x4.trans.shared.b16 {%0,%1,%2,%3}, [%4];"
                             : "=r"(r0), "=r"(r1), "=r"(r2), "=r"(r3)
                             : "r"(addr));
                bfr[nb * 2][0] = r0; bfr[nb * 2][1] = r1;
                bfr[nb * 2 + 1][0] = r2; bfr[nb * 2 + 1][1] = r3;
            }
#pragma unroll
            for (int mi = 0; mi < 4; mi++)
#pragma unroll
                for (int ni = 0; ni < 4; ni++) {
                    asm volatile(
                        "mma.sync.aligned.m16n8k16.row.col.f32.f16.f16.f32 "
                        "{%0,%1,%2,%3}, {%4,%5,%6,%7}, {%8,%9}, {%0,%1,%2,%3};"
                        : "+f"(acc[mi][ni][0]), "+f"(acc[mi][ni][1]),
                          "+f"(acc[mi][ni][2]), "+f"(acc[mi][ni][3])
                        : "r"(af[mi][0]), "r"(af[mi][1]), "r"(af[mi][2]), "r"(af[mi][3]),
                          "r"(bfr[ni][0]), "r"(bfr[ni][1]));
                }
        }
        __syncthreads();
    }

#pragma unroll
    for (int mi = 0; mi < 4; mi++) {
        int row0 = bRow + wm * 64 + mi * 16 + (lane >> 2);
#pragma unroll
        for (int ni = 0; ni < 4; ni++) {
            int col = bCol + wn * 32 + ni * 8 + (lane & 3) * 2;
            float b0 = bias[col], b1 = bias[col + 1];
            float v0 = (acc[mi][ni][0] + b0) * alpha;
            float v1 = (acc[mi][ni][1] + b1) * alpha;
            float v2 = (acc[mi][ni][2] + b0) * alpha;
            float v3 = (acc[mi][ni][3] + b1) * alpha;
            if (act == 1) { v0 = gelu_f(v0); v1 = gelu_f(v1); v2 = gelu_f(v2); v3 = gelu_f(v3); }
            if (outHalf) {
                __half* Ch = (__half*)C;
                *(uint32_t*)&Ch[(size_t)row0 * N + col]       = pack_h2(v0, v1);
                *(uint32_t*)&Ch[(size_t)(row0 + 8) * N + col] = pack_h2(v2, v3);
            } else {
                float* Cf = (float*)C;
                *(float2*)&Cf[(size_t)row0 * N + col]       = make_float2(v0, v1);
                *(float2*)&Cf[(size_t)(row0 + 8) * N + col] = make_float2(v2, v3);
            }
        }
    }
}

// ---------------- local attention (flash-style), 128 queries/block, cp.async K/V ----------------
__global__ __launch_bounds__(256)
void local_attn_mma(const __half* __restrict__ q, const __half* __restrict__ k,
                    const __half* __restrict__ v, __half* __restrict__ out)
{
    const int bx = blockIdx.x;
    const int c = bx >> 1, half = bx & 1;
    const int hh = blockIdx.y;
    const int tid = threadIdx.x;
    const int lane = tid & 31, warp = tid >> 5;
    const int hoff = hh * HD;
    const int qbase = c * WIN + half * 128;

    __shared__ __align__(16) __half Qs[128][72];
    __shared__ __align__(16) __half Ks[2][16][72];
    __shared__ __align__(16) __half Vs[2][16][72];

    // staging indices (fixed per thread)
    const int st_hs = tid >> 7;            // 0: K, 1: V
    const int st_j  = (tid & 127) >> 3;    // key row 0..15
    const int st_ch = (tid & 7) * 8;       // dim chunk

    // stage Q[128][64]
    for (int i = tid; i < 1024; i += 256) {
        int row = i >> 3, ch = (i & 7) * 8;
        *(uint4*)&Qs[row][ch] = *(const uint4*)&q[(size_t)(qbase + row) * DM + hoff + ch];
    }

    // prologue: issue K/V tile 0 (global keys) into buf 0
    {
        int kpos = st_j * 512;
        bool valid = (st_j < 8);
        const __half* src = st_hs ? v : k;
        void* dst = st_hs ? (void*)&Vs[0][st_j][st_ch] : (void*)&Ks[0][st_j][st_ch];
        cp_async16z(dst, src + (size_t)(valid ? kpos : 0) * DM + hoff + st_ch, valid ? 16 : 0);
        asm volatile("cp.async.commit_group;" ::);
    }
    __syncthreads();

    // Q a-frags
    uint32_t qf[4][4];
#pragma unroll
    for (int kt = 0; kt < 4; kt++) {
        uint32_t addr = (uint32_t)__cvta_generic_to_shared(
            &Qs[warp * 16 + (lane & 15)][kt * 16 + (lane >> 4) * 8]);
        asm volatile("ldmatrix.sync.aligned.m8n8.x4.shared.b16 {%0,%1,%2,%3}, [%4];"
                     : "=r"(qf[kt][0]), "=r"(qf[kt][1]), "=r"(qf[kt][2]), "=r"(qf[kt][3])
                     : "r"(addr));
    }

    float mrow[2] = { -1e30f, -1e30f }, lrow[2] = { 0.f, 0.f };
    float acc[8][4];
#pragma unroll
    for (int n8 = 0; n8 < 8; n8++)
#pragma unroll
        for (int r = 0; r < 4; r++) acc[n8][r] = 0.f;

    for (int t0 = 0; t0 <= 48; t0++) {
        const int cur = t0 & 1, nxt = cur ^ 1;

        asm volatile("cp.async.wait_group 0;" ::);
        __syncthreads();   // tile t0 resident; all warps done with buf[nxt] (tile t0-1)

        // issue tile t0+1 into buf[nxt]
        if (t0 < 48) {
            int jg = t0 * 16 + st_j;           // tile t0+1 covers window keys t0*16..t0*16+15
            int kpos = c * WIN + jg - WIN;
            bool valid = (kpos >= 0 && kpos < S);
            const __half* src = st_hs ? v : k;
            void* dst = st_hs ? (void*)&Vs[nxt][st_j][st_ch] : (void*)&Ks[nxt][st_j][st_ch];
            cp_async16z(dst, src + (size_t)(valid ? kpos : 0) * DM + hoff + st_ch, valid ? 16 : 0);
        }
        asm volatile("cp.async.commit_group;" ::);

        // K b-frags from buf[cur]
        uint32_t kf[4][4];
#pragma unroll
        for (int kt = 0; kt < 4; kt++) {
            uint32_t addr = (uint32_t)__cvta_generic_to_shared(
                &Ks[cur][lane & 15][kt * 16 + (lane >> 4) * 8]);
            asm volatile("ldmatrix.sync.aligned.m8n8.x4.shared.b16 {%0,%1,%2,%3}, [%4];"
                         : "=r"(kf[kt][0]), "=r"(kf[kt][1]), "=r"(kf[kt][2]), "=r"(kf[kt][3])
                         : "r"(addr));
        }

        float sc[2][4];
#pragma unroll
        for (int ni = 0; ni < 2; ni++)
#pragma unroll
            for (int r = 0; r < 4; r++) sc[ni][r] = 0.f;
#pragma unroll
        for (int kt = 0; kt < 4; kt++) {
            asm volatile(
                "mma.sync.aligned.m16n8k16.row.col.f32.f16.f16.f32 "
                "{%0,%1,%2,%3}, {%4,%5,%6,%7}, {%8,%9}, {%0,%1,%2,%3};"
                : "+f"(sc[0][0]), "+f"(sc[0][1]), "+f"(sc[0][2]), "+f"(sc[0][3])
                : "r"(qf[kt][0]), "r"(qf[kt][1]), "r"(qf[kt][2]), "r"(qf[kt][3]),
                  "r"(kf[kt][0]), "r"(kf[kt][2]));
            asm volatile(
                "mma.sync.aligned.m16n8k16.row.col.f32.f16.f16.f32 "
                "{%0,%1,%2,%3}, {%4,%5,%6,%7}, {%8,%9}, {%0,%1,%2,%3};"
                : "+f"(sc[1][0]), "+f"(sc[1][1]), "+f"(sc[1][2]), "+f"(sc[1][3])
                : "r"(qf[kt][0]), "r"(qf[kt][1]), "r"(qf[kt][2]), "r"(qf[kt][3]),
                  "r"(kf[kt][1]), "r"(kf[kt][3]));
        }

        // mask + online softmax + P a-frags
        uint32_t pa[4];
#pragma unroll
        for (int h = 0; h < 2; h++) {
            int qi = half * 128 + warp * 16 + (lane >> 2) + h * 8;
            float s0 = sc[0][2 * h], s1 = sc[0][2 * h + 1];
            float s2 = sc[1][2 * h], s3 = sc[1][2 * h + 1];
            int j0 = (lane & 3) * 2;
#pragma unroll
            for (int e = 0; e < 4; e++) {
                int jj = (e >> 1) * 8 + j0 + (e & 1);
                bool valid;
                if (t0 == 0) valid = (jj < 8);
                else {
                    int jg = (t0 - 1) * 16 + jj;
                    int kp = c * WIN + jg - WIN;
                    valid = (jg >= qi) && (jg <= qi + 2 * WIN) && (kp >= 0) && (kp < S);
                }
                float* sp = (e == 0) ? &s0 : (e == 1) ? &s1 : (e == 2) ? &s2 : &s3;
                if (!valid) *sp = -1e30f;
            }
            float rmax = fmaxf(fmaxf(s0, s1), fmaxf(s2, s3));
            rmax = fmaxf(rmax, __shfl_xor_sync(0xffffffffu, rmax, 1));
            rmax = fmaxf(rmax, __shfl_xor_sync(0xffffffffu, rmax, 2));
            float mnew = fmaxf(mrow[h], rmax);
            float scale = __expf(mrow[h] - mnew);
            float p0 = __expf(s0 - mnew), p1 = __expf(s1 - mnew);
            float p2 = __expf(s2 - mnew), p3 = __expf(s3 - mnew);
            float ls = p0 + p1 + p2 + p3;
            ls += __shfl_xor_sync(0xffffffffu, ls, 1);
            ls += __shfl_xor_sync(0xffffffffu, ls, 2);
            lrow[h] = lrow[h] * scale + ls;
            mrow[h] = mnew;
#pragma unroll
            for (int n8 = 0; n8 < 8; n8++) {
                acc[n8][2 * h]     *= scale;
                acc[n8][2 * h + 1] *= scale;
            }
            pa[h]     = pack_h2(p0, p1);
            pa[h + 2] = pack_h2(p2, p3);
        }

        // V b-frags + AV MMAs ({r0,r1} low-n, {r2,r3} high-n)
#pragma unroll
        for (int nb = 0; nb < 4; nb++) {
            uint32_t addr = (uint32_t)__cvta_generic_to_shared(
                &Vs[cur][lane & 15][nb * 16 + (lane >> 4) * 8]);
            uint32_t r0, r1, r2, r3;
            asm volatile("ldmatrix.sync.aligned.m8n8.x4.trans.shared.b16 {%0,%1,%2,%3}, [%4];"
                         : "=r"(r0), "=r"(r1), "=r"(r2), "=r"(r3)
                         : "r"(addr));
            asm volatile(
                "mma.sync.aligned.m16n8k16.row.col.f32.f16.f16.f32 "
                "{%0,%1,%2,%3}, {%4,%5,%6,%7}, {%8,%9}, {%0,%1,%2,%3};"
                : "+f"(acc[nb*2][0]), "+f"(acc[nb*2][1]), "+f"(acc[nb*2][2]), "+f"(acc[nb*2][3])
                : "r"(pa[0]), "r"(pa[1]), "r"(pa[2]), "r"(pa[3]),
                  "r"(r0), "r"(r1));
            asm volatile(
                "mma.sync.aligned.m16n8k16.row.col.f32.f16.f16.f32 "
                "{%0,%1,%2,%3}, {%4,%5,%6,%7}, {%8,%9}, {%0,%1,%2,%3};"
                : "+f"(acc[nb*2+1][0]), "+f"(acc[nb*2+1][1]), "+f"(acc[nb*2+1][2]), "+f"(acc[nb*2+1][3])
                : "r"(pa[0]), "r"(pa[1]), "r"(pa[2]), "r"(pa[3]),
                  "r"(r2), "r"(r3));
        }
    }

    // epilogue
#pragma unroll
    for (int h = 0; h < 2; h++) {
        float inv = 1.f / lrow[h];
        int row = warp * 16 + (lane >> 2) + h * 8;
        size_t base = (size_t)(qbase + row) * DM + hoff;
#pragma unroll
        for (int n8 = 0; n8 < 8; n8++) {
            int dim = n8 * 8 + (lane & 3) * 2;
            *(uint32_t*)&out[base + dim] =
                pack_h2(acc[n8][2 * h] * inv, acc[n8][2 * h + 1] * inv);
        }
    }
}

// ---------------- global-token full attention (qg fused, fp16 kg/vg) ----------------
__global__ void global_attn_kernel(const float* __restrict__ h, const float* __restrict__ Wqg,
                                   const float* __restrict__ bqg,
                                   const __half* __restrict__ kg, const __half* __restrict__ vg,
                                   __half* __restrict__ out)
{
    int g = blockIdx.x, hh = blockIdx.y;
    int hoff = hh * HD;
    int tid = threadIdx.x;
    __shared__ float qs[HD];
    __shared__ float sc[S];
    __shared__ float red[256];

    // fused qg projection
    {
        int d = tid & 63, part = tid >> 6;
        const float* hr = h + (size_t)(g * 512) * DM;
        float a = 0.f;
        for (int kk = part * 192; kk < (part + 1) * 192; kk++)
            a += hr[kk] * Wqg[(size_t)kk * DM + hoff + d];
        red[tid] = a; __syncthreads();
        if (tid < 64)
            qs[tid] = (red[tid] + red[tid + 64] + red[tid + 128] + red[tid + 192]
                       + bqg[hoff + tid]) * SCALE;
        __syncthreads();
    }

    float lmax = -1e30f;
    for (int i = 0; i < 16; i++) {
        int s = i * 256 + tid;
        const __half2* kr = (const __half2*)(kg + (size_t)s * DM + hoff);
        float a = 0.f;
#pragma unroll
        for (int d2 = 0; d2 < 32; d2++) {
            float2 f = __half22float2(kr[d2]);
            a += qs[d2 * 2] * f.x + qs[d2 * 2 + 1] * f.y;
        }
        sc[s] = a;
        lmax = fmaxf(lmax, a);
    }
    red[tid] = lmax; __syncthreads();
    for (int o = 128; o > 0; o >>= 1) { if (tid < o) red[tid] = fmaxf(red[tid], red[tid + o]); __syncthreads(); }
    float mx = red[0]; __syncthreads();

    float lsum = 0.f;
    for (int i = 0; i < 16; i++) {
        int s = i * 256 + tid;
        float p = __expf(sc[s] - mx);
        sc[s] = p;
        lsum += p;
    }
    red[tid] = lsum; __syncthreads();
    for (int o = 128; o > 0; o >>= 1) { if (tid < o) red[tid] += red[tid + o]; __syncthreads(); }
    float inv = 1.f / red[0]; __syncthreads();

    int d = tid & 63;
    int part = tid >> 6;
    float a = 0.f;
    for (int s = part * 1024; s < (part + 1) * 1024; s++)
        a += sc[s] * __half2float(vg[(size_t)s * DM + hoff + d]);
    red[tid] = a; __syncthreads();
    if (tid < 64) {
        float r = red[tid] + red[tid + 64] + red[tid + 128] + red[tid + 192];
        out[(size_t)(g * 512) * DM + hoff + d] = __float2half(r * inv);
    }
}

// ---------------- output head ----------------
__global__ void head_kernel(const float* __restrict__ h, const float* __restrict__ Wout,
                            const float* __restrict__ bout, float* __restrict__ out)
{
    int g = blockIdx.x;
    int o = threadIdx.x;
    const float* hr = h + (size_t)(g * 512) * DM;
    float a = bout[o];
    for (int d = 0; d < DM; d++) a += hr[d] * Wout[(size_t)d * OUTD + o];
    out[g * OUTD + o] = a;
}

// ---------------- driver ----------------
extern "C" void kernel_launch(void* const* d_in, const int* in_sizes, int n_in,
                              void* d_out, int out_size)
{
    (void)in_sizes; (void)n_in; (void)out_size;
    const int*   x        = (const int*)  d_in[0];
    const float* word_emb = (const float*)d_in[1];
    const float* pos_emb  = (const float*)d_in[2];
    const float* emb_ln_s = (const float*)d_in[3];
    const float* emb_ln_b = (const float*)d_in[4];
    const float* Wq  = (const float*)d_in[5];   const float* bq  = (const float*)d_in[6];
    const float* Wk  = (const float*)d_in[7];   const float* bk  = (const float*)d_in[8];
    const float* Wv  = (const float*)d_in[9];   const float* bv  = (const float*)d_in[10];
    const float* Wo  = (const float*)d_in[11];  const float* bo  = (const float*)d_in[12];
    const float* Wqg = (const float*)d_in[13];  const float* bqg = (const float*)d_in[14];
    const float* Wkg = (const float*)d_in[15];  const float* bkg = (const float*)d_in[16];
    const float* Wvg = (const float*)d_in[17];  const float* bvg = (const float*)d_in[18];
    const float* ln1s= (const float*)d_in[19];  const float* ln1b= (const float*)d_in[20];
    const float* W1  = (const float*)d_in[21];  const float* b1  = (const float*)d_in[22];
    const float* W2  = (const float*)d_in[23];  const float* b2  = (const float*)d_in[24];
    const float* ln2s= (const float*)d_in[25];  const float* ln2b= (const float*)d_in[26];
    const float* Wout= (const float*)d_in[27];  const float* bout= (const float*)d_in[28];
    float* out = (float*)d_out;

    float *h, *y;
    __half *h16, *q16, *k16, *v16, *kg16, *vg16, *attn16, *ffn16;
    cudaGetSymbolAddress((void**)&h,    g_h);
    cudaGetSymbolAddress((void**)&y,    g_y);
    cudaGetSymbolAddress((void**)&h16,    g_h16);
    cudaGetSymbolAddress((void**)&q16,    g_q16);
    cudaGetSymbolAddress((void**)&k16,    g_k16);
    cudaGetSymbolAddress((void**)&v16,    g_v16);
    cudaGetSymbolAddress((void**)&kg16,   g_kg16);
    cudaGetSymbolAddress((void**)&vg16,   g_vg16);
    cudaGetSymbolAddress((void**)&attn16, g_attn16);
    cudaGetSymbolAddress((void**)&ffn16,  g_ffn16);

    __half *hWq, *hWk, *hWv, *hWo, *hWkg, *hWvg, *hW1, *hW2;
    cudaGetSymbolAddress((void**)&hWq,  g_hWq);
    cudaGetSymbolAddress((void**)&hWk,  g_hWk);
    cudaGetSymbolAddress((void**)&hWv,  g_hWv);
    cudaGetSymbolAddress((void**)&hWo,  g_hWo);
    cudaGetSymbolAddress((void**)&hWkg, g_hWkg);
    cudaGetSymbolAddress((void**)&hWvg, g_hWvg);
    cudaGetSymbolAddress((void**)&hW1,  g_hW1);
    cudaGetSymbolAddress((void**)&hW2,  g_hW2);

    cudaFuncSetAttribute(hgemm_kernel, cudaFuncAttributeMaxDynamicSharedMemorySize, TGEMM_SMEM);

    const int nP4 = LNUM * DM * DM / 4;
    const int nF4 = LNUM * DM * FF / 4;
    // launch 1: all 6 projection weights
    dim3 g6(512, 1, 6);
    f2h_kernel6<<<g6, 256>>>((const float4*)Wq, (const float4*)Wk, (const float4*)Wv,
                             (const float4*)Wo, (const float4*)Wkg, (const float4*)Wvg,
                             (uint2*)hWq, (uint2*)hWk, (uint2*)hWv,
                             (uint2*)hWo, (uint2*)hWkg, (uint2*)hWvg, nP4);
    // launches 2-3: FFN weights
    f2h_kernel<<<2048, 256>>>((const float4*)W1, (uint2*)hW1, nF4);
    f2h_kernel<<<2048, 256>>>((const float4*)W2, (uint2*)hW2, nF4);
    // launch 4: embed; launch 5 (ncu target): first grid5 hgemm
    embed_kernel<<<S, 256>>>(x, word_emb, pos_emb, emb_ln_s, emb_ln_b, h, h16);

    dim3 grid5  (DM / 128, S / 128, 5);
    dim3 gridP  (DM / 128, S / 128, 1);
    dim3 gridF1 (FF / 128, S / 128, 1);
    dim3 gridF2 (DM / 128, S / 128, 1);
    dim3 gridAtt(2 * CCH, HNUM);
    dim3 gridGA (NW, HNUM);

    for (int l = 0; l < LNUM; l++) {
        size_t wO  = (size_t)l * DM * DM;
        size_t bO  = (size_t)l * DM;
        size_t w1O = (size_t)l * DM * FF;
        size_t b1O = (size_t)l * FF;
        size_t w2O = (size_t)l * FF * DM;

        hgemm_kernel<<<grid5, 256, TGEMM_SMEM>>>(h16,
            hWq + wO, hWk + wO, hWv + wO, hWkg + wO, hWvg + wO,
            bq + bO, bk + bO, bv + bO, bkg + bO, bvg + bO,
            q16, k16, v16, kg16, vg16,
            S, DM, DM, SCALE, 0, 0b11111);
        local_attn_mma<<<gridAtt, 256>>>(q16, k16, v16, attn16);
        global_attn_kernel<<<gridGA, 256>>>(h, Wqg + wO, bqg + bO, kg16, vg16, attn16);

        hgemm_kernel<<<gridP, 256, TGEMM_SMEM>>>(attn16,
            hWo + wO, hWo + wO, hWo + wO, hWo + wO, hWo + wO,
            bo + bO, bo + bO, bo + bO, bo + bO, bo + bO,
            y, y, y, y, y,
            S, DM, DM, 1.0f, 0, 0);
        add_ln_kernel<<<S, 256>>>(h, y, ln1s + bO, ln1b + bO, h, h16);

        hgemm_kernel<<<gridF1, 256, TGEMM_SMEM>>>(h16,
            hW1 + w1O, hW1 + w1O, hW1 + w1O, hW1 + w1O, hW1 + w1O,
            b1 + b1O, b1 + b1O, b1 + b1O, b1 + b1O, b1 + b1O,
            ffn16, ffn16, ffn16, ffn16, ffn16,
            S, FF, DM, 1.0f, 1, 0b11111);
        hgemm_kernel<<<gridF2, 256, TGEMM_SMEM>>>(ffn16,
            hW2 + w2O, hW2 + w2O, hW2 + w2O, hW2 + w2O, hW2 + w2O,
            b2 + bO, b2 + bO, b2 + bO, b2 + bO, b2 + bO,
            y, y, y, y, y,
            S, DM, FF, 1.0f, 0, 0);
        add_ln_kernel<<<S, 256>>>(h, y, ln2s + bO, ln2b + bO, h, h16);
    }

    head_kernel<<<NW, 128>>>(h, Wout, bout, out);
}

// round 14
// speedup vs baseline: 3.7245x; 1.0410x over previous
#include <cuda_runtime.h>
#include <cuda_fp16.h>
#include <math.h>
#include <stdint.h>

// ---------------- problem constants ----------------
#define S     4096
#define DM    768
#define FF    3072
#define HNUM  12
#define HD    64
#define WIN   256
#define CCH   16
#define NW    8
#define LNUM  12
#define OUTD  128
#define SCALE 0.125f

// ---------------- scratch ----------------
__device__ float g_h    [S*DM];
__device__ float g_y    [S*DM];
__device__ __half g_h16   [S*DM];
__device__ __half g_q16   [S*DM];
__device__ __half g_k16   [S*DM];
__device__ __half g_v16   [S*DM];
__device__ __half g_kg16  [S*DM];
__device__ __half g_vg16  [S*DM];
__device__ __half g_attn16[S*DM];
__device__ __half g_ffn16 [S*FF];

// fp16 weight copies
__device__ __half g_hWq [LNUM*DM*DM];
__device__ __half g_hWk [LNUM*DM*DM];
__device__ __half g_hWv [LNUM*DM*DM];
__device__ __half g_hWo [LNUM*DM*DM];
__device__ __half g_hWkg[LNUM*DM*DM];
__device__ __half g_hWvg[LNUM*DM*DM];
__device__ __half g_hW1 [LNUM*DM*FF];
__device__ __half g_hW2 [LNUM*FF*DM];

// ---------------- helpers ----------------
__device__ __forceinline__ float gelu_f(float x) {
    float x3 = x * x * x;
    return 0.5f * x * (1.0f + tanhf(0.7978845608028654f * (x + 0.044715f * x3)));
}

__device__ __forceinline__ unsigned pack_h2(float a, float b) {
    __half2 p = __float22half2_rn(make_float2(a, b));
    return *reinterpret_cast<unsigned*>(&p);
}

__device__ __forceinline__ void cp_async16(void* smem_dst, const void* gmem_src) {
    uint32_t dst = (uint32_t)__cvta_generic_to_shared(smem_dst);
    asm volatile("cp.async.ca.shared.global [%0], [%1], 16;" :: "r"(dst), "l"(gmem_src));
}

__device__ __forceinline__ void cp_async16z(void* smem_dst, const void* gmem_src, int src_sz) {
    uint32_t dst = (uint32_t)__cvta_generic_to_shared(smem_dst);
    asm volatile("cp.async.ca.shared.global [%0], [%1], 16, %2;"
                 :: "r"(dst), "l"(gmem_src), "r"(src_sz));
}

// ---------------- fp32 -> fp16 conversion, batched over z ----------------
__global__ void f2h_kernel6(const float4* in0, const float4* in1, const float4* in2,
                            const float4* in3, const float4* in4, const float4* in5,
                            uint2* out0, uint2* out1, uint2* out2,
                            uint2* out3, uint2* out4, uint2* out5, int n4)
{
    int z = blockIdx.z;
    const float4* in = (z == 0) ? in0 : (z == 1) ? in1 : (z == 2) ? in2 :
                       (z == 3) ? in3 : (z == 4) ? in4 : in5;
    uint2* out = (z == 0) ? out0 : (z == 1) ? out1 : (z == 2) ? out2 :
                 (z == 3) ? out3 : (z == 4) ? out4 : out5;
    for (int i = blockIdx.x * blockDim.x + threadIdx.x; i < n4; i += gridDim.x * blockDim.x) {
        float4 v = in[i];
        uint2 o;
        o.x = pack_h2(v.x, v.y);
        o.y = pack_h2(v.z, v.w);
        out[i] = o;
    }
}

__global__ void f2h_kernel(const float4* __restrict__ in, uint2* __restrict__ out, int n4)
{
    for (int i = blockIdx.x * blockDim.x + threadIdx.x; i < n4; i += gridDim.x * blockDim.x) {
        float4 v = in[i];
        uint2 o;
        o.x = pack_h2(v.x, v.y);
        o.y = pack_h2(v.z, v.w);
        out[i] = o;
    }
}

// ---------------- LN core: 192 threads, float4, single-pass sum/sumsq ----------------
__device__ __forceinline__ void ln_write(float4 v, const float4* __restrict__ ls4,
                                         const float4* __restrict__ lb4,
                                         float4* __restrict__ o, uint2* __restrict__ o16,
                                         size_t idx, int t)
{
    const int warp = t >> 5, lane = t & 31;
    __shared__ float ss[6], ss2[6];
    float sum = v.x + v.y + v.z + v.w;
    float sq  = v.x * v.x + v.y * v.y + v.z * v.z + v.w * v.w;
#pragma unroll
    for (int o_ = 16; o_ > 0; o_ >>= 1) {
        sum += __shfl_xor_sync(0xffffffffu, sum, o_);
        sq  += __shfl_xor_sync(0xffffffffu, sq,  o_);
    }
    if (lane == 0) { ss[warp] = sum; ss2[warp] = sq; }
    __syncthreads();
    float tot  = ss[0] + ss[1] + ss[2] + ss[3] + ss[4] + ss[5];
    float tot2 = ss2[0] + ss2[1] + ss2[2] + ss2[3] + ss2[4] + ss2[5];
    float mean = tot * (1.f / (float)DM);
    float var  = tot2 * (1.f / (float)DM) - mean * mean;
    float rstd = rsqrtf(var + 1e-5f);
    float4 lsv = ls4[t], lbv = lb4[t];
    float4 ov;
    ov.x = (v.x - mean) * rstd * lsv.x + lbv.x;
    ov.y = (v.y - mean) * rstd * lsv.y + lbv.y;
    ov.z = (v.z - mean) * rstd * lsv.z + lbv.z;
    ov.w = (v.w - mean) * rstd * lsv.w + lbv.w;
    o[idx] = ov;
    uint2 pk;
    pk.x = pack_h2(ov.x, ov.y);
    pk.y = pack_h2(ov.z, ov.w);
    o16[idx] = pk;
}

// ---------------- embedding + LN (192 threads/row) ----------------
__global__ void embed_kernel(const int* __restrict__ x, const float4* __restrict__ we,
                             const float4* __restrict__ pe, const float4* __restrict__ ls,
                             const float4* __restrict__ lb, float4* __restrict__ h,
                             uint2* __restrict__ h16)
{
    int s = blockIdx.x;
    int t = threadIdx.x;             // 0..191
    int r = s & 511, w = s >> 9;
    int id = (r == 0) ? 0 : x[w * 511 + r - 1];
    float4 a = we[(size_t)id * 192 + t];
    float4 b = pe[(size_t)s * 192 + t];
    float4 v = make_float4(a.x + b.x, a.y + b.y, a.z + b.z, a.w + b.w);
    ln_write(v, ls, lb, h, h16, (size_t)s * 192 + t, t);
}

// ---------------- residual add + LN (192 threads/row) ----------------
__global__ void add_ln_kernel(const float4* __restrict__ x, const float4* __restrict__ y,
                              const float4* __restrict__ ls, const float4* __restrict__ lb,
                              float4* __restrict__ o, uint2* __restrict__ o16)
{
    int s = blockIdx.x;
    int t = threadIdx.x;
    size_t idx = (size_t)s * 192 + t;
    float4 a = x[idx], b = y[idx];
    float4 v = make_float4(a.x + b.x, a.y + b.y, a.z + b.z, a.w + b.w);
    ln_write(v, ls, lb, o, o16, idx, t);
}

// ---------------- fp16 tensor-core GEMM, cp.async 2-stage, batched over z (up to 5) ----------------
#define AS_H    9216
#define STG_H   17920
#define TGEMM_SMEM (2 * STG_H * 2)

__global__ __launch_bounds__(256, 2)
void hgemm_kernel(const __half* __restrict__ A,
                  const __half* B0, const __half* B1, const __half* B2,
                  const __half* B3, const __half* B4,
                  const float* bias0, const float* bias1, const float* bias2,
                  const float* bias3, const float* bias4,
                  void* C0, void* C1, void* C2, void* C3, void* C4,
                  int M, int N, int K,
                  float al0, int act, int outHalfMask)
{
    extern __shared__ __half sm[];

    const int z = blockIdx.z;
    const __half* B = (z == 0) ? B0 : (z == 1) ? B1 : (z == 2) ? B2 : (z == 3) ? B3 : B4;
    const float* bias = (z == 0) ? bias0 : (z == 1) ? bias1 : (z == 2) ? bias2 : (z == 3) ? bias3 : bias4;
    void* C = (z == 0) ? C0 : (z == 1) ? C1 : (z == 2) ? C2 : (z == 3) ? C3 : C4;
    const float alpha = (z == 0) ? al0 : 1.0f;
    const int outHalf = (outHalfMask >> z) & 1;

    const int tid  = threadIdx.x;
    const int lane = tid & 31;
    const int warp = tid >> 5;
    const int wm = warp >> 2;
    const int wn = warp & 3;

    const int bRow = blockIdx.y * 128;
    const int bCol = blockIdx.x * 128;

    float acc[4][4][4];
#pragma unroll
    for (int i = 0; i < 4; i++)
#pragma unroll
        for (int j = 0; j < 4; j++)
#pragma unroll
            for (int r = 0; r < 4; r++) acc[i][j][r] = 0.f;

    const int nk = K >> 6;

    {
        __half* as = sm;
        __half* bs = sm + AS_H;
#pragma unroll
        for (int p = 0; p < 4; p++) {
            int id = p * 256 + tid;
            int r = id >> 3, c = (id & 7) * 8;
            cp_async16(as + r * 72 + c, A + (size_t)(bRow + r) * K + c);
        }
#pragma unroll
        for (int p = 0; p < 4; p++) {
            int id = p * 256 + tid;
            int r = id >> 4, c = (id & 15) * 8;
            cp_async16(bs + r * 136 + c, B + (size_t)r * N + bCol + c);
        }
        asm volatile("cp.async.commit_group;" ::);
    }

    for (int kt = 0; kt < nk; kt++) {
        asm volatile("cp.async.wait_group 0;" ::);
        __syncthreads();

        if (kt + 1 < nk) {
            const int k0 = (kt + 1) << 6;
            __half* as = sm + ((kt + 1) & 1) * STG_H;
            __half* bs = as + AS_H;
#pragma unroll
            for (int p = 0; p < 4; p++) {
                int id = p * 256 + tid;
                int r = id >> 3, c = (id & 7) * 8;
                cp_async16(as + r * 72 + c, A + (size_t)(bRow + r) * K + k0 + c);
            }
#pragma unroll
            for (int p = 0; p < 4; p++) {
                int id = p * 256 + tid;
                int r = id >> 4, c = (id & 15) * 8;
                cp_async16(bs + r * 136 + c, B + (size_t)(k0 + r) * N + bCol + c);
            }
            asm volatile("cp.async.commit_group;" ::);
        }

        const __half* as = sm + (kt & 1) * STG_H;
        const __half* bs = as + AS_H;
#pragma unroll
        for (int kk = 0; kk < 64; kk += 16) {
            uint32_t af[4][4];
#pragma unroll
            for (int mi = 0; mi < 4; mi++) {
                uint32_t addr = (uint32_t)__cvta_generic_to_shared(
                    as + (wm * 64 + mi * 16 + (lane & 15)) * 72 + kk + (lane >> 4) * 8);
                asm volatile("ldmatrix.sync.aligned.m8n8.x4.shared.b16 {%0,%1,%2,%3}, [%4];"
                             : "=r"(af[mi][0]), "=r"(af[mi][1]), "=r"(af[mi][2]), "=r"(af[mi][3])
                             : "r"(addr));
            }
            uint32_t bfr[4][2];
#pragma unroll
            for (int nb = 0; nb < 2; nb++) {
                uint32_t addr = (uint32_t)__cvta_generic_to_shared(
                    bs + (kk + (lane & 15)) * 136 + wn * 32 + nb * 16 + (lane >> 4) * 8);
                uint32_t r0, r1, r2, r3;
                asm volatile("ldmatrix.sync.aligned.m8n8.x4.trans.shared.b16 {%0,%1,%2,%3}, [%4];"
                             : "=r"(r0), "=r"(r1), "=r"(r2), "=r"(r3)
                             : "r"(addr));
                bfr[nb * 2][0] = r0; bfr[nb * 2][1] = r1;
                bfr[nb * 2 + 1][0] = r2; bfr[nb * 2 + 1][1] = r3;
            }
#pragma unroll
            for (int mi = 0; mi < 4; mi++)
#pragma unroll
                for (int ni = 0; ni < 4; ni++) {
                    asm volatile(
                        "mma.sync.aligned.m16n8k16.row.col.f32.f16.f16.f32 "
                        "{%0,%1,%2,%3}, {%4,%5,%6,%7}, {%8,%9}, {%0,%1,%2,%3};"
                        : "+f"(acc[mi][ni][0]), "+f"(acc[mi][ni][1]),
                          "+f"(acc[mi][ni][2]), "+f"(acc[mi][ni][3])
                        : "r"(af[mi][0]), "r"(af[mi][1]), "r"(af[mi][2]), "r"(af[mi][3]),
                          "r"(bfr[ni][0]), "r"(bfr[ni][1]));
                }
        }
        __syncthreads();
    }

#pragma unroll
    for (int mi = 0; mi < 4; mi++) {
        int row0 = bRow + wm * 64 + mi * 16 + (lane >> 2);
#pragma unroll
        for (int ni = 0; ni < 4; ni++) {
            int col = bCol + wn * 32 + ni * 8 + (lane & 3) * 2;
            float b0 = bias[col], b1 = bias[col + 1];
            float v0 = (acc[mi][ni][0] + b0) * alpha;
            float v1 = (acc[mi][ni][1] + b1) * alpha;
            float v2 = (acc[mi][ni][2] + b0) * alpha;
            float v3 = (acc[mi][ni][3] + b1) * alpha;
            if (act == 1) { v0 = gelu_f(v0); v1 = gelu_f(v1); v2 = gelu_f(v2); v3 = gelu_f(v3); }
            if (outHalf) {
                __half* Ch = (__half*)C;
                *(uint32_t*)&Ch[(size_t)row0 * N + col]       = pack_h2(v0, v1);
                *(uint32_t*)&Ch[(size_t)(row0 + 8) * N + col] = pack_h2(v2, v3);
            } else {
                float* Cf = (float*)C;
                *(float2*)&Cf[(size_t)row0 * N + col]       = make_float2(v0, v1);
                *(float2*)&Cf[(size_t)(row0 + 8) * N + col] = make_float2(v2, v3);
            }
        }
    }
}

// ---------------- local attention (flash-style), 128 queries/block, 32-key tiles ----------------
__global__ __launch_bounds__(256)
void local_attn_mma(const __half* __restrict__ q, const __half* __restrict__ k,
                    const __half* __restrict__ v, __half* __restrict__ out)
{
    const int bx = blockIdx.x;
    const int c = bx >> 1, half = bx & 1;
    const int hh = blockIdx.y;
    const int tid = threadIdx.x;
    const int lane = tid & 31, warp = tid >> 5;
    const int hoff = hh * HD;
    const int qbase = c * WIN + half * 128;

    __shared__ __align__(16) __half Qs[128][72];
    __shared__ __align__(16) __half Ks[2][32][72];
    __shared__ __align__(16) __half Vs[2][32][72];

    const int st_hs = tid >> 7;            // 0: K, 1: V
    const int st_j  = (tid & 127) >> 3;    // key row 0..15 (also covers +16)
    const int st_ch = (tid & 7) * 8;       // dim chunk

    // stage Q[128][64]
    for (int i = tid; i < 1024; i += 256) {
        int row = i >> 3, ch = (i & 7) * 8;
        *(uint4*)&Qs[row][ch] = *(const uint4*)&q[(size_t)(qbase + row) * DM + hoff + ch];
    }

    // prologue: tile 0 (global keys; rows 0..7 valid, rest zero) into buf 0
    {
        const __half* src = st_hs ? v : k;
#pragma unroll
        for (int rr = 0; rr < 2; rr++) {
            int row = st_j + rr * 16;
            bool valid = (row < 8);
            int kpos = valid ? row * 512 : 0;
            void* dst = st_hs ? (void*)&Vs[0][row][st_ch] : (void*)&Ks[0][row][st_ch];
            cp_async16z(dst, src + (size_t)kpos * DM + hoff + st_ch, valid ? 16 : 0);
        }
        asm volatile("cp.async.commit_group;" ::);
    }
    __syncthreads();

    // Q a-frags
    uint32_t qf[4][4];
#pragma unroll
    for (int kt = 0; kt < 4; kt++) {
        uint32_t addr = (uint32_t)__cvta_generic_to_shared(
            &Qs[warp * 16 + (lane & 15)][kt * 16 + (lane >> 4) * 8]);
        asm volatile("ldmatrix.sync.aligned.m8n8.x4.shared.b16 {%0,%1,%2,%3}, [%4];"
                     : "=r"(qf[kt][0]), "=r"(qf[kt][1]), "=r"(qf[kt][2]), "=r"(qf[kt][3])
                     : "r"(addr));
    }

    float mrow[2] = { -1e30f, -1e30f }, lrow[2] = { 0.f, 0.f };
    float acc[8][4];
#pragma unroll
    for (int n8 = 0; n8 < 8; n8++)
#pragma unroll
        for (int r = 0; r < 4; r++) acc[n8][r] = 0.f;

    // tiles: 0 = global (32-wide, 8 valid), 1..24 = window keys (t0-1)*32..+31
    for (int t0 = 0; t0 <= 24; t0++) {
        const int cur = t0 & 1, nxt = cur ^ 1;

        asm volatile("cp.async.wait_group 0;" ::);
        __syncthreads();

        // prefetch tile t0+1 into buf[nxt]
        if (t0 < 24) {
            const __half* src = st_hs ? v : k;
#pragma unroll
            for (int rr = 0; rr < 2; rr++) {
                int row = st_j + rr * 16;
                int jg = t0 * 32 + row;
                int kpos = c * WIN + jg - WIN;
                bool valid = (kpos >= 0 && kpos < S);
                void* dst = st_hs ? (void*)&Vs[nxt][row][st_ch] : (void*)&Ks[nxt][row][st_ch];
                cp_async16z(dst, src + (size_t)(valid ? kpos : 0) * DM + hoff + st_ch,
                            valid ? 16 : 0);
            }
        }
        asm volatile("cp.async.commit_group;" ::);

        // scores: 4 n8-blocks over 32 keys
        float sc[4][4];
#pragma unroll
        for (int nb = 0; nb < 4; nb++)
#pragma unroll
            for (int r = 0; r < 4; r++) sc[nb][r] = 0.f;
#pragma unroll
        for (int g = 0; g < 2; g++) {
            uint32_t kf[4][4];
#pragma unroll
            for (int kt = 0; kt < 4; kt++) {
                uint32_t addr = (uint32_t)__cvta_generic_to_shared(
                    &Ks[cur][g * 16 + (lane & 15)][kt * 16 + (lane >> 4) * 8]);
                asm volatile("ldmatrix.sync.aligned.m8n8.x4.shared.b16 {%0,%1,%2,%3}, [%4];"
                             : "=r"(kf[kt][0]), "=r"(kf[kt][1]), "=r"(kf[kt][2]), "=r"(kf[kt][3])
                             : "r"(addr));
            }
#pragma unroll
            for (int kt = 0; kt < 4; kt++) {
                asm volatile(
                    "mma.sync.aligned.m16n8k16.row.col.f32.f16.f16.f32 "
                    "{%0,%1,%2,%3}, {%4,%5,%6,%7}, {%8,%9}, {%0,%1,%2,%3};"
                    : "+f"(sc[g*2][0]), "+f"(sc[g*2][1]), "+f"(sc[g*2][2]), "+f"(sc[g*2][3])
                    : "r"(qf[kt][0]), "r"(qf[kt][1]), "r"(qf[kt][2]), "r"(qf[kt][3]),
                      "r"(kf[kt][0]), "r"(kf[kt][2]));
                asm volatile(
                    "mma.sync.aligned.m16n8k16.row.col.f32.f16.f16.f32 "
                    "{%0,%1,%2,%3}, {%4,%5,%6,%7}, {%8,%9}, {%0,%1,%2,%3};"
                    : "+f"(sc[g*2+1][0]), "+f"(sc[g*2+1][1]), "+f"(sc[g*2+1][2]), "+f"(sc[g*2+1][3])
                    : "r"(qf[kt][0]), "r"(qf[kt][1]), "r"(qf[kt][2]), "r"(qf[kt][3]),
                      "r"(kf[kt][1]), "r"(kf[kt][3]));
            }
        }

        // mask + online softmax + P a-frags (2 k-steps)
        uint32_t pa[2][4];
#pragma unroll
        for (int h = 0; h < 2; h++) {
            int qi = half * 128 + warp * 16 + (lane >> 2) + h * 8;
            int j0 = (lane & 3) * 2;
            float sv[8];
#pragma unroll
            for (int nb = 0; nb < 4; nb++) {
                sv[nb * 2]     = sc[nb][2 * h];
                sv[nb * 2 + 1] = sc[nb][2 * h + 1];
            }
#pragma unroll
            for (int e = 0; e < 8; e++) {
                int jj = (e >> 1) * 8 + j0 + (e & 1);
                bool valid;
                if (t0 == 0) valid = (jj < 8);
                else {
                    int jg = (t0 - 1) * 32 + jj;
                    int kp = c * WIN + jg - WIN;
                    valid = (jg >= qi) && (jg <= qi + 2 * WIN) && (kp >= 0) && (kp < S);
                }
                if (!valid) sv[e] = -1e30f;
            }
            float rmax = sv[0];
#pragma unroll
            for (int e = 1; e < 8; e++) rmax = fmaxf(rmax, sv[e]);
            rmax = fmaxf(rmax, __shfl_xor_sync(0xffffffffu, rmax, 1));
            rmax = fmaxf(rmax, __shfl_xor_sync(0xffffffffu, rmax, 2));
            float mnew = fmaxf(mrow[h], rmax);
            float scale = __expf(mrow[h] - mnew);
            float p[8], ls = 0.f;
#pragma unroll
            for (int e = 0; e < 8; e++) { p[e] = __expf(sv[e] - mnew); ls += p[e]; }
            ls += __shfl_xor_sync(0xffffffffu, ls, 1);
            ls += __shfl_xor_sync(0xffffffffu, ls, 2);
            lrow[h] = lrow[h] * scale + ls;
            mrow[h] = mnew;
#pragma unroll
            for (int n8 = 0; n8 < 8; n8++) {
                acc[n8][2 * h]     *= scale;
                acc[n8][2 * h + 1] *= scale;
            }
            pa[0][h]     = pack_h2(p[0], p[1]);   // keys 0-7
            pa[0][h + 2] = pack_h2(p[2], p[3]);   // keys 8-15
            pa[1][h]     = pack_h2(p[4], p[5]);   // keys 16-23
            pa[1][h + 2] = pack_h2(p[6], p[7]);   // keys 24-31
        }

        // AV: 2 k-steps x 4 dim-blocks; pairs {r0,r1} low-n, {r2,r3} high-n
#pragma unroll
        for (int ks = 0; ks < 2; ks++) {
#pragma unroll
            for (int nb = 0; nb < 4; nb++) {
                uint32_t addr = (uint32_t)__cvta_generic_to_shared(
                    &Vs[cur][ks * 16 + (lane & 15)][nb * 16 + (lane >> 4) * 8]);
                uint32_t r0, r1, r2, r3;
                asm volatile("ldmatrix.sync.aligned.m8n8.x4.trans.shared.b16 {%0,%1,%2,%3}, [%4];"
                             : "=r"(r0), "=r"(r1), "=r"(r2), "=r"(r3)
                             : "r"(addr));
                asm volatile(
                    "mma.sync.aligned.m16n8k16.row.col.f32.f16.f16.f32 "
                    "{%0,%1,%2,%3}, {%4,%5,%6,%7}, {%8,%9}, {%0,%1,%2,%3};"
                    : "+f"(acc[nb*2][0]), "+f"(acc[nb*2][1]), "+f"(acc[nb*2][2]), "+f"(acc[nb*2][3])
                    : "r"(pa[ks][0]), "r"(pa[ks][1]), "r"(pa[ks][2]), "r"(pa[ks][3]),
                      "r"(r0), "r"(r1));
                asm volatile(
                    "mma.sync.aligned.m16n8k16.row.col.f32.f16.f16.f32 "
                    "{%0,%1,%2,%3}, {%4,%5,%6,%7}, {%8,%9}, {%0,%1,%2,%3};"
                    : "+f"(acc[nb*2+1][0]), "+f"(acc[nb*2+1][1]), "+f"(acc[nb*2+1][2]), "+f"(acc[nb*2+1][3])
                    : "r"(pa[ks][0]), "r"(pa[ks][1]), "r"(pa[ks][2]), "r"(pa[ks][3]),
                      "r"(r2), "r"(r3));
            }
        }
    }

    // epilogue
#pragma unroll
    for (int h = 0; h < 2; h++) {
        float inv = 1.f / lrow[h];
        int row = warp * 16 + (lane >> 2) + h * 8;
        size_t base = (size_t)(qbase + row) * DM + hoff;
#pragma unroll
        for (int n8 = 0; n8 < 8; n8++) {
            int dim = n8 * 8 + (lane & 3) * 2;
            *(uint32_t*)&out[base + dim] =
                pack_h2(acc[n8][2 * h] * inv, acc[n8][2 * h + 1] * inv);
        }
    }
}

// ---------------- global-token full attention (qg fused, fp16 kg/vg) ----------------
__global__ void global_attn_kernel(const float* __restrict__ h, const float* __restrict__ Wqg,
                                   const float* __restrict__ bqg,
                                   const __half* __restrict__ kg, const __half* __restrict__ vg,
                                   __half* __restrict__ out)
{
    int g = blockIdx.x, hh = blockIdx.y;
    int hoff = hh * HD;
    int tid = threadIdx.x;
    __shared__ float qs[HD];
    __shared__ float sc[S];
    __shared__ float red[256];

    // fused qg projection
    {
        int d = tid & 63, part = tid >> 6;
        const float* hr = h + (size_t)(g * 512) * DM;
        float a = 0.f;
        for (int kk = part * 192; kk < (part + 1) * 192; kk++)
            a += hr[kk] * Wqg[(size_t)kk * DM + hoff + d];
        red[tid] = a; __syncthreads();
        if (tid < 64)
            qs[tid] = (red[tid] + red[tid + 64] + red[tid + 128] + red[tid + 192]
                       + bqg[hoff + tid]) * SCALE;
        __syncthreads();
    }

    float lmax = -1e30f;
    for (int i = 0; i < 16; i++) {
        int s = i * 256 + tid;
        const __half2* kr = (const __half2*)(kg + (size_t)s * DM + hoff);
        float a = 0.f;
#pragma unroll
        for (int d2 = 0; d2 < 32; d2++) {
            float2 f = __half22float2(kr[d2]);
            a += qs[d2 * 2] * f.x + qs[d2 * 2 + 1] * f.y;
        }
        sc[s] = a;
        lmax = fmaxf(lmax, a);
    }
    red[tid] = lmax; __syncthreads();
    for (int o = 128; o > 0; o >>= 1) { if (tid < o) red[tid] = fmaxf(red[tid], red[tid + o]); __syncthreads(); }
    float mx = red[0]; __syncthreads();

    float lsum = 0.f;
    for (int i = 0; i < 16; i++) {
        int s = i * 256 + tid;
        float p = __expf(sc[s] - mx);
        sc[s] = p;
        lsum += p;
    }
    red[tid] = lsum; __syncthreads();
    for (int o = 128; o > 0; o >>= 1) { if (tid < o) red[tid] += red[tid + o]; __syncthreads(); }
    float inv = 1.f / red[0]; __syncthreads();

    int d = tid & 63;
    int part = tid >> 6;
    float a = 0.f;
    for (int s = part * 1024; s < (part + 1) * 1024; s++)
        a += sc[s] * __half2float(vg[(size_t)s * DM + hoff + d]);
    red[tid] = a; __syncthreads();
    if (tid < 64) {
        float r = red[tid] + red[tid + 64] + red[tid + 128] + red[tid + 192];
        out[(size_t)(g * 512) * DM + hoff + d] = __float2half(r * inv);
    }
}

// ---------------- output head ----------------
__global__ void head_kernel(const float* __restrict__ h, const float* __restrict__ Wout,
                            const float* __restrict__ bout, float* __restrict__ out)
{
    int g = blockIdx.x;
    int o = threadIdx.x;
    const float* hr = h + (size_t)(g * 512) * DM;
    float a = bout[o];
    for (int d = 0; d < DM; d++) a += hr[d] * Wout[(size_t)d * OUTD + o];
    out[g * OUTD + o] = a;
}

// ---------------- driver ----------------
extern "C" void kernel_launch(void* const* d_in, const int* in_sizes, int n_in,
                              void* d_out, int out_size)
{
    (void)in_sizes; (void)n_in; (void)out_size;
    const int*   x        = (const int*)  d_in[0];
    const float* word_emb = (const float*)d_in[1];
    const float* pos_emb  = (const float*)d_in[2];
    const float* emb_ln_s = (const float*)d_in[3];
    const float* emb_ln_b = (const float*)d_in[4];
    const float* Wq  = (const float*)d_in[5];   const float* bq  = (const float*)d_in[6];
    const float* Wk  = (const float*)d_in[7];   const float* bk  = (const float*)d_in[8];
    const float* Wv  = (const float*)d_in[9];   const float* bv  = (const float*)d_in[10];
    const float* Wo  = (const float*)d_in[11];  const float* bo  = (const float*)d_in[12];
    const float* Wqg = (const float*)d_in[13];  const float* bqg = (const float*)d_in[14];
    const float* Wkg = (const float*)d_in[15];  const float* bkg = (const float*)d_in[16];
    const float* Wvg = (const float*)d_in[17];  const float* bvg = (const float*)d_in[18];
    const float* ln1s= (const float*)d_in[19];  const float* ln1b= (const float*)d_in[20];
    const float* W1  = (const float*)d_in[21];  const float* b1  = (const float*)d_in[22];
    const float* W2  = (const float*)d_in[23];  const float* b2  = (const float*)d_in[24];
    const float* ln2s= (const float*)d_in[25];  const float* ln2b= (const float*)d_in[26];
    const float* Wout= (const float*)d_in[27];  const float* bout= (const float*)d_in[28];
    float* out = (float*)d_out;

    float *h, *y;
    __half *h16, *q16, *k16, *v16, *kg16, *vg16, *attn16, *ffn16;
    cudaGetSymbolAddress((void**)&h,    g_h);
    cudaGetSymbolAddress((void**)&y,    g_y);
    cudaGetSymbolAddress((void**)&h16,    g_h16);
    cudaGetSymbolAddress((void**)&q16,    g_q16);
    cudaGetSymbolAddress((void**)&k16,    g_k16);
    cudaGetSymbolAddress((void**)&v16,    g_v16);
    cudaGetSymbolAddress((void**)&kg16,   g_kg16);
    cudaGetSymbolAddress((void**)&vg16,   g_vg16);
    cudaGetSymbolAddress((void**)&attn16, g_attn16);
    cudaGetSymbolAddress((void**)&ffn16,  g_ffn16);

    __half *hWq, *hWk, *hWv, *hWo, *hWkg, *hWvg, *hW1, *hW2;
    cudaGetSymbolAddress((void**)&hWq,  g_hWq);
    cudaGetSymbolAddress((void**)&hWk,  g_hWk);
    cudaGetSymbolAddress((void**)&hWv,  g_hWv);
    cudaGetSymbolAddress((void**)&hWo,  g_hWo);
    cudaGetSymbolAddress((void**)&hWkg, g_hWkg);
    cudaGetSymbolAddress((void**)&hWvg, g_hWvg);
    cudaGetSymbolAddress((void**)&hW1,  g_hW1);
    cudaGetSymbolAddress((void**)&hW2,  g_hW2);

    cudaFuncSetAttribute(hgemm_kernel, cudaFuncAttributeMaxDynamicSharedMemorySize, TGEMM_SMEM);

    const int nP4 = LNUM * DM * DM / 4;
    const int nF4 = LNUM * DM * FF / 4;
    dim3 g6(512, 1, 6);
    f2h_kernel6<<<g6, 256>>>((const float4*)Wq, (const float4*)Wk, (const float4*)Wv,
                             (const float4*)Wo, (const float4*)Wkg, (const float4*)Wvg,
                             (uint2*)hWq, (uint2*)hWk, (uint2*)hWv,
                             (uint2*)hWo, (uint2*)hWkg, (uint2*)hWvg, nP4);
    f2h_kernel<<<2048, 256>>>((const float4*)W1, (uint2*)hW1, nF4);
    f2h_kernel<<<2048, 256>>>((const float4*)W2, (uint2*)hW2, nF4);

    embed_kernel<<<S, 192>>>(x, (const float4*)word_emb, (const float4*)pos_emb,
                             (const float4*)emb_ln_s, (const float4*)emb_ln_b,
                             (float4*)h, (uint2*)h16);

    dim3 grid5  (DM / 128, S / 128, 5);
    dim3 gridP  (DM / 128, S / 128, 1);
    dim3 gridF1 (FF / 128, S / 128, 1);
    dim3 gridF2 (DM / 128, S / 128, 1);
    dim3 gridAtt(2 * CCH, HNUM);
    dim3 gridGA (NW, HNUM);

    for (int l = 0; l < LNUM; l++) {
        size_t wO  = (size_t)l * DM * DM;
        size_t bO  = (size_t)l * DM;
        size_t w1O = (size_t)l * DM * FF;
        size_t b1O = (size_t)l * FF;
        size_t w2O = (size_t)l * FF * DM;

        hgemm_kernel<<<grid5, 256, TGEMM_SMEM>>>(h16,
            hWq + wO, hWk + wO, hWv + wO, hWkg + wO, hWvg + wO,
            bq + bO, bk + bO, bv + bO, bkg + bO, bvg + bO,
            q16, k16, v16, kg16, vg16,
            S, DM, DM, SCALE, 0, 0b11111);
        local_attn_mma<<<gridAtt, 256>>>(q16, k16, v16, attn16);
        global_attn_kernel<<<gridGA, 256>>>(h, Wqg + wO, bqg + bO, kg16, vg16, attn16);

        hgemm_kernel<<<gridP, 256, TGEMM_SMEM>>>(attn16,
            hWo + wO, hWo + wO, hWo + wO, hWo + wO, hWo + wO,
            bo + bO, bo + bO, bo + bO, bo + bO, bo + bO,
            y, y, y, y, y,
            S, DM, DM, 1.0f, 0, 0);
        add_ln_kernel<<<S, 192>>>((const float4*)h, (const float4*)y,
                                  (const float4*)(ln1s + bO), (const float4*)(ln1b + bO),
                                  (float4*)h, (uint2*)h16);

        hgemm_kernel<<<gridF1, 256, TGEMM_SMEM>>>(h16,
            hW1 + w1O, hW1 + w1O, hW1 + w1O, hW1 + w1O, hW1 + w1O,
            b1 + b1O, b1 + b1O, b1 + b1O, b1 + b1O, b1 + b1O,
            ffn16, ffn16, ffn16, ffn16, ffn16,
            S, FF, DM, 1.0f, 1, 0b11111);
        hgemm_kernel<<<gridF2, 256, TGEMM_SMEM>>>(ffn16,
            hW2 + w2O, hW2 + w2O, hW2 + w2O, hW2 + w2O, hW2 + w2O,
            b2 + bO, b2 + bO, b2 + bO, b2 + bO, b2 + bO,
            y, y, y, y, y,
            S, DM, FF, 1.0f, 0, 0);
        add_ln_kernel<<<S, 192>>>((const float4*)h, (const float4*)y,
                                  (const float4*)(ln2s + bO), (const float4*)(ln2b + bO),
                                  (float4*)h, (uint2*)h16);
    }

    head_kernel<<<NW, 128>>>(h, Wout, bout, out);
}